// round 5
// baseline (speedup 1.0000x reference)
#include <cuda_runtime.h>
#include <math.h>

#define BATCH 2
#define T 8
#define C 64
#define R 16
#define H 160
#define W 160
#define HW (H*W)            // 25600
#define CHW (C*HW)          // 1,638,400
#define TCHW (T*CHW)
#define C2 128
#define C4 256

typedef unsigned long long ull;

__device__ __forceinline__ ull pk2(float a, float b) {
    ull r; asm("mov.b64 %0, {%1,%2};" : "=l"(r) : "f"(a), "f"(b)); return r;
}
__device__ __forceinline__ float2 upk2(ull v) {
    float2 r; asm("mov.b64 {%0,%1}, %2;" : "=f"(r.x), "=f"(r.y) : "l"(v)); return r;
}
__device__ __forceinline__ void ffma2(ull& d, ull a, ull b) {
    asm("fma.rn.f32x2 %0, %1, %2, %0;" : "+l"(d) : "l"(a), "l"(b));
}
__device__ __forceinline__ ull d2u(double d) { return __double_as_longlong(d); }

// ---------------- scratch (device globals) -------------------------------------
__device__ float g_pool[BATCH*C];
__device__ float g_wd[BATCH*C*9];
__device__ float g_fp[BATCH*CHW];                    // 13.1 MB
__device__ float g_fusion[(size_t)BATCH*C2*HW];      // 26.2 MB
__device__ float g_a1[(size_t)BATCH*C4*HW];          // 52.4 MB  gate1 expand out
__device__ float g_b1[(size_t)BATCH*C4*HW];          // 52.4 MB  gate1 dw out
__device__ float g_a2[(size_t)BATCH*C4*HW];          // 52.4 MB  gate2 expand out
__device__ float g_b2[(size_t)BATCH*C4*HW];          // 52.4 MB  gate2 dw out
__device__ float g_g1[BATCH*CHW];                    // 13.1 MB

// ---------------- pool ----------------------------------------------------------
__global__ void pool_kernel(const float* __restrict__ xbase) {
    int plane = blockIdx.x;
    int bi = plane >> 6, c = plane & 63;
    const float* p = xbase + (size_t)bi*TCHW + (size_t)c*HW;
    float s = 0.f;
    for (int i = threadIdx.x; i < HW; i += 256) s += p[i];
    __shared__ float red[8];
    #pragma unroll
    for (int o = 16; o; o >>= 1) s += __shfl_down_sync(0xffffffffu, s, o);
    if ((threadIdx.x & 31) == 0) red[threadIdx.x >> 5] = s;
    __syncthreads();
    if (threadIdx.x == 0) {
        float t = 0.f;
        #pragma unroll
        for (int k = 0; k < 8; k++) t += red[k];
        g_pool[plane] = t * (1.0f / (float)HW);
    }
}

// ---------------- tiny MLP ------------------------------------------------------
__global__ void mlp_kernel(const float* __restrict__ w1,
                           const float* __restrict__ gamma,
                           const float* __restrict__ beta,
                           const float* __restrict__ mean,
                           const float* __restrict__ var,
                           const float* __restrict__ w2,
                           const float* __restrict__ b2) {
    __shared__ float zs[BATCH*R];
    int tid = threadIdx.x;
    if (tid < BATCH*R) {
        int bi = tid / R, j = tid % R;
        float s = 0.f;
        for (int c = 0; c < C; c++) s = fmaf(g_pool[bi*C + c], w1[j*C + c], s);
        s = (s - mean[j]) * rsqrtf(var[j] + 1e-5f) * gamma[j] + beta[j];
        zs[tid] = fmaxf(s, 0.f);
    }
    __syncthreads();
    for (int o = tid; o < BATCH*C*9; o += blockDim.x) {
        int bi = o / (C*9), oo = o % (C*9);
        float s = b2[oo];
        #pragma unroll
        for (int j = 0; j < R; j++) s = fmaf(zs[bi*R + j], w2[oo*R + j], s);
        g_wd[o] = s;
    }
}

// ---------------- dynamic depthwise 3x3 -----------------------------------------
__global__ void dyndw_kernel(const float* __restrict__ ybase,
                             const float* __restrict__ kc_bias) {
    int idx = blockIdx.x * 256 + threadIdx.x;
    int px = idx % HW;
    int plane = idx / HW;
    int c = plane & 63, bi = plane >> 6;
    const float* p = ybase + (size_t)bi*TCHW + (size_t)c*HW;
    const float* wp = g_wd + plane*9;
    float w[9];
    #pragma unroll
    for (int k = 0; k < 9; k++) w[k] = wp[k];
    int y0 = px / W, x0 = px % W;
    float s = 0.f;
    #pragma unroll
    for (int kh = 0; kh < 3; kh++) {
        int yy = y0 + kh - 1;
        if ((unsigned)yy >= H) continue;
        const float* row = p + yy*W;
        #pragma unroll
        for (int kw = 0; kw < 3; kw++) {
            int xx = x0 + kw - 1;
            if ((unsigned)xx < W) s = fmaf(row[xx], w[kh*3 + kw], s);
        }
    }
    g_fp[idx] = s + kc_bias[c];
}

// ---------------- conv3x3 128->128 + leaky, FFMA2-lite ---------------------------
// block 256 thr; tile 32x16 px, 16 oc/block; per-thread 8px (x) x 4oc.
// grid (5, 10, BATCH*8). acc = 16 ull -> ~85 regs, no spills at occ 2.
__global__ void __launch_bounds__(256, 2) conv3x3_kernel(const float* __restrict__ xbase,
                                                         const float* __restrict__ wgt,
                                                         const float* __restrict__ bias) {
    __shared__ __align__(16) float tile_s[18*35];
    __shared__ __align__(16) float wsd[9*32];    // [tap][16 oc duplicated pairs]
    int tid = threadIdx.x;
    int pc = tid & 3;                            // x sub-block of 8 px
    int ty = (tid >> 2) & 15;                    // output row in tile
    int og = tid >> 6;                           // 0..3 -> 4 oc each
    int x0 = blockIdx.x * 32;
    int y0 = blockIdx.y * 16;
    int bz = blockIdx.z;
    int bi = bz >> 3;
    int oc0 = (bz & 7) * 16;

    const float* xp  = xbase + (size_t)bi*TCHW;
    const float* fpp = g_fp  + (size_t)bi*CHW;

    // tile staging positions (612 = 18x34): smok gates smem store (zero-fill halo),
    // tval additionally gates the global load.
    int toff[3], tsm[3]; bool tval[3], smok[3];
    #pragma unroll
    for (int l = 0; l < 3; l++) {
        int s = tid + l*256;
        int r = s / 34, cc = s - r*34;
        int gy = y0 + r - 1, gx = x0 + cc - 1;
        bool ok = (s < 612);
        bool v = ok && ((unsigned)gy < H) && ((unsigned)gx < W);
        smok[l] = ok;
        toff[l] = v ? gy*W + gx : 0;
        tval[l] = v;
        tsm[l]  = ok ? (r*35 + cc) : 0;
    }
    // weight staging: 16 oc x 9 taps = 144 entries, one per thread (tid<144)
    int wo0 = tid / 9, wk0 = tid % 9;
    bool wv0 = tid < 144;
    size_t wg0 = ((size_t)(oc0 + wo0)*C2)*9 + wk0;
    int wsm0 = wk0*32 + wo0*2;

    ull acc[4][4];
    #pragma unroll
    for (int k = 0; k < 4; k++)
        #pragma unroll
        for (int o = 0; o < 4; o++) acc[k][o] = 0ull;

    // prefetch ic=0
    float tv[3], pw0 = 0.f;
    {
        #pragma unroll
        for (int l = 0; l < 3; l++) tv[l] = tval[l] ? __ldg(xp + toff[l]) : 0.f;
        if (wv0) pw0 = __ldg(wgt + wg0);
    }

    int vbase0 = ty*35 + pc*8;

    for (int ic = 0; ic < C2; ic++) {
        __syncthreads();
        #pragma unroll
        for (int l = 0; l < 3; l++) if (smok[l]) tile_s[tsm[l]] = tv[l];
        if (wv0) { wsd[wsm0] = pw0; wsd[wsm0+1] = pw0; }
        __syncthreads();

        if (ic + 1 < C2) {
            int icn = ic + 1;
            const float* src = (icn < C) ? (xp + (size_t)icn*HW) : (fpp + (size_t)(icn - C)*HW);
            #pragma unroll
            for (int l = 0; l < 3; l++) tv[l] = tval[l] ? __ldg(src + toff[l]) : 0.f;
            if (wv0) pw0 = __ldg(wgt + wg0 + (size_t)icn*9);
        }

        #pragma unroll
        for (int kh = 0; kh < 3; kh++) {
            int vb = vbase0 + kh*35;
            float v[10];
            #pragma unroll
            for (int j = 0; j < 10; j++) v[j] = tile_s[vb + j];
            ull E[5], O[4];
            #pragma unroll
            for (int k = 0; k < 5; k++) E[k] = pk2(v[2*k], v[2*k+1]);
            #pragma unroll
            for (int k = 0; k < 4; k++) O[k] = pk2(v[2*k+1], v[2*k+2]);
            #pragma unroll
            for (int kw = 0; kw < 3; kw++) {
                int tap = kh*3 + kw;
                const float* wb = wsd + tap*32 + og*8;
                double2 wp0 = ((const double2*)wb)[0];
                double2 wp1 = ((const double2*)wb)[1];
                ull w4[4] = { d2u(wp0.x), d2u(wp0.y), d2u(wp1.x), d2u(wp1.y) };
                #pragma unroll
                for (int k = 0; k < 4; k++) {
                    ull P = (kw == 0) ? E[k] : (kw == 1) ? O[k] : E[k+1];
                    #pragma unroll
                    for (int o = 0; o < 4; o++) ffma2(acc[k][o], P, w4[o]);
                }
            }
        }
    }

    // epilogue: bias + leaky relu + store (8 px x 4 oc)
    int row = y0 + ty;
    #pragma unroll
    for (int o = 0; o < 4; o++) {
        int oc = oc0 + og*4 + o;
        float bv = bias[oc];
        float r8[8];
        #pragma unroll
        for (int k = 0; k < 4; k++) {
            float2 p = upk2(acc[k][o]);
            float a = p.x + bv, b = p.y + bv;
            r8[2*k]   = (a > 0.f) ? a : 0.1f*a;
            r8[2*k+1] = (b > 0.f) ? b : 0.1f*b;
        }
        float* op = g_fusion + ((size_t)bi*C2 + oc)*HW + (size_t)row*W + x0 + pc*8;
        ((float4*)op)[0] = make_float4(r8[0], r8[1], r8[2], r8[3]);
        ((float4*)op)[1] = make_float4(r8[4], r8[5], r8[6], r8[7]);
    }
}

// ---------------- pointwise expand 64 -> 256 (+bias)  [R1 version] ---------------
__global__ void __launch_bounds__(256) expand_kernel(int halfoff,
                                                     float* __restrict__ outbase,
                                                     const float* __restrict__ wgt,   // [256][64]
                                                     const float* __restrict__ bias) {
    __shared__ float in_s[C][68];
    int bi  = blockIdx.y;
    int px0 = blockIdx.x * 64;
    int tid = threadIdx.x;
    const float* in = g_fusion + ((size_t)bi*C2 + halfoff)*HW + px0;
    for (int s = tid; s < C*16; s += 256) {
        int ic = s >> 4, p4 = s & 15;
        float4 v = ((const float4*)(in + (size_t)ic*HW))[p4];
        *((float4*)&in_s[ic][p4*4]) = v;
    }
    __syncthreads();

    int pg = tid & 7;
    int og = tid >> 3;
    float acc[8][8];
    #pragma unroll
    for (int p = 0; p < 8; p++)
        #pragma unroll
        for (int o = 0; o < 8; o++) acc[p][o] = 0.f;

    const float* wp = wgt + (size_t)og*8*C;
    for (int ic = 0; ic < C; ic++) {
        float4 a0 = *((const float4*)&in_s[ic][pg*8]);
        float4 a1 = *((const float4*)&in_s[ic][pg*8 + 4]);
        float a[8] = {a0.x, a0.y, a0.z, a0.w, a1.x, a1.y, a1.z, a1.w};
        float wv[8];
        #pragma unroll
        for (int o = 0; o < 8; o++) wv[o] = __ldg(wp + (size_t)o*C + ic);
        #pragma unroll
        for (int p = 0; p < 8; p++)
            #pragma unroll
            for (int o = 0; o < 8; o++) acc[p][o] = fmaf(a[p], wv[o], acc[p][o]);
    }
    float* outb = outbase + (size_t)bi*C4*HW + px0 + pg*8;
    #pragma unroll
    for (int o = 0; o < 8; o++) {
        int oc = og*8 + o;
        float bv = bias[oc];
        float4 v0 = make_float4(acc[0][o]+bv, acc[1][o]+bv, acc[2][o]+bv, acc[3][o]+bv);
        float4 v1 = make_float4(acc[4][o]+bv, acc[5][o]+bv, acc[6][o]+bv, acc[7][o]+bv);
        float4* op = (float4*)(outb + (size_t)oc*HW);
        op[0] = v0; op[1] = v1;
    }
}

// ---------------- static depthwise 3x3 on 256 channels (+bias) [R1 version] ------
__global__ void dwstatic_kernel(const float* __restrict__ inbase,
                                float* __restrict__ outbase,
                                const float* __restrict__ wgt,
                                const float* __restrict__ bias) {
    int idx = blockIdx.x * 256 + threadIdx.x;
    int px = idx % HW;
    int plane = idx / HW;
    int ch = plane & (C4 - 1);
    const float* p = inbase + (size_t)plane*HW;
    const float* wp = wgt + ch*9;
    float w[9];
    #pragma unroll
    for (int k = 0; k < 9; k++) w[k] = wp[k];
    int y0 = px / W, x0 = px % W;
    float s = 0.f;
    #pragma unroll
    for (int kh = 0; kh < 3; kh++) {
        int yy = y0 + kh - 1;
        if ((unsigned)yy >= H) continue;
        const float* row = p + yy*W;
        #pragma unroll
        for (int kw = 0; kw < 3; kw++) {
            int xx = x0 + kw - 1;
            if ((unsigned)xx < W) s = fmaf(row[xx], w[kh*3 + kw], s);
        }
    }
    outbase[idx] = s + bias[ch];
}

// ---------------- pointwise contract 256->64, +bias, sigmoid [R1 version] --------
template<bool FINAL>
__global__ void __launch_bounds__(256) contract_kernel(const float* __restrict__ inbase,
                                                       const float* __restrict__ wgt,  // [64][256]
                                                       const float* __restrict__ bias,
                                                       float* __restrict__ outbase) {
    __shared__ float in_s[64][132];
    __shared__ float w_s[64][68];
    int bi  = blockIdx.y;
    int px0 = blockIdx.x * 128;
    int tid = threadIdx.x;
    int pg = tid & 15;
    int og = tid >> 4;
    float acc[8][4];
    #pragma unroll
    for (int p = 0; p < 8; p++)
        #pragma unroll
        for (int o = 0; o < 4; o++) acc[p][o] = 0.f;

    const float* in = inbase + (size_t)bi*C4*HW + px0;

    for (int kc = 0; kc < C4; kc += 64) {
        for (int s = tid; s < 64*32; s += 256) {
            int ic = s >> 5, p4 = s & 31;
            float4 v = ((const float4*)(in + (size_t)(kc + ic)*HW))[p4];
            *((float4*)&in_s[ic][p4*4]) = v;
        }
        for (int s = tid; s < 64*64; s += 256) {
            int ic = s & 63, oc = s >> 6;
            w_s[ic][oc] = wgt[(size_t)oc*C4 + kc + ic];
        }
        __syncthreads();
        #pragma unroll
        for (int ic = 0; ic < 64; ic++) {
            float4 a0 = *((const float4*)&in_s[ic][pg*8]);
            float4 a1 = *((const float4*)&in_s[ic][pg*8 + 4]);
            float4 wv = *((const float4*)&w_s[ic][og*4]);
            float a[8] = {a0.x, a0.y, a0.z, a0.w, a1.x, a1.y, a1.z, a1.w};
            float wr[4] = {wv.x, wv.y, wv.z, wv.w};
            #pragma unroll
            for (int p = 0; p < 8; p++)
                #pragma unroll
                for (int o = 0; o < 4; o++) acc[p][o] = fmaf(a[p], wr[o], acc[p][o]);
        }
        __syncthreads();
    }

    #pragma unroll
    for (int o = 0; o < 4; o++) {
        int oc = og*4 + o;
        float bv = bias[oc];
        float g[8];
        #pragma unroll
        for (int p = 0; p < 8; p++) {
            float x = acc[p][o] + bv;
            g[p] = 1.0f / (1.0f + __expf(-x));
        }
        size_t poff = px0 + (size_t)pg*8;
        if (!FINAL) {
            float4* gp = (float4*)(g_g1 + ((size_t)bi*C + oc)*HW + poff);
            gp[0] = make_float4(g[0], g[1], g[2], g[3]);
            gp[1] = make_float4(g[4], g[5], g[6], g[7]);
        } else {
            const float4* f1p = (const float4*)(g_fusion + ((size_t)bi*C2 + oc)*HW + poff);
            const float4* f2p = (const float4*)(g_fusion + ((size_t)bi*C2 + C + oc)*HW + poff);
            const float4* g1p = (const float4*)(g_g1 + ((size_t)bi*C + oc)*HW + poff);
            float4* op = (float4*)(outbase + (size_t)bi*TCHW + (size_t)oc*HW + poff);
            #pragma unroll
            for (int q = 0; q < 2; q++) {
                float4 f1 = f1p[q], f2 = f2p[q], g1 = g1p[q];
                float4 r;
                r.x = f1.x*g1.x + f2.x*g[q*4+0];
                r.y = f1.y*g1.y + f2.y*g[q*4+1];
                r.z = f1.z*g1.z + f2.z*g[q*4+2];
                r.w = f1.w*g1.w + f2.w*g[q*4+3];
                op[q] = r;
            }
        }
    }
}

// ---------------- launcher -------------------------------------------------------
extern "C" void kernel_launch(void* const* d_in, const int* in_sizes, int n_in,
                              void* d_out, int out_size) {
    (void)in_sizes; (void)n_in; (void)out_size;
    const float* feature   = (const float*)d_in[0];
    const float* kc_w1     = (const float*)d_in[1];
    const float* kc_gamma  = (const float*)d_in[2];
    const float* kc_beta   = (const float*)d_in[3];
    const float* kc_mean   = (const float*)d_in[4];
    const float* kc_var    = (const float*)d_in[5];
    const float* kc_w2     = (const float*)d_in[6];
    const float* kc_b2     = (const float*)d_in[7];
    const float* kc_bias   = (const float*)d_in[8];
    const float* conv1_w   = (const float*)d_in[9];
    const float* conv1_b   = (const float*)d_in[10];
    const float* pi1_w     = (const float*)d_in[11];
    const float* pi1_b     = (const float*)d_in[12];
    const float* dw1_w     = (const float*)d_in[13];
    const float* dw1_b     = (const float*)d_in[14];
    const float* po1_w     = (const float*)d_in[15];
    const float* po1_b     = (const float*)d_in[16];
    const float* pi2_w     = (const float*)d_in[17];
    const float* pi2_b     = (const float*)d_in[18];
    const float* dw2_w     = (const float*)d_in[19];
    const float* dw2_b     = (const float*)d_in[20];
    const float* po2_w     = (const float*)d_in[21];
    const float* po2_b     = (const float*)d_in[22];
    float* out = (float*)d_out;

    // one-time infra (streams/events), created before any capture (first call
    // is the uncaptured correctness run)
    static cudaStream_t s1 = nullptr;
    static cudaEvent_t evA[7], evB[7];
    if (s1 == nullptr) {
        cudaStreamCreate(&s1);
        for (int k = 0; k < 7; k++) {
            cudaEventCreateWithFlags(&evA[k], cudaEventDisableTiming);
            cudaEventCreateWithFlags(&evB[k], cudaEventDisableTiming);
        }
    }

    // out[:, T-1] = feature[:, T-1]
    for (int bi = 0; bi < BATCH; bi++) {
        size_t off = ((size_t)bi*T + (T-1)) * CHW;
        cudaMemcpyAsync(out + off, feature + off, (size_t)CHW*sizeof(float),
                        cudaMemcpyDeviceToDevice, 0);
    }

    for (int i = T - 2; i >= 0; --i) {
        int k = (T - 2) - i;                                  // 0..6
        const float* xbase = feature + (size_t)i*CHW;
        const float* ybase = out + (size_t)(i+1)*CHW;

        // critical path on stream 0
        pool_kernel<<<BATCH*C, 256>>>(xbase);
        mlp_kernel<<<1, 128>>>(kc_w1, kc_gamma, kc_beta, kc_mean, kc_var, kc_w2, kc_b2);
        dyndw_kernel<<<(BATCH*CHW)/256, 256>>>(ybase, kc_bias);
        conv3x3_kernel<<<dim3(5, 10, BATCH*8), 256>>>(xbase, conv1_w, conv1_b);
        cudaEventRecord(evA[k], 0);

        // gate 1 chain on s1 (depends on conv)
        cudaStreamWaitEvent(s1, evA[k], 0);
        expand_kernel<<<dim3(HW/64, BATCH), 256, 0, s1>>>(0, g_a1, pi1_w, pi1_b);
        dwstatic_kernel<<<(BATCH*C4*HW)/256, 256, 0, s1>>>(g_a1, g_b1, dw1_w, dw1_b);
        contract_kernel<false><<<dim3(HW/128, BATCH), 256, 0, s1>>>(g_b1, po1_w, po1_b, nullptr);
        cudaEventRecord(evB[k], s1);

        // gate 2 chain on stream 0 (concurrent with gate 1)
        expand_kernel<<<dim3(HW/64, BATCH), 256>>>(C, g_a2, pi2_w, pi2_b);
        dwstatic_kernel<<<(BATCH*C4*HW)/256, 256>>>(g_a2, g_b2, dw2_w, dw2_b);

        // final combine needs g_g1 from s1
        cudaStreamWaitEvent(0, evB[k], 0);
        contract_kernel<true><<<dim3(HW/128, BATCH), 256>>>(g_b2, po2_w, po2_b, out + (size_t)i*CHW);
    }
}

// round 7
// speedup vs baseline: 3.6397x; 3.6397x over previous
#include <cuda_runtime.h>
#include <math.h>

#define BATCH 2
#define T 8
#define C 64
#define R 16
#define H 160
#define W 160
#define HW (H*W)            // 25600
#define CHW (C*HW)          // 1,638,400
#define TCHW (T*CHW)
#define C2 128
#define C4 256

typedef unsigned long long ull;

__device__ __forceinline__ ull pk2(float a, float b) {
    ull r; asm("mov.b64 %0, {%1,%2};" : "=l"(r) : "f"(a), "f"(b)); return r;
}
__device__ __forceinline__ float2 upk2(ull v) {
    float2 r; asm("mov.b64 {%0,%1}, %2;" : "=f"(r.x), "=f"(r.y) : "l"(v)); return r;
}
__device__ __forceinline__ void ffma2(ull& d, ull a, ull b) {
    asm("fma.rn.f32x2 %0, %1, %2, %0;" : "+l"(d) : "l"(a), "l"(b));
}
__device__ __forceinline__ ull d2u(double d) { return __double_as_longlong(d); }

// ---------------- scratch (device globals; referenced ONLY from device code) ----
__device__ float g_pool[BATCH*C];
__device__ float g_wd[BATCH*C*9];
__device__ float g_fp[BATCH*CHW];
__device__ float g_fusion[(size_t)BATCH*C2*HW];
__device__ float g_a1[(size_t)BATCH*C4*HW];
__device__ float g_b1[(size_t)BATCH*C4*HW];
__device__ float g_a2[(size_t)BATCH*C4*HW];
__device__ float g_b2[(size_t)BATCH*C4*HW];
__device__ float g_g1[BATCH*CHW];

// ---------------- pool ----------------------------------------------------------
__global__ void pool_kernel(const float* __restrict__ xbase) {
    int plane = blockIdx.x;
    int bi = plane >> 6, c = plane & 63;
    const float* p = xbase + (size_t)bi*TCHW + (size_t)c*HW;
    float s = 0.f;
    for (int i = threadIdx.x; i < HW; i += 256) s += p[i];
    __shared__ float red[8];
    #pragma unroll
    for (int o = 16; o; o >>= 1) s += __shfl_down_sync(0xffffffffu, s, o);
    if ((threadIdx.x & 31) == 0) red[threadIdx.x >> 5] = s;
    __syncthreads();
    if (threadIdx.x == 0) {
        float t = 0.f;
        #pragma unroll
        for (int k = 0; k < 8; k++) t += red[k];
        g_pool[plane] = t * (1.0f / (float)HW);
    }
}

// ---------------- tiny MLP ------------------------------------------------------
__global__ void mlp_kernel(const float* __restrict__ w1,
                           const float* __restrict__ gamma,
                           const float* __restrict__ beta,
                           const float* __restrict__ mean,
                           const float* __restrict__ var,
                           const float* __restrict__ w2,
                           const float* __restrict__ b2) {
    __shared__ float zs[BATCH*R];
    int tid = threadIdx.x;
    if (tid < BATCH*R) {
        int bi = tid / R, j = tid % R;
        float s = 0.f;
        for (int c = 0; c < C; c++) s = fmaf(g_pool[bi*C + c], w1[j*C + c], s);
        s = (s - mean[j]) * rsqrtf(var[j] + 1e-5f) * gamma[j] + beta[j];
        zs[tid] = fmaxf(s, 0.f);
    }
    __syncthreads();
    for (int o = tid; o < BATCH*C*9; o += blockDim.x) {
        int bi = o / (C*9), oo = o % (C*9);
        float s = b2[oo];
        #pragma unroll
        for (int j = 0; j < R; j++) s = fmaf(zs[bi*R + j], w2[oo*R + j], s);
        g_wd[o] = s;
    }
}

// ---------------- dynamic depthwise 3x3 -----------------------------------------
__global__ void dyndw_kernel(const float* __restrict__ ybase,
                             const float* __restrict__ kc_bias) {
    int idx = blockIdx.x * 256 + threadIdx.x;
    int px = idx % HW;
    int plane = idx / HW;
    int c = plane & 63, bi = plane >> 6;
    const float* p = ybase + (size_t)bi*TCHW + (size_t)c*HW;
    const float* wp = g_wd + plane*9;
    float w[9];
    #pragma unroll
    for (int k = 0; k < 9; k++) w[k] = wp[k];
    int y0 = px / W, x0 = px % W;
    float s = 0.f;
    #pragma unroll
    for (int kh = 0; kh < 3; kh++) {
        int yy = y0 + kh - 1;
        if ((unsigned)yy >= H) continue;
        const float* row = p + yy*W;
        #pragma unroll
        for (int kw = 0; kw < 3; kw++) {
            int xx = x0 + kw - 1;
            if ((unsigned)xx < W) s = fmaf(row[xx], w[kh*3 + kw], s);
        }
    }
    g_fp[idx] = s + kc_bias[c];
}

// ---------------- conv3x3 128->128 + leaky, FFMA2-lite (verified R5) -------------
__global__ void __launch_bounds__(256, 2) conv3x3_kernel(const float* __restrict__ xbase,
                                                         const float* __restrict__ wgt,
                                                         const float* __restrict__ bias) {
    __shared__ __align__(16) float tile_s[18*35];
    __shared__ __align__(16) float wsd[9*32];
    int tid = threadIdx.x;
    int pc = tid & 3;
    int ty = (tid >> 2) & 15;
    int og = tid >> 6;
    int x0 = blockIdx.x * 32;
    int y0 = blockIdx.y * 16;
    int bz = blockIdx.z;
    int bi = bz >> 3;
    int oc0 = (bz & 7) * 16;

    const float* xp  = xbase + (size_t)bi*TCHW;
    const float* fpp = g_fp  + (size_t)bi*CHW;

    int toff[3], tsm[3]; bool tval[3], smok[3];
    #pragma unroll
    for (int l = 0; l < 3; l++) {
        int s = tid + l*256;
        int r = s / 34, cc = s - r*34;
        int gy = y0 + r - 1, gx = x0 + cc - 1;
        bool ok = (s < 612);
        bool v = ok && ((unsigned)gy < H) && ((unsigned)gx < W);
        smok[l] = ok;
        toff[l] = v ? gy*W + gx : 0;
        tval[l] = v;
        tsm[l]  = ok ? (r*35 + cc) : 0;
    }
    int wo0 = tid / 9, wk0 = tid % 9;
    bool wv0 = tid < 144;
    size_t wg0 = ((size_t)(oc0 + wo0)*C2)*9 + wk0;
    int wsm0 = wk0*32 + wo0*2;

    ull acc[4][4];
    #pragma unroll
    for (int k = 0; k < 4; k++)
        #pragma unroll
        for (int o = 0; o < 4; o++) acc[k][o] = 0ull;

    float tv[3], pw0 = 0.f;
    {
        #pragma unroll
        for (int l = 0; l < 3; l++) tv[l] = tval[l] ? __ldg(xp + toff[l]) : 0.f;
        if (wv0) pw0 = __ldg(wgt + wg0);
    }

    int vbase0 = ty*35 + pc*8;

    for (int ic = 0; ic < C2; ic++) {
        __syncthreads();
        #pragma unroll
        for (int l = 0; l < 3; l++) if (smok[l]) tile_s[tsm[l]] = tv[l];
        if (wv0) { wsd[wsm0] = pw0; wsd[wsm0+1] = pw0; }
        __syncthreads();

        if (ic + 1 < C2) {
            int icn = ic + 1;
            const float* src = (icn < C) ? (xp + (size_t)icn*HW) : (fpp + (size_t)(icn - C)*HW);
            #pragma unroll
            for (int l = 0; l < 3; l++) tv[l] = tval[l] ? __ldg(src + toff[l]) : 0.f;
            if (wv0) pw0 = __ldg(wgt + wg0 + (size_t)icn*9);
        }

        #pragma unroll
        for (int kh = 0; kh < 3; kh++) {
            int vb = vbase0 + kh*35;
            float v[10];
            #pragma unroll
            for (int j = 0; j < 10; j++) v[j] = tile_s[vb + j];
            ull E[5], O[4];
            #pragma unroll
            for (int k = 0; k < 5; k++) E[k] = pk2(v[2*k], v[2*k+1]);
            #pragma unroll
            for (int k = 0; k < 4; k++) O[k] = pk2(v[2*k+1], v[2*k+2]);
            #pragma unroll
            for (int kw = 0; kw < 3; kw++) {
                int tap = kh*3 + kw;
                const float* wb = wsd + tap*32 + og*8;
                double2 wp0 = ((const double2*)wb)[0];
                double2 wp1 = ((const double2*)wb)[1];
                ull w4[4] = { d2u(wp0.x), d2u(wp0.y), d2u(wp1.x), d2u(wp1.y) };
                #pragma unroll
                for (int k = 0; k < 4; k++) {
                    ull P = (kw == 0) ? E[k] : (kw == 1) ? O[k] : E[k+1];
                    #pragma unroll
                    for (int o = 0; o < 4; o++) ffma2(acc[k][o], P, w4[o]);
                }
            }
        }
    }

    int row = y0 + ty;
    #pragma unroll
    for (int o = 0; o < 4; o++) {
        int oc = oc0 + og*4 + o;
        float bv = bias[oc];
        float r8[8];
        #pragma unroll
        for (int k = 0; k < 4; k++) {
            float2 p = upk2(acc[k][o]);
            float a = p.x + bv, b = p.y + bv;
            r8[2*k]   = (a > 0.f) ? a : 0.1f*a;
            r8[2*k+1] = (b > 0.f) ? b : 0.1f*b;
        }
        float* op = g_fusion + ((size_t)bi*C2 + oc)*HW + (size_t)row*W + x0 + pc*8;
        ((float4*)op)[0] = make_float4(r8[0], r8[1], r8[2], r8[3]);
        ((float4*)op)[1] = make_float4(r8[4], r8[5], r8[6], r8[7]);
    }
}

// ---------------- pointwise expand 64 -> 256, both gates in one launch ------------
// grid (HW/64, BATCH, 2); z = gate; buffers selected in DEVICE code.
__global__ void __launch_bounds__(256) expand_both_kernel(const float* __restrict__ w1,
                                                          const float* __restrict__ b1,
                                                          const float* __restrict__ w2,
                                                          const float* __restrict__ b2) {
    __shared__ float in_s[C][68];
    int gate = blockIdx.z;
    const float* wgt  = gate ? w2 : w1;
    const float* bias = gate ? b2 : b1;
    float* outbase    = gate ? g_a2 : g_a1;
    int halfoff       = gate ? C : 0;

    int bi  = blockIdx.y;
    int px0 = blockIdx.x * 64;
    int tid = threadIdx.x;
    const float* in = g_fusion + ((size_t)bi*C2 + halfoff)*HW + px0;
    for (int s = tid; s < C*16; s += 256) {
        int ic = s >> 4, p4 = s & 15;
        float4 v = ((const float4*)(in + (size_t)ic*HW))[p4];
        *((float4*)&in_s[ic][p4*4]) = v;
    }
    __syncthreads();

    int pg = tid & 7;
    int og = tid >> 3;
    float acc[8][8];
    #pragma unroll
    for (int p = 0; p < 8; p++)
        #pragma unroll
        for (int o = 0; o < 8; o++) acc[p][o] = 0.f;

    const float* wp = wgt + (size_t)og*8*C;
    for (int ic = 0; ic < C; ic++) {
        float4 a0 = *((const float4*)&in_s[ic][pg*8]);
        float4 a1 = *((const float4*)&in_s[ic][pg*8 + 4]);
        float a[8] = {a0.x, a0.y, a0.z, a0.w, a1.x, a1.y, a1.z, a1.w};
        float wv[8];
        #pragma unroll
        for (int o = 0; o < 8; o++) wv[o] = __ldg(wp + (size_t)o*C + ic);
        #pragma unroll
        for (int p = 0; p < 8; p++)
            #pragma unroll
            for (int o = 0; o < 8; o++) acc[p][o] = fmaf(a[p], wv[o], acc[p][o]);
    }
    float* outb = outbase + (size_t)bi*C4*HW + px0 + pg*8;
    #pragma unroll
    for (int o = 0; o < 8; o++) {
        int oc = og*8 + o;
        float bv = bias[oc];
        float4 v0 = make_float4(acc[0][o]+bv, acc[1][o]+bv, acc[2][o]+bv, acc[3][o]+bv);
        float4 v1 = make_float4(acc[4][o]+bv, acc[5][o]+bv, acc[6][o]+bv, acc[7][o]+bv);
        float4* op = (float4*)(outb + (size_t)oc*HW);
        op[0] = v0; op[1] = v1;
    }
}

// ---------------- static depthwise 3x3, 4px/thread, both gates --------------------
// grid ((BATCH*C4*HW/4)/256, 2); y = gate; buffers selected in DEVICE code.
__global__ void __launch_bounds__(256) dw_both_kernel(const float* __restrict__ w1,
                                                      const float* __restrict__ b1,
                                                      const float* __restrict__ w2,
                                                      const float* __restrict__ b2) {
    int gate = blockIdx.y;
    const float* inb  = gate ? g_a2 : g_a1;
    float* outb       = gate ? g_b2 : g_b1;
    const float* wgt  = gate ? w2 : w1;
    const float* bias = gate ? b2 : b1;

    int g = blockIdx.x * 256 + threadIdx.x;
    int px4   = g % (HW/4);
    int plane = g / (HW/4);
    int ch = plane & (C4 - 1);
    int y  = px4 / (W/4);
    int x0 = (px4 % (W/4)) * 4;

    const float* p = inb + (size_t)plane*HW;
    const float* wp = wgt + ch*9;
    float w[9];
    #pragma unroll
    for (int k = 0; k < 9; k++) w[k] = wp[k];

    float A[3][6];
    #pragma unroll
    for (int kh = 0; kh < 3; kh++) {
        int yy = y + kh - 1;
        if ((unsigned)yy < H) {
            const float* row = p + yy*W;
            float4 m = *((const float4*)(row + x0));
            A[kh][0] = (x0 > 0)      ? row[x0 - 1] : 0.f;
            A[kh][1] = m.x; A[kh][2] = m.y; A[kh][3] = m.z; A[kh][4] = m.w;
            A[kh][5] = (x0 + 4 < W)  ? row[x0 + 4] : 0.f;
        } else {
            #pragma unroll
            for (int j = 0; j < 6; j++) A[kh][j] = 0.f;
        }
    }

    float bv = bias[ch];
    float r[4];
    #pragma unroll
    for (int j = 0; j < 4; j++) {
        float s = bv;
        #pragma unroll
        for (int kh = 0; kh < 3; kh++)
            #pragma unroll
            for (int kw = 0; kw < 3; kw++)
                s = fmaf(A[kh][j + kw], w[kh*3 + kw], s);
        r[j] = s;
    }
    *((float4*)(outb + (size_t)plane*HW + (size_t)y*W + x0)) = make_float4(r[0], r[1], r[2], r[3]);
}

// ---------------- pointwise contract 256->64, +bias, sigmoid ---------------------
// GATE=0: reads g_b1, writes g_g1. GATE=1: reads g_b2, combines, writes out slice.
// Input scratch selected in DEVICE code (never passed from host).
template<int GATE>
__global__ void __launch_bounds__(256) contract_kernel(const float* __restrict__ wgt,  // [64][256]
                                                       const float* __restrict__ bias,
                                                       float* __restrict__ outbase) {
    __shared__ float in_s[64][132];
    __shared__ float w_s[64][68];
    const float* inbase = GATE ? g_b2 : g_b1;
    int bi  = blockIdx.y;
    int px0 = blockIdx.x * 128;
    int tid = threadIdx.x;
    int pg = tid & 15;
    int og = tid >> 4;
    float acc[8][4];
    #pragma unroll
    for (int p = 0; p < 8; p++)
        #pragma unroll
        for (int o = 0; o < 4; o++) acc[p][o] = 0.f;

    const float* in = inbase + (size_t)bi*C4*HW + px0;

    for (int kc = 0; kc < C4; kc += 64) {
        for (int s = tid; s < 64*32; s += 256) {
            int ic = s >> 5, p4 = s & 31;
            float4 v = ((const float4*)(in + (size_t)(kc + ic)*HW))[p4];
            *((float4*)&in_s[ic][p4*4]) = v;
        }
        for (int s = tid; s < 64*64; s += 256) {
            int ic = s & 63, oc = s >> 6;
            w_s[ic][oc] = wgt[(size_t)oc*C4 + kc + ic];
        }
        __syncthreads();
        #pragma unroll
        for (int ic = 0; ic < 64; ic++) {
            float4 a0 = *((const float4*)&in_s[ic][pg*8]);
            float4 a1 = *((const float4*)&in_s[ic][pg*8 + 4]);
            float4 wv = *((const float4*)&w_s[ic][og*4]);
            float a[8] = {a0.x, a0.y, a0.z, a0.w, a1.x, a1.y, a1.z, a1.w};
            float wr[4] = {wv.x, wv.y, wv.z, wv.w};
            #pragma unroll
            for (int p = 0; p < 8; p++)
                #pragma unroll
                for (int o = 0; o < 4; o++) acc[p][o] = fmaf(a[p], wr[o], acc[p][o]);
        }
        __syncthreads();
    }

    #pragma unroll
    for (int o = 0; o < 4; o++) {
        int oc = og*4 + o;
        float bv = bias[oc];
        float g[8];
        #pragma unroll
        for (int p = 0; p < 8; p++) {
            float x = acc[p][o] + bv;
            g[p] = 1.0f / (1.0f + __expf(-x));
        }
        size_t poff = px0 + (size_t)pg*8;
        if (GATE == 0) {
            float4* gp = (float4*)(g_g1 + ((size_t)bi*C + oc)*HW + poff);
            gp[0] = make_float4(g[0], g[1], g[2], g[3]);
            gp[1] = make_float4(g[4], g[5], g[6], g[7]);
        } else {
            const float4* f1p = (const float4*)(g_fusion + ((size_t)bi*C2 + oc)*HW + poff);
            const float4* f2p = (const float4*)(g_fusion + ((size_t)bi*C2 + C + oc)*HW + poff);
            const float4* g1p = (const float4*)(g_g1 + ((size_t)bi*C + oc)*HW + poff);
            float4* op = (float4*)(outbase + (size_t)bi*TCHW + (size_t)oc*HW + poff);
            #pragma unroll
            for (int q = 0; q < 2; q++) {
                float4 f1 = f1p[q], f2 = f2p[q], g1 = g1p[q];
                float4 r;
                r.x = f1.x*g1.x + f2.x*g[q*4+0];
                r.y = f1.y*g1.y + f2.y*g[q*4+1];
                r.z = f1.z*g1.z + f2.z*g[q*4+2];
                r.w = f1.w*g1.w + f2.w*g[q*4+3];
                op[q] = r;
            }
        }
    }
}

// ---------------- launcher -------------------------------------------------------
extern "C" void kernel_launch(void* const* d_in, const int* in_sizes, int n_in,
                              void* d_out, int out_size) {
    (void)in_sizes; (void)n_in; (void)out_size;
    const float* feature   = (const float*)d_in[0];
    const float* kc_w1     = (const float*)d_in[1];
    const float* kc_gamma  = (const float*)d_in[2];
    const float* kc_beta   = (const float*)d_in[3];
    const float* kc_mean   = (const float*)d_in[4];
    const float* kc_var    = (const float*)d_in[5];
    const float* kc_w2     = (const float*)d_in[6];
    const float* kc_b2     = (const float*)d_in[7];
    const float* kc_bias   = (const float*)d_in[8];
    const float* conv1_w   = (const float*)d_in[9];
    const float* conv1_b   = (const float*)d_in[10];
    const float* pi1_w     = (const float*)d_in[11];
    const float* pi1_b     = (const float*)d_in[12];
    const float* dw1_w     = (const float*)d_in[13];
    const float* dw1_b     = (const float*)d_in[14];
    const float* po1_w     = (const float*)d_in[15];
    const float* po1_b     = (const float*)d_in[16];
    const float* pi2_w     = (const float*)d_in[17];
    const float* pi2_b     = (const float*)d_in[18];
    const float* dw2_w     = (const float*)d_in[19];
    const float* dw2_b     = (const float*)d_in[20];
    const float* po2_w     = (const float*)d_in[21];
    const float* po2_b     = (const float*)d_in[22];
    float* out = (float*)d_out;

    // out[:, T-1] = feature[:, T-1]
    for (int bi = 0; bi < BATCH; bi++) {
        size_t off = ((size_t)bi*T + (T-1)) * CHW;
        cudaMemcpyAsync(out + off, feature + off, (size_t)CHW*sizeof(float),
                        cudaMemcpyDeviceToDevice, 0);
    }

    for (int i = T - 2; i >= 0; --i) {
        const float* xbase = feature + (size_t)i*CHW;
        const float* ybase = out + (size_t)(i+1)*CHW;

        pool_kernel<<<BATCH*C, 256>>>(xbase);
        mlp_kernel<<<1, 128>>>(kc_w1, kc_gamma, kc_beta, kc_mean, kc_var, kc_w2, kc_b2);
        dyndw_kernel<<<(BATCH*CHW)/256, 256>>>(ybase, kc_bias);
        conv3x3_kernel<<<dim3(5, 10, BATCH*8), 256>>>(xbase, conv1_w, conv1_b);

        expand_both_kernel<<<dim3(HW/64, BATCH, 2), 256>>>(pi1_w, pi1_b, pi2_w, pi2_b);
        dw_both_kernel<<<dim3((BATCH*C4*HW/4)/256, 2), 256>>>(dw1_w, dw1_b, dw2_w, dw2_b);

        contract_kernel<0><<<dim3(HW/128, BATCH), 256>>>(po1_w, po1_b, nullptr);
        contract_kernel<1><<<dim3(HW/128, BATCH), 256>>>(po2_w, po2_b, out + (size_t)i*CHW);
    }
}

// round 8
// speedup vs baseline: 4.9418x; 1.3578x over previous
#include <cuda_runtime.h>
#include <cuda_fp16.h>
#include <math.h>

#define BATCH 2
#define T 8
#define C 64
#define R 16
#define H 160
#define W 160
#define HW (H*W)            // 25600
#define CHW (C*HW)          // 1,638,400
#define TCHW (T*CHW)
#define C2 128
#define C4 256

typedef unsigned long long ull;

// ---------------- scratch (device globals; referenced ONLY from device code) ----
__device__ float g_pool[BATCH*C];
__device__ float g_wd[BATCH*C*9];
__device__ float g_fp[BATCH*CHW];
__device__ float g_fusion[(size_t)BATCH*C2*HW];
__device__ float g_a1[(size_t)BATCH*C4*HW];
__device__ float g_b1[(size_t)BATCH*C4*HW];
__device__ float g_a2[(size_t)BATCH*C4*HW];
__device__ float g_b2[(size_t)BATCH*C4*HW];
__device__ float g_g1[BATCH*CHW];
// conv weights pre-split to fp16 hi/lo, ldmatrix-ready: [tap][chunk][oc=128][24(pad of 16 k)]
__device__ __half g_whi[9*8*128*24];
__device__ __half g_wlo[9*8*128*24];

// ---------------- mma helpers -----------------------------------------------------
__device__ __forceinline__ void ldsm4(unsigned* r, const void* p) {
    unsigned s = (unsigned)__cvta_generic_to_shared(p);
    asm volatile("ldmatrix.sync.aligned.m8n8.x4.shared.b16 {%0,%1,%2,%3}, [%4];"
        : "=r"(r[0]), "=r"(r[1]), "=r"(r[2]), "=r"(r[3]) : "r"(s));
}
__device__ __forceinline__ void mma16816(float* d, const unsigned* a, const unsigned* b) {
    asm volatile("mma.sync.aligned.m16n8k16.row.col.f32.f16.f16.f32 "
        "{%0,%1,%2,%3},{%4,%5,%6,%7},{%8,%9},{%0,%1,%2,%3};"
        : "+f"(d[0]), "+f"(d[1]), "+f"(d[2]), "+f"(d[3])
        : "r"(a[0]), "r"(a[1]), "r"(a[2]), "r"(a[3]), "r"(b[0]), "r"(b[1]));
}

// ---------------- pool ----------------------------------------------------------
__global__ void pool_kernel(const float* __restrict__ xbase) {
    int plane = blockIdx.x;
    int bi = plane >> 6, c = plane & 63;
    const float* p = xbase + (size_t)bi*TCHW + (size_t)c*HW;
    float s = 0.f;
    for (int i = threadIdx.x; i < HW; i += 256) s += p[i];
    __shared__ float red[8];
    #pragma unroll
    for (int o = 16; o; o >>= 1) s += __shfl_down_sync(0xffffffffu, s, o);
    if ((threadIdx.x & 31) == 0) red[threadIdx.x >> 5] = s;
    __syncthreads();
    if (threadIdx.x == 0) {
        float t = 0.f;
        #pragma unroll
        for (int k = 0; k < 8; k++) t += red[k];
        g_pool[plane] = t * (1.0f / (float)HW);
    }
}

// ---------------- tiny MLP ------------------------------------------------------
__global__ void mlp_kernel(const float* __restrict__ w1,
                           const float* __restrict__ gamma,
                           const float* __restrict__ beta,
                           const float* __restrict__ mean,
                           const float* __restrict__ var,
                           const float* __restrict__ w2,
                           const float* __restrict__ b2) {
    __shared__ float zs[BATCH*R];
    int tid = threadIdx.x;
    if (tid < BATCH*R) {
        int bi = tid / R, j = tid % R;
        float s = 0.f;
        for (int c = 0; c < C; c++) s = fmaf(g_pool[bi*C + c], w1[j*C + c], s);
        s = (s - mean[j]) * rsqrtf(var[j] + 1e-5f) * gamma[j] + beta[j];
        zs[tid] = fmaxf(s, 0.f);
    }
    __syncthreads();
    for (int o = tid; o < BATCH*C*9; o += blockDim.x) {
        int bi = o / (C*9), oo = o % (C*9);
        float s = b2[oo];
        #pragma unroll
        for (int j = 0; j < R; j++) s = fmaf(zs[bi*R + j], w2[oo*R + j], s);
        g_wd[o] = s;
    }
}

// ---------------- dynamic depthwise 3x3 -----------------------------------------
__global__ void dyndw_kernel(const float* __restrict__ ybase,
                             const float* __restrict__ kc_bias) {
    int idx = blockIdx.x * 256 + threadIdx.x;
    int px = idx % HW;
    int plane = idx / HW;
    int c = plane & 63, bi = plane >> 6;
    const float* p = ybase + (size_t)bi*TCHW + (size_t)c*HW;
    const float* wp = g_wd + plane*9;
    float w[9];
    #pragma unroll
    for (int k = 0; k < 9; k++) w[k] = wp[k];
    int y0 = px / W, x0 = px % W;
    float s = 0.f;
    #pragma unroll
    for (int kh = 0; kh < 3; kh++) {
        int yy = y0 + kh - 1;
        if ((unsigned)yy >= H) continue;
        const float* row = p + yy*W;
        #pragma unroll
        for (int kw = 0; kw < 3; kw++) {
            int xx = x0 + kw - 1;
            if ((unsigned)xx < W) s = fmaf(row[xx], w[kh*3 + kw], s);
        }
    }
    g_fp[idx] = s + kc_bias[c];
}

// ---------------- weight split prep (once per launch) ----------------------------
// conv1_w [oc=128][ic=128][tap=9] -> g_whi/g_wlo [tap][ch=ic/16][oc][24pad: k=ic%16]
__global__ void prep_w_kernel(const float* __restrict__ conv1_w) {
    int idx = blockIdx.x * 256 + threadIdx.x;      // 9*8*128*16 = 147456
    if (idx >= 9*8*128*16) return;
    int k   = idx & 15;
    int oc  = (idx >> 4) & 127;
    int ch  = (idx >> 11) & 7;
    int tap = idx >> 14;
    int ic = ch*16 + k;
    float v = conv1_w[((size_t)oc*C2 + ic)*9 + tap];
    __half h = __float2half_rn(v);
    __half l = __float2half_rn(v - __half2float(h));
    size_t o = ((size_t)(tap*8 + ch)*128 + oc)*24 + k;
    g_whi[o] = h;
    g_wlo[o] = l;
}

// ---------------- conv3x3 128->128 + leaky via fp16-split tensor mma -------------
// block 256 thr (8 warps: 4 m x 2 n); block tile: 128 oc x (2y x 32x) px.
// grid (W/32=5, H/2=80, BATCH). K = 9 taps x 128 ic, chunked by 16.
__global__ void __launch_bounds__(256, 2) conv_mma_kernel(const float* __restrict__ xbase,
                                                          const float* __restrict__ bias) {
    __shared__ __align__(16) __half Whi_s[128*24];
    __shared__ __align__(16) __half Wlo_s[128*24];
    __shared__ __align__(16) __half Xhi_s[64*24];
    __shared__ __align__(16) __half Xlo_s[64*24];

    int tid = threadIdx.x;
    int lane = tid & 31, wid = tid >> 5;
    int wm = wid & 3, wn = wid >> 2;
    int x0 = blockIdx.x * 32;
    int y0 = blockIdx.y * 2;
    int bi = blockIdx.z;

    const float* xp  = xbase + (size_t)bi*TCHW;
    const float* fpp = g_fp  + (size_t)bi*CHW;

    float acc[2][4][4];
    #pragma unroll
    for (int m = 0; m < 2; m++)
        #pragma unroll
        for (int n = 0; n < 4; n++)
            #pragma unroll
            for (int r = 0; r < 4; r++) acc[m][n][r] = 0.f;

    // X loader geometry: thread -> (ic_l, 4 consecutive n)
    int ic_l = tid >> 4;
    int sub  = tid & 15;
    int n0   = sub*4;
    int yy   = n0 >> 5;       // 0 or 1
    int xxb  = n0 & 31;

    // ldmatrix address patterns
    int a_row = (lane & 7) + ((lane >> 3) & 1)*8;
    int a_col = (lane >> 4)*8;
    int b_n   = (lane & 7) + ((lane >> 4) & 1)*8;
    int b_col = ((lane >> 3) & 1)*8;

    for (int tap = 0; tap < 9; tap++) {
        int dy = tap/3 - 1, dx = tap%3 - 1;
        int yq = y0 + yy + dy;
        bool yok = (unsigned)yq < H;
        const float4* wsrcH = (const float4*)(g_whi + (size_t)(tap*8)*128*24);
        const float4* wsrcL = (const float4*)(g_wlo + (size_t)(tap*8)*128*24);

        for (int ch = 0; ch < 8; ch++) {
            __syncthreads();
            // ---- stage X chunk [16 ic x 64 n], split fp32 -> hi/lo
            int ic = ch*16 + ic_l;
            const float* pl = (ic < C) ? (xp + (size_t)ic*HW) : (fpp + (size_t)(ic - C)*HW);
            const float* rowp = pl + yq*W;
            #pragma unroll
            for (int j = 0; j < 4; j++) {
                int xq = x0 + xxb + j + dx;
                float v = (yok && (unsigned)xq < W) ? __ldg(rowp + xq) : 0.f;
                __half h = __float2half_rn(v);
                __half l = __float2half_rn(v - __half2float(h));
                Xhi_s[(n0 + j)*24 + ic_l] = h;
                Xlo_s[(n0 + j)*24 + ic_l] = l;
            }
            // ---- stage W chunk [128 oc x 16 k] (pre-split, identical layout)
            {
                const float4* sH = wsrcH + (size_t)ch*384;   // 128*24*2B /16
                const float4* sL = wsrcL + (size_t)ch*384;
                ((float4*)Whi_s)[tid] = sH[tid];
                ((float4*)Wlo_s)[tid] = sL[tid];
                if (tid < 128) {
                    ((float4*)Whi_s)[256 + tid] = sH[256 + tid];
                    ((float4*)Wlo_s)[256 + tid] = sL[256 + tid];
                }
            }
            __syncthreads();

            // ---- fragments
            unsigned Ahi[2][4], Alo[2][4];
            ldsm4(Ahi[0], &Whi_s[(wm*32 +      a_row)*24 + a_col]);
            ldsm4(Ahi[1], &Whi_s[(wm*32 + 16 + a_row)*24 + a_col]);
            ldsm4(Alo[0], &Wlo_s[(wm*32 +      a_row)*24 + a_col]);
            ldsm4(Alo[1], &Wlo_s[(wm*32 + 16 + a_row)*24 + a_col]);
            unsigned Bhi[4][2], Blo[4][2];
            #pragma unroll
            for (int p = 0; p < 2; p++) {
                unsigned t[4];
                ldsm4(t, &Xhi_s[(wn*32 + p*16 + b_n)*24 + b_col]);
                Bhi[2*p][0] = t[0]; Bhi[2*p][1] = t[1];
                Bhi[2*p+1][0] = t[2]; Bhi[2*p+1][1] = t[3];
                ldsm4(t, &Xlo_s[(wn*32 + p*16 + b_n)*24 + b_col]);
                Blo[2*p][0] = t[0]; Blo[2*p][1] = t[1];
                Blo[2*p+1][0] = t[2]; Blo[2*p+1][1] = t[3];
            }
            // ---- 3-pass split mma: hi*hi + hi*lo + lo*hi
            #pragma unroll
            for (int m = 0; m < 2; m++)
                #pragma unroll
                for (int n = 0; n < 4; n++) {
                    mma16816(acc[m][n], Ahi[m], Bhi[n]);
                    mma16816(acc[m][n], Ahi[m], Blo[n]);
                    mma16816(acc[m][n], Alo[m], Bhi[n]);
                }
        }
    }

    // ---- epilogue: bias + leaky + store
    int row_ = lane >> 2;
    int colp = (lane & 3)*2;
    int yo = y0 + wn;
    #pragma unroll
    for (int m = 0; m < 2; m++) {
        int ocA = wm*32 + m*16 + row_;
        int ocB = ocA + 8;
        float bA = bias[ocA], bB = bias[ocB];
        #pragma unroll
        for (int n = 0; n < 4; n++) {
            int xo = x0 + n*8 + colp;
            float v0 = acc[m][n][0] + bA, v1 = acc[m][n][1] + bA;
            float v2 = acc[m][n][2] + bB, v3 = acc[m][n][3] + bB;
            v0 = (v0 > 0.f) ? v0 : 0.1f*v0;
            v1 = (v1 > 0.f) ? v1 : 0.1f*v1;
            v2 = (v2 > 0.f) ? v2 : 0.1f*v2;
            v3 = (v3 > 0.f) ? v3 : 0.1f*v3;
            *((float2*)(g_fusion + ((size_t)bi*C2 + ocA)*HW + (size_t)yo*W + xo)) = make_float2(v0, v1);
            *((float2*)(g_fusion + ((size_t)bi*C2 + ocB)*HW + (size_t)yo*W + xo)) = make_float2(v2, v3);
        }
    }
}

// ---------------- pointwise expand 64 -> 256, both gates in one launch ------------
__global__ void __launch_bounds__(256) expand_both_kernel(const float* __restrict__ w1,
                                                          const float* __restrict__ b1,
                                                          const float* __restrict__ w2,
                                                          const float* __restrict__ b2) {
    __shared__ float in_s[C][68];
    int gate = blockIdx.z;
    const float* wgt  = gate ? w2 : w1;
    const float* bias = gate ? b2 : b1;
    float* outbase    = gate ? g_a2 : g_a1;
    int halfoff       = gate ? C : 0;

    int bi  = blockIdx.y;
    int px0 = blockIdx.x * 64;
    int tid = threadIdx.x;
    const float* in = g_fusion + ((size_t)bi*C2 + halfoff)*HW + px0;
    for (int s = tid; s < C*16; s += 256) {
        int ic = s >> 4, p4 = s & 15;
        float4 v = ((const float4*)(in + (size_t)ic*HW))[p4];
        *((float4*)&in_s[ic][p4*4]) = v;
    }
    __syncthreads();

    int pg = tid & 7;
    int og = tid >> 3;
    float acc[8][8];
    #pragma unroll
    for (int p = 0; p < 8; p++)
        #pragma unroll
        for (int o = 0; o < 8; o++) acc[p][o] = 0.f;

    const float* wp = wgt + (size_t)og*8*C;
    for (int ic = 0; ic < C; ic++) {
        float4 a0 = *((const float4*)&in_s[ic][pg*8]);
        float4 a1 = *((const float4*)&in_s[ic][pg*8 + 4]);
        float a[8] = {a0.x, a0.y, a0.z, a0.w, a1.x, a1.y, a1.z, a1.w};
        float wv[8];
        #pragma unroll
        for (int o = 0; o < 8; o++) wv[o] = __ldg(wp + (size_t)o*C + ic);
        #pragma unroll
        for (int p = 0; p < 8; p++)
            #pragma unroll
            for (int o = 0; o < 8; o++) acc[p][o] = fmaf(a[p], wv[o], acc[p][o]);
    }
    float* outb = outbase + (size_t)bi*C4*HW + px0 + pg*8;
    #pragma unroll
    for (int o = 0; o < 8; o++) {
        int oc = og*8 + o;
        float bv = bias[oc];
        float4 v0 = make_float4(acc[0][o]+bv, acc[1][o]+bv, acc[2][o]+bv, acc[3][o]+bv);
        float4 v1 = make_float4(acc[4][o]+bv, acc[5][o]+bv, acc[6][o]+bv, acc[7][o]+bv);
        float4* op = (float4*)(outb + (size_t)oc*HW);
        op[0] = v0; op[1] = v1;
    }
}

// ---------------- static depthwise 3x3, 4px/thread, both gates --------------------
__global__ void __launch_bounds__(256) dw_both_kernel(const float* __restrict__ w1,
                                                      const float* __restrict__ b1,
                                                      const float* __restrict__ w2,
                                                      const float* __restrict__ b2) {
    int gate = blockIdx.y;
    const float* inb  = gate ? g_a2 : g_a1;
    float* outb       = gate ? g_b2 : g_b1;
    const float* wgt  = gate ? w2 : w1;
    const float* bias = gate ? b2 : b1;

    int g = blockIdx.x * 256 + threadIdx.x;
    int px4   = g % (HW/4);
    int plane = g / (HW/4);
    int ch = plane & (C4 - 1);
    int y  = px4 / (W/4);
    int x0 = (px4 % (W/4)) * 4;

    const float* p = inb + (size_t)plane*HW;
    const float* wp = wgt + ch*9;
    float w[9];
    #pragma unroll
    for (int k = 0; k < 9; k++) w[k] = wp[k];

    float A[3][6];
    #pragma unroll
    for (int kh = 0; kh < 3; kh++) {
        int yy = y + kh - 1;
        if ((unsigned)yy < H) {
            const float* row = p + yy*W;
            float4 m = *((const float4*)(row + x0));
            A[kh][0] = (x0 > 0)      ? row[x0 - 1] : 0.f;
            A[kh][1] = m.x; A[kh][2] = m.y; A[kh][3] = m.z; A[kh][4] = m.w;
            A[kh][5] = (x0 + 4 < W)  ? row[x0 + 4] : 0.f;
        } else {
            #pragma unroll
            for (int j = 0; j < 6; j++) A[kh][j] = 0.f;
        }
    }

    float bv = bias[ch];
    float r[4];
    #pragma unroll
    for (int j = 0; j < 4; j++) {
        float s = bv;
        #pragma unroll
        for (int kh = 0; kh < 3; kh++)
            #pragma unroll
            for (int kw = 0; kw < 3; kw++)
                s = fmaf(A[kh][j + kw], w[kh*3 + kw], s);
        r[j] = s;
    }
    *((float4*)(outb + (size_t)plane*HW + (size_t)y*W + x0)) = make_float4(r[0], r[1], r[2], r[3]);
}

// ---------------- pointwise contract 256->64, +bias, sigmoid ---------------------
template<int GATE>
__global__ void __launch_bounds__(256) contract_kernel(const float* __restrict__ wgt,
                                                       const float* __restrict__ bias,
                                                       float* __restrict__ outbase) {
    __shared__ float in_s[64][132];
    __shared__ float w_s[64][68];
    const float* inbase = GATE ? g_b2 : g_b1;
    int bi  = blockIdx.y;
    int px0 = blockIdx.x * 128;
    int tid = threadIdx.x;
    int pg = tid & 15;
    int og = tid >> 4;
    float acc[8][4];
    #pragma unroll
    for (int p = 0; p < 8; p++)
        #pragma unroll
        for (int o = 0; o < 4; o++) acc[p][o] = 0.f;

    const float* in = inbase + (size_t)bi*C4*HW + px0;

    for (int kc = 0; kc < C4; kc += 64) {
        for (int s = tid; s < 64*32; s += 256) {
            int ic = s >> 5, p4 = s & 31;
            float4 v = ((const float4*)(in + (size_t)(kc + ic)*HW))[p4];
            *((float4*)&in_s[ic][p4*4]) = v;
        }
        for (int s = tid; s < 64*64; s += 256) {
            int ic = s & 63, oc = s >> 6;
            w_s[ic][oc] = wgt[(size_t)oc*C4 + kc + ic];
        }
        __syncthreads();
        #pragma unroll
        for (int ic = 0; ic < 64; ic++) {
            float4 a0 = *((const float4*)&in_s[ic][pg*8]);
            float4 a1 = *((const float4*)&in_s[ic][pg*8 + 4]);
            float4 wv = *((const float4*)&w_s[ic][og*4]);
            float a[8] = {a0.x, a0.y, a0.z, a0.w, a1.x, a1.y, a1.z, a1.w};
            float wr[4] = {wv.x, wv.y, wv.z, wv.w};
            #pragma unroll
            for (int p = 0; p < 8; p++)
                #pragma unroll
                for (int o = 0; o < 4; o++) acc[p][o] = fmaf(a[p], wr[o], acc[p][o]);
        }
        __syncthreads();
    }

    #pragma unroll
    for (int o = 0; o < 4; o++) {
        int oc = og*4 + o;
        float bv = bias[oc];
        float g[8];
        #pragma unroll
        for (int p = 0; p < 8; p++) {
            float x = acc[p][o] + bv;
            g[p] = 1.0f / (1.0f + __expf(-x));
        }
        size_t poff = px0 + (size_t)pg*8;
        if (GATE == 0) {
            float4* gp = (float4*)(g_g1 + ((size_t)bi*C + oc)*HW + poff);
            gp[0] = make_float4(g[0], g[1], g[2], g[3]);
            gp[1] = make_float4(g[4], g[5], g[6], g[7]);
        } else {
            const float4* f1p = (const float4*)(g_fusion + ((size_t)bi*C2 + oc)*HW + poff);
            const float4* f2p = (const float4*)(g_fusion + ((size_t)bi*C2 + C + oc)*HW + poff);
            const float4* g1p = (const float4*)(g_g1 + ((size_t)bi*C + oc)*HW + poff);
            float4* op = (float4*)(outbase + (size_t)bi*TCHW + (size_t)oc*HW + poff);
            #pragma unroll
            for (int q = 0; q < 2; q++) {
                float4 f1 = f1p[q], f2 = f2p[q], g1 = g1p[q];
                float4 r;
                r.x = f1.x*g1.x + f2.x*g[q*4+0];
                r.y = f1.y*g1.y + f2.y*g[q*4+1];
                r.z = f1.z*g1.z + f2.z*g[q*4+2];
                r.w = f1.w*g1.w + f2.w*g[q*4+3];
                op[q] = r;
            }
        }
    }
}

// ---------------- launcher -------------------------------------------------------
extern "C" void kernel_launch(void* const* d_in, const int* in_sizes, int n_in,
                              void* d_out, int out_size) {
    (void)in_sizes; (void)n_in; (void)out_size;
    const float* feature   = (const float*)d_in[0];
    const float* kc_w1     = (const float*)d_in[1];
    const float* kc_gamma  = (const float*)d_in[2];
    const float* kc_beta   = (const float*)d_in[3];
    const float* kc_mean   = (const float*)d_in[4];
    const float* kc_var    = (const float*)d_in[5];
    const float* kc_w2     = (const float*)d_in[6];
    const float* kc_b2     = (const float*)d_in[7];
    const float* kc_bias   = (const float*)d_in[8];
    const float* conv1_w   = (const float*)d_in[9];
    const float* conv1_b   = (const float*)d_in[10];
    const float* pi1_w     = (const float*)d_in[11];
    const float* pi1_b     = (const float*)d_in[12];
    const float* dw1_w     = (const float*)d_in[13];
    const float* dw1_b     = (const float*)d_in[14];
    const float* po1_w     = (const float*)d_in[15];
    const float* po1_b     = (const float*)d_in[16];
    const float* pi2_w     = (const float*)d_in[17];
    const float* pi2_b     = (const float*)d_in[18];
    const float* dw2_w     = (const float*)d_in[19];
    const float* dw2_b     = (const float*)d_in[20];
    const float* po2_w     = (const float*)d_in[21];
    const float* po2_b     = (const float*)d_in[22];
    float* out = (float*)d_out;

    // out[:, T-1] = feature[:, T-1]
    for (int bi = 0; bi < BATCH; bi++) {
        size_t off = ((size_t)bi*T + (T-1)) * CHW;
        cudaMemcpyAsync(out + off, feature + off, (size_t)CHW*sizeof(float),
                        cudaMemcpyDeviceToDevice, 0);
    }

    // one-time per launch: split conv weights into fp16 hi/lo, ldmatrix layout
    prep_w_kernel<<<(9*8*128*16 + 255)/256, 256>>>(conv1_w);

    for (int i = T - 2; i >= 0; --i) {
        const float* xbase = feature + (size_t)i*CHW;
        const float* ybase = out + (size_t)(i+1)*CHW;

        pool_kernel<<<BATCH*C, 256>>>(xbase);
        mlp_kernel<<<1, 128>>>(kc_w1, kc_gamma, kc_beta, kc_mean, kc_var, kc_w2, kc_b2);
        dyndw_kernel<<<(BATCH*CHW)/256, 256>>>(ybase, kc_bias);
        conv_mma_kernel<<<dim3(W/32, H/2, BATCH), 256>>>(xbase, conv1_b);

        expand_both_kernel<<<dim3(HW/64, BATCH, 2), 256>>>(pi1_w, pi1_b, pi2_w, pi2_b);
        dw_both_kernel<<<dim3((BATCH*C4*HW/4)/256, 2), 256>>>(dw1_w, dw1_b, dw2_w, dw2_b);

        contract_kernel<0><<<dim3(HW/128, BATCH), 256>>>(po1_w, po1_b, nullptr);
        contract_kernel<1><<<dim3(HW/128, BATCH), 256>>>(po2_w, po2_b, out + (size_t)i*CHW);
    }
}

// round 9
// speedup vs baseline: 5.3270x; 1.0779x over previous
#include <cuda_runtime.h>
#include <cuda_fp16.h>
#include <math.h>

#define BATCH 2
#define T 8
#define C 64
#define R 16
#define H 160
#define W 160
#define HW (H*W)            // 25600
#define CHW (C*HW)          // 1,638,400
#define TCHW (T*CHW)
#define C2 128
#define C4 256

typedef unsigned long long ull;

// ---------------- scratch (device globals; referenced ONLY from device code) ----
__device__ float g_pool[BATCH*C];
__device__ float g_wd[BATCH*C*9];
__device__ float g_fp[BATCH*CHW];
__device__ float g_fusion[(size_t)BATCH*C2*HW];
__device__ float g_a1[(size_t)BATCH*C4*HW];
__device__ float g_b1[(size_t)BATCH*C4*HW];
__device__ float g_a2[(size_t)BATCH*C4*HW];
__device__ float g_b2[(size_t)BATCH*C4*HW];
__device__ float g_g1[BATCH*CHW];
// conv weights pre-split fp16 hi/lo, ldmatrix-ready [tap][ch8][oc128][24]
__device__ __half g_whi[9*8*128*24];
__device__ __half g_wlo[9*8*128*24];
// expand weights [gate][ch4][oc256][24]
__device__ __half g_pwhi[2*4*256*24];
__device__ __half g_pwlo[2*4*256*24];
// contract weights [gate][ch16][oc64][24]
__device__ __half g_cwhi[2*16*64*24];
__device__ __half g_cwlo[2*16*64*24];

// ---------------- mma helpers -----------------------------------------------------
__device__ __forceinline__ void ldsm4(unsigned* r, const void* p) {
    unsigned s = (unsigned)__cvta_generic_to_shared(p);
    asm volatile("ldmatrix.sync.aligned.m8n8.x4.shared.b16 {%0,%1,%2,%3}, [%4];"
        : "=r"(r[0]), "=r"(r[1]), "=r"(r[2]), "=r"(r[3]) : "r"(s));
}
__device__ __forceinline__ void mma16816(float* d, const unsigned* a, const unsigned* b) {
    asm volatile("mma.sync.aligned.m16n8k16.row.col.f32.f16.f16.f32 "
        "{%0,%1,%2,%3},{%4,%5,%6,%7},{%8,%9},{%0,%1,%2,%3};"
        : "+f"(d[0]), "+f"(d[1]), "+f"(d[2]), "+f"(d[3])
        : "r"(a[0]), "r"(a[1]), "r"(a[2]), "r"(a[3]), "r"(b[0]), "r"(b[1]));
}
__device__ __forceinline__ void split2(float v, __half& h, __half& l) {
    h = __float2half_rn(v);
    l = __float2half_rn(v - __half2float(h));
}

// ---------------- pool ----------------------------------------------------------
__global__ void pool_kernel(const float* __restrict__ xbase) {
    int plane = blockIdx.x;
    int bi = plane >> 6, c = plane & 63;
    const float* p = xbase + (size_t)bi*TCHW + (size_t)c*HW;
    float s = 0.f;
    for (int i = threadIdx.x; i < HW; i += 256) s += p[i];
    __shared__ float red[8];
    #pragma unroll
    for (int o = 16; o; o >>= 1) s += __shfl_down_sync(0xffffffffu, s, o);
    if ((threadIdx.x & 31) == 0) red[threadIdx.x >> 5] = s;
    __syncthreads();
    if (threadIdx.x == 0) {
        float t = 0.f;
        #pragma unroll
        for (int k = 0; k < 8; k++) t += red[k];
        g_pool[plane] = t * (1.0f / (float)HW);
    }
}

// ---------------- tiny MLP ------------------------------------------------------
__global__ void mlp_kernel(const float* __restrict__ w1,
                           const float* __restrict__ gamma,
                           const float* __restrict__ beta,
                           const float* __restrict__ mean,
                           const float* __restrict__ var,
                           const float* __restrict__ w2,
                           const float* __restrict__ b2) {
    __shared__ float zs[BATCH*R];
    int tid = threadIdx.x;
    if (tid < BATCH*R) {
        int bi = tid / R, j = tid % R;
        float s = 0.f;
        for (int c = 0; c < C; c++) s = fmaf(g_pool[bi*C + c], w1[j*C + c], s);
        s = (s - mean[j]) * rsqrtf(var[j] + 1e-5f) * gamma[j] + beta[j];
        zs[tid] = fmaxf(s, 0.f);
    }
    __syncthreads();
    for (int o = tid; o < BATCH*C*9; o += blockDim.x) {
        int bi = o / (C*9), oo = o % (C*9);
        float s = b2[oo];
        #pragma unroll
        for (int j = 0; j < R; j++) s = fmaf(zs[bi*R + j], w2[oo*R + j], s);
        g_wd[o] = s;
    }
}

// ---------------- dynamic depthwise 3x3 -----------------------------------------
__global__ void dyndw_kernel(const float* __restrict__ ybase,
                             const float* __restrict__ kc_bias) {
    int idx = blockIdx.x * 256 + threadIdx.x;
    int px = idx % HW;
    int plane = idx / HW;
    int c = plane & 63, bi = plane >> 6;
    const float* p = ybase + (size_t)bi*TCHW + (size_t)c*HW;
    const float* wp = g_wd + plane*9;
    float w[9];
    #pragma unroll
    for (int k = 0; k < 9; k++) w[k] = wp[k];
    int y0 = px / W, x0 = px % W;
    float s = 0.f;
    #pragma unroll
    for (int kh = 0; kh < 3; kh++) {
        int yy = y0 + kh - 1;
        if ((unsigned)yy >= H) continue;
        const float* row = p + yy*W;
        #pragma unroll
        for (int kw = 0; kw < 3; kw++) {
            int xx = x0 + kw - 1;
            if ((unsigned)xx < W) s = fmaf(row[xx], w[kh*3 + kw], s);
        }
    }
    g_fp[idx] = s + kc_bias[c];
}

// ---------------- weight split preps (once per launch) ---------------------------
__global__ void prep_w_kernel(const float* __restrict__ conv1_w) {
    int idx = blockIdx.x * 256 + threadIdx.x;      // 9*8*128*16 = 147456
    if (idx >= 9*8*128*16) return;
    int k   = idx & 15;
    int oc  = (idx >> 4) & 127;
    int ch  = (idx >> 11) & 7;
    int tap = idx >> 14;
    int ic = ch*16 + k;
    float v = conv1_w[((size_t)oc*C2 + ic)*9 + tap];
    __half h, l; split2(v, h, l);
    size_t o = ((size_t)(tap*8 + ch)*128 + oc)*24 + k;
    g_whi[o] = h; g_wlo[o] = l;
}
__global__ void prep_pw_kernel(const float* __restrict__ pi1_w, const float* __restrict__ pi2_w) {
    int idx = blockIdx.x * 256 + threadIdx.x;      // 2*4*256*16 = 32768
    if (idx >= 2*4*256*16) return;
    int k    = idx & 15;
    int oc   = (idx >> 4) & 255;
    int ch   = (idx >> 12) & 3;
    int gate = idx >> 14;
    const float* w = gate ? pi2_w : pi1_w;         // [256][64]
    float v = w[(size_t)oc*C + ch*16 + k];
    __half h, l; split2(v, h, l);
    size_t o = ((size_t)(gate*4 + ch)*256 + oc)*24 + k;
    g_pwhi[o] = h; g_pwlo[o] = l;
}
__global__ void prep_cw_kernel(const float* __restrict__ po1_w, const float* __restrict__ po2_w) {
    int idx = blockIdx.x * 256 + threadIdx.x;      // 2*16*64*16 = 32768
    if (idx >= 2*16*64*16) return;
    int k    = idx & 15;
    int oc   = (idx >> 4) & 63;
    int ch   = (idx >> 10) & 15;
    int gate = idx >> 14;
    const float* w = gate ? po2_w : po1_w;         // [64][256]
    float v = w[(size_t)oc*C4 + ch*16 + k];
    __half h, l; split2(v, h, l);
    size_t o = ((size_t)(gate*16 + ch)*64 + oc)*24 + k;
    g_cwhi[o] = h; g_cwlo[o] = l;
}

// ---------------- conv3x3 128->128 + leaky via fp16-split tensor mma (R8) --------
__global__ void __launch_bounds__(256, 2) conv_mma_kernel(const float* __restrict__ xbase,
                                                          const float* __restrict__ bias) {
    __shared__ __align__(16) __half Whi_s[128*24];
    __shared__ __align__(16) __half Wlo_s[128*24];
    __shared__ __align__(16) __half Xhi_s[64*24];
    __shared__ __align__(16) __half Xlo_s[64*24];

    int tid = threadIdx.x;
    int lane = tid & 31, wid = tid >> 5;
    int wm = wid & 3, wn = wid >> 2;
    int x0 = blockIdx.x * 32;
    int y0 = blockIdx.y * 2;
    int bi = blockIdx.z;

    const float* xp  = xbase + (size_t)bi*TCHW;
    const float* fpp = g_fp  + (size_t)bi*CHW;

    float acc[2][4][4];
    #pragma unroll
    for (int m = 0; m < 2; m++)
        #pragma unroll
        for (int n = 0; n < 4; n++)
            #pragma unroll
            for (int r = 0; r < 4; r++) acc[m][n][r] = 0.f;

    int ic_l = tid >> 4;
    int sub  = tid & 15;
    int n0   = sub*4;
    int yy   = n0 >> 5;
    int xxb  = n0 & 31;

    int a_row = (lane & 7) + ((lane >> 3) & 1)*8;
    int a_col = (lane >> 4)*8;
    int b_n   = (lane & 7) + ((lane >> 4) & 1)*8;
    int b_col = ((lane >> 3) & 1)*8;

    for (int tap = 0; tap < 9; tap++) {
        int dy = tap/3 - 1, dx = tap%3 - 1;
        int yq = y0 + yy + dy;
        bool yok = (unsigned)yq < H;
        const float4* wsrcH = (const float4*)(g_whi + (size_t)(tap*8)*128*24);
        const float4* wsrcL = (const float4*)(g_wlo + (size_t)(tap*8)*128*24);

        for (int ch = 0; ch < 8; ch++) {
            __syncthreads();
            int ic = ch*16 + ic_l;
            const float* pl = (ic < C) ? (xp + (size_t)ic*HW) : (fpp + (size_t)(ic - C)*HW);
            const float* rowp = pl + yq*W;
            #pragma unroll
            for (int j = 0; j < 4; j++) {
                int xq = x0 + xxb + j + dx;
                float v = (yok && (unsigned)xq < W) ? __ldg(rowp + xq) : 0.f;
                __half h, l; split2(v, h, l);
                Xhi_s[(n0 + j)*24 + ic_l] = h;
                Xlo_s[(n0 + j)*24 + ic_l] = l;
            }
            {
                const float4* sH = wsrcH + (size_t)ch*384;
                const float4* sL = wsrcL + (size_t)ch*384;
                ((float4*)Whi_s)[tid] = sH[tid];
                ((float4*)Wlo_s)[tid] = sL[tid];
                if (tid < 128) {
                    ((float4*)Whi_s)[256 + tid] = sH[256 + tid];
                    ((float4*)Wlo_s)[256 + tid] = sL[256 + tid];
                }
            }
            __syncthreads();

            unsigned Ahi[2][4], Alo[2][4];
            ldsm4(Ahi[0], &Whi_s[(wm*32 +      a_row)*24 + a_col]);
            ldsm4(Ahi[1], &Whi_s[(wm*32 + 16 + a_row)*24 + a_col]);
            ldsm4(Alo[0], &Wlo_s[(wm*32 +      a_row)*24 + a_col]);
            ldsm4(Alo[1], &Wlo_s[(wm*32 + 16 + a_row)*24 + a_col]);
            unsigned Bhi[4][2], Blo[4][2];
            #pragma unroll
            for (int p = 0; p < 2; p++) {
                unsigned t[4];
                ldsm4(t, &Xhi_s[(wn*32 + p*16 + b_n)*24 + b_col]);
                Bhi[2*p][0] = t[0]; Bhi[2*p][1] = t[1];
                Bhi[2*p+1][0] = t[2]; Bhi[2*p+1][1] = t[3];
                ldsm4(t, &Xlo_s[(wn*32 + p*16 + b_n)*24 + b_col]);
                Blo[2*p][0] = t[0]; Blo[2*p][1] = t[1];
                Blo[2*p+1][0] = t[2]; Blo[2*p+1][1] = t[3];
            }
            #pragma unroll
            for (int m = 0; m < 2; m++)
                #pragma unroll
                for (int n = 0; n < 4; n++) {
                    mma16816(acc[m][n], Ahi[m], Bhi[n]);
                    mma16816(acc[m][n], Ahi[m], Blo[n]);
                    mma16816(acc[m][n], Alo[m], Bhi[n]);
                }
        }
    }

    int row_ = lane >> 2;
    int colp = (lane & 3)*2;
    int yo = y0 + wn;
    #pragma unroll
    for (int m = 0; m < 2; m++) {
        int ocA = wm*32 + m*16 + row_;
        int ocB = ocA + 8;
        float bA = bias[ocA], bB = bias[ocB];
        #pragma unroll
        for (int n = 0; n < 4; n++) {
            int xo = x0 + n*8 + colp;
            float v0 = acc[m][n][0] + bA, v1 = acc[m][n][1] + bA;
            float v2 = acc[m][n][2] + bB, v3 = acc[m][n][3] + bB;
            v0 = (v0 > 0.f) ? v0 : 0.1f*v0;
            v1 = (v1 > 0.f) ? v1 : 0.1f*v1;
            v2 = (v2 > 0.f) ? v2 : 0.1f*v2;
            v3 = (v3 > 0.f) ? v3 : 0.1f*v3;
            *((float2*)(g_fusion + ((size_t)bi*C2 + ocA)*HW + (size_t)yo*W + xo)) = make_float2(v0, v1);
            *((float2*)(g_fusion + ((size_t)bi*C2 + ocB)*HW + (size_t)yo*W + xo)) = make_float2(v2, v3);
        }
    }
}

// ---------------- expand via mma: D[128oc x 64px], K=64 ---------------------------
// grid (HW/64, 4, BATCH); y = gate*2 + oc-half
__global__ void __launch_bounds__(256, 2) expand_mma_kernel(const float* __restrict__ b1,
                                                            const float* __restrict__ b2) {
    __shared__ __align__(16) __half Whi_s[128*24];
    __shared__ __align__(16) __half Wlo_s[128*24];
    __shared__ __align__(16) __half Xhi_s[64*24];
    __shared__ __align__(16) __half Xlo_s[64*24];

    int tid = threadIdx.x;
    int lane = tid & 31, wid = tid >> 5;
    int wm = wid & 3, wn = wid >> 2;
    int px0 = blockIdx.x * 64;
    int gy  = blockIdx.y;
    int gate = gy >> 1, hh = gy & 1;
    int bi = blockIdx.z;

    const float* bias = gate ? b2 : b1;
    float* outb       = gate ? g_a2 : g_a1;
    int halfoff       = gate ? C : 0;

    float acc[2][4][4];
    #pragma unroll
    for (int m = 0; m < 2; m++)
        #pragma unroll
        for (int n = 0; n < 4; n++)
            #pragma unroll
            for (int r = 0; r < 4; r++) acc[m][n][r] = 0.f;

    int ic_l = tid >> 4;
    int n0   = (tid & 15)*4;

    int a_row = (lane & 7) + ((lane >> 3) & 1)*8;
    int a_col = (lane >> 4)*8;
    int b_n   = (lane & 7) + ((lane >> 4) & 1)*8;
    int b_col = ((lane >> 3) & 1)*8;

    #pragma unroll
    for (int ch = 0; ch < 4; ch++) {
        __syncthreads();
        // stage X [16ic x 64px]
        {
            const float* src = g_fusion + ((size_t)(bi*C2 + halfoff + ch*16 + ic_l))*HW + px0 + n0;
            float4 v = *((const float4*)src);
            float vv[4] = {v.x, v.y, v.z, v.w};
            #pragma unroll
            for (int j = 0; j < 4; j++) {
                __half h, l; split2(vv[j], h, l);
                Xhi_s[(n0 + j)*24 + ic_l] = h;
                Xlo_s[(n0 + j)*24 + ic_l] = l;
            }
        }
        // stage W [128oc x 16k]: 3072 halves = 384 float4 per buf
        {
            const float4* sH = (const float4*)(g_pwhi + ((size_t)(gate*4 + ch)*256 + hh*128)*24);
            const float4* sL = (const float4*)(g_pwlo + ((size_t)(gate*4 + ch)*256 + hh*128)*24);
            ((float4*)Whi_s)[tid] = sH[tid];
            ((float4*)Wlo_s)[tid] = sL[tid];
            if (tid < 128) {
                ((float4*)Whi_s)[256 + tid] = sH[256 + tid];
                ((float4*)Wlo_s)[256 + tid] = sL[256 + tid];
            }
        }
        __syncthreads();

        unsigned Ahi[2][4], Alo[2][4];
        ldsm4(Ahi[0], &Whi_s[(wm*32 +      a_row)*24 + a_col]);
        ldsm4(Ahi[1], &Whi_s[(wm*32 + 16 + a_row)*24 + a_col]);
        ldsm4(Alo[0], &Wlo_s[(wm*32 +      a_row)*24 + a_col]);
        ldsm4(Alo[1], &Wlo_s[(wm*32 + 16 + a_row)*24 + a_col]);
        unsigned Bhi[4][2], Blo[4][2];
        #pragma unroll
        for (int p = 0; p < 2; p++) {
            unsigned t[4];
            ldsm4(t, &Xhi_s[(wn*32 + p*16 + b_n)*24 + b_col]);
            Bhi[2*p][0] = t[0]; Bhi[2*p][1] = t[1];
            Bhi[2*p+1][0] = t[2]; Bhi[2*p+1][1] = t[3];
            ldsm4(t, &Xlo_s[(wn*32 + p*16 + b_n)*24 + b_col]);
            Blo[2*p][0] = t[0]; Blo[2*p][1] = t[1];
            Blo[2*p+1][0] = t[2]; Blo[2*p+1][1] = t[3];
        }
        #pragma unroll
        for (int m = 0; m < 2; m++)
            #pragma unroll
            for (int n = 0; n < 4; n++) {
                mma16816(acc[m][n], Ahi[m], Bhi[n]);
                mma16816(acc[m][n], Ahi[m], Blo[n]);
                mma16816(acc[m][n], Alo[m], Bhi[n]);
            }
    }

    int row_ = lane >> 2;
    int colp = (lane & 3)*2;
    #pragma unroll
    for (int m = 0; m < 2; m++) {
        int ocA = hh*128 + wm*32 + m*16 + row_;
        int ocB = ocA + 8;
        float bA = bias[ocA], bB = bias[ocB];
        #pragma unroll
        for (int n = 0; n < 4; n++) {
            int xo = px0 + wn*32 + n*8 + colp;
            *((float2*)(outb + ((size_t)bi*C4 + ocA)*HW + xo)) =
                make_float2(acc[m][n][0] + bA, acc[m][n][1] + bA);
            *((float2*)(outb + ((size_t)bi*C4 + ocB)*HW + xo)) =
                make_float2(acc[m][n][2] + bB, acc[m][n][3] + bB);
        }
    }
}

// ---------------- static depthwise 3x3, 4px/thread, both gates --------------------
__global__ void __launch_bounds__(256) dw_both_kernel(const float* __restrict__ w1,
                                                      const float* __restrict__ b1,
                                                      const float* __restrict__ w2,
                                                      const float* __restrict__ b2) {
    int gate = blockIdx.y;
    const float* inb  = gate ? g_a2 : g_a1;
    float* outb       = gate ? g_b2 : g_b1;
    const float* wgt  = gate ? w2 : w1;
    const float* bias = gate ? b2 : b1;

    int g = blockIdx.x * 256 + threadIdx.x;
    int px4   = g % (HW/4);
    int plane = g / (HW/4);
    int ch = plane & (C4 - 1);
    int y  = px4 / (W/4);
    int x0 = (px4 % (W/4)) * 4;

    const float* p = inb + (size_t)plane*HW;
    const float* wp = wgt + ch*9;
    float w[9];
    #pragma unroll
    for (int k = 0; k < 9; k++) w[k] = wp[k];

    float A[3][6];
    #pragma unroll
    for (int kh = 0; kh < 3; kh++) {
        int yy = y + kh - 1;
        if ((unsigned)yy < H) {
            const float* row = p + yy*W;
            float4 m = *((const float4*)(row + x0));
            A[kh][0] = (x0 > 0)      ? row[x0 - 1] : 0.f;
            A[kh][1] = m.x; A[kh][2] = m.y; A[kh][3] = m.z; A[kh][4] = m.w;
            A[kh][5] = (x0 + 4 < W)  ? row[x0 + 4] : 0.f;
        } else {
            #pragma unroll
            for (int j = 0; j < 6; j++) A[kh][j] = 0.f;
        }
    }

    float bv = bias[ch];
    float r[4];
    #pragma unroll
    for (int j = 0; j < 4; j++) {
        float s = bv;
        #pragma unroll
        for (int kh = 0; kh < 3; kh++)
            #pragma unroll
            for (int kw = 0; kw < 3; kw++)
                s = fmaf(A[kh][j + kw], w[kh*3 + kw], s);
        r[j] = s;
    }
    *((float4*)(outb + (size_t)plane*HW + (size_t)y*W + x0)) = make_float4(r[0], r[1], r[2], r[3]);
}

// ---------------- contract via mma: D[64oc x 128px], K=256 ------------------------
// GATE=0: sigmoid -> g_g1. GATE=1: sigmoid + combine -> out slice.
// grid (HW/128, BATCH)
template<int GATE>
__global__ void __launch_bounds__(256, 2) contract_mma_kernel(const float* __restrict__ bias,
                                                              float* __restrict__ outbase) {
    __shared__ __align__(16) __half Ahi_s[64*24];
    __shared__ __align__(16) __half Alo_s[64*24];
    __shared__ __align__(16) __half Bhi_s[128*24];
    __shared__ __align__(16) __half Blo_s[128*24];

    int tid = threadIdx.x;
    int lane = tid & 31, wid = tid >> 5;
    int wm = wid & 1, wn = wid >> 1;
    int px0 = blockIdx.x * 128;
    int bi = blockIdx.y;

    const float* inb = GATE ? g_b2 : g_b1;

    float acc[2][4][4];
    #pragma unroll
    for (int m = 0; m < 2; m++)
        #pragma unroll
        for (int n = 0; n < 4; n++)
            #pragma unroll
            for (int r = 0; r < 4; r++) acc[m][n][r] = 0.f;

    int ic_l = tid >> 4;
    int n0   = (tid & 15)*8;

    int a_row = (lane & 7) + ((lane >> 3) & 1)*8;
    int a_col = (lane >> 4)*8;
    int b_n   = (lane & 7) + ((lane >> 4) & 1)*8;
    int b_col = ((lane >> 3) & 1)*8;

    for (int ch = 0; ch < 16; ch++) {
        __syncthreads();
        // stage B [16ic x 128px]
        {
            const float* src = inb + ((size_t)(bi*C4 + ch*16 + ic_l))*HW + px0 + n0;
            float4 v0 = ((const float4*)src)[0];
            float4 v1 = ((const float4*)src)[1];
            float vv[8] = {v0.x, v0.y, v0.z, v0.w, v1.x, v1.y, v1.z, v1.w};
            #pragma unroll
            for (int j = 0; j < 8; j++) {
                __half h, l; split2(vv[j], h, l);
                Bhi_s[(n0 + j)*24 + ic_l] = h;
                Blo_s[(n0 + j)*24 + ic_l] = l;
            }
        }
        // stage A [64oc x 16k]: 1536 halves = 192 float4 per buf
        if (tid < 192) {
            const float4* sH = (const float4*)(g_cwhi + ((size_t)(GATE*16 + ch)*64)*24);
            const float4* sL = (const float4*)(g_cwlo + ((size_t)(GATE*16 + ch)*64)*24);
            ((float4*)Ahi_s)[tid] = sH[tid];
            ((float4*)Alo_s)[tid] = sL[tid];
        }
        __syncthreads();

        unsigned Ahi[2][4], Alo[2][4];
        ldsm4(Ahi[0], &Ahi_s[(wm*32 +      a_row)*24 + a_col]);
        ldsm4(Ahi[1], &Ahi_s[(wm*32 + 16 + a_row)*24 + a_col]);
        ldsm4(Alo[0], &Alo_s[(wm*32 +      a_row)*24 + a_col]);
        ldsm4(Alo[1], &Alo_s[(wm*32 + 16 + a_row)*24 + a_col]);
        unsigned Bhi[4][2], Blo[4][2];
        #pragma unroll
        for (int p = 0; p < 2; p++) {
            unsigned t[4];
            ldsm4(t, &Bhi_s[(wn*32 + p*16 + b_n)*24 + b_col]);
            Bhi[2*p][0] = t[0]; Bhi[2*p][1] = t[1];
            Bhi[2*p+1][0] = t[2]; Bhi[2*p+1][1] = t[3];
            ldsm4(t, &Blo_s[(wn*32 + p*16 + b_n)*24 + b_col]);
            Blo[2*p][0] = t[0]; Blo[2*p][1] = t[1];
            Blo[2*p+1][0] = t[2]; Blo[2*p+1][1] = t[3];
        }
        #pragma unroll
        for (int m = 0; m < 2; m++)
            #pragma unroll
            for (int n = 0; n < 4; n++) {
                mma16816(acc[m][n], Ahi[m], Bhi[n]);
                mma16816(acc[m][n], Ahi[m], Blo[n]);
                mma16816(acc[m][n], Alo[m], Bhi[n]);
            }
    }

    int row_ = lane >> 2;
    int colp = (lane & 3)*2;
    #pragma unroll
    for (int m = 0; m < 2; m++) {
        int ocA = wm*32 + m*16 + row_;
        int ocB = ocA + 8;
        float bA = bias[ocA], bB = bias[ocB];
        #pragma unroll
        for (int n = 0; n < 4; n++) {
            int xo = px0 + wn*32 + n*8 + colp;
            float gA0 = 1.0f / (1.0f + __expf(-(acc[m][n][0] + bA)));
            float gA1 = 1.0f / (1.0f + __expf(-(acc[m][n][1] + bA)));
            float gB0 = 1.0f / (1.0f + __expf(-(acc[m][n][2] + bB)));
            float gB1 = 1.0f / (1.0f + __expf(-(acc[m][n][3] + bB)));
            if (GATE == 0) {
                *((float2*)(g_g1 + ((size_t)bi*C + ocA)*HW + xo)) = make_float2(gA0, gA1);
                *((float2*)(g_g1 + ((size_t)bi*C + ocB)*HW + xo)) = make_float2(gB0, gB1);
            } else {
                float2 f1A = *((const float2*)(g_fusion + ((size_t)bi*C2 + ocA)*HW + xo));
                float2 f2A = *((const float2*)(g_fusion + ((size_t)bi*C2 + C + ocA)*HW + xo));
                float2 g1A = *((const float2*)(g_g1 + ((size_t)bi*C + ocA)*HW + xo));
                float2 f1B = *((const float2*)(g_fusion + ((size_t)bi*C2 + ocB)*HW + xo));
                float2 f2B = *((const float2*)(g_fusion + ((size_t)bi*C2 + C + ocB)*HW + xo));
                float2 g1B = *((const float2*)(g_g1 + ((size_t)bi*C + ocB)*HW + xo));
                *((float2*)(outbase + (size_t)bi*TCHW + (size_t)ocA*HW + xo)) =
                    make_float2(f1A.x*g1A.x + f2A.x*gA0, f1A.y*g1A.y + f2A.y*gA1);
                *((float2*)(outbase + (size_t)bi*TCHW + (size_t)ocB*HW + xo)) =
                    make_float2(f1B.x*g1B.x + f2B.x*gB0, f1B.y*g1B.y + f2B.y*gB1);
            }
        }
    }
}

// ---------------- launcher -------------------------------------------------------
extern "C" void kernel_launch(void* const* d_in, const int* in_sizes, int n_in,
                              void* d_out, int out_size) {
    (void)in_sizes; (void)n_in; (void)out_size;
    const float* feature   = (const float*)d_in[0];
    const float* kc_w1     = (const float*)d_in[1];
    const float* kc_gamma  = (const float*)d_in[2];
    const float* kc_beta   = (const float*)d_in[3];
    const float* kc_mean   = (const float*)d_in[4];
    const float* kc_var    = (const float*)d_in[5];
    const float* kc_w2     = (const float*)d_in[6];
    const float* kc_b2     = (const float*)d_in[7];
    const float* kc_bias   = (const float*)d_in[8];
    const float* conv1_w   = (const float*)d_in[9];
    const float* conv1_b   = (const float*)d_in[10];
    const float* pi1_w     = (const float*)d_in[11];
    const float* pi1_b     = (const float*)d_in[12];
    const float* dw1_w     = (const float*)d_in[13];
    const float* dw1_b     = (const float*)d_in[14];
    const float* po1_w     = (const float*)d_in[15];
    const float* po1_b     = (const float*)d_in[16];
    const float* pi2_w     = (const float*)d_in[17];
    const float* pi2_b     = (const float*)d_in[18];
    const float* dw2_w     = (const float*)d_in[19];
    const float* dw2_b     = (const float*)d_in[20];
    const float* po2_w     = (const float*)d_in[21];
    const float* po2_b     = (const float*)d_in[22];
    float* out = (float*)d_out;

    // out[:, T-1] = feature[:, T-1]
    for (int bi = 0; bi < BATCH; bi++) {
        size_t off = ((size_t)bi*T + (T-1)) * CHW;
        cudaMemcpyAsync(out + off, feature + off, (size_t)CHW*sizeof(float),
                        cudaMemcpyDeviceToDevice, 0);
    }

    // one-time per launch: weight splits
    prep_w_kernel<<<(9*8*128*16 + 255)/256, 256>>>(conv1_w);
    prep_pw_kernel<<<(2*4*256*16 + 255)/256, 256>>>(pi1_w, pi2_w);
    prep_cw_kernel<<<(2*16*64*16 + 255)/256, 256>>>(po1_w, po2_w);

    for (int i = T - 2; i >= 0; --i) {
        const float* xbase = feature + (size_t)i*CHW;
        const float* ybase = out + (size_t)(i+1)*CHW;

        pool_kernel<<<BATCH*C, 256>>>(xbase);
        mlp_kernel<<<1, 128>>>(kc_w1, kc_gamma, kc_beta, kc_mean, kc_var, kc_w2, kc_b2);
        dyndw_kernel<<<(BATCH*CHW)/256, 256>>>(ybase, kc_bias);
        conv_mma_kernel<<<dim3(W/32, H/2, BATCH), 256>>>(xbase, conv1_b);

        expand_mma_kernel<<<dim3(HW/64, 4, BATCH), 256>>>(pi1_b, pi2_b);
        dw_both_kernel<<<dim3((BATCH*C4*HW/4)/256, 2), 256>>>(dw1_w, dw1_b, dw2_w, dw2_b);

        contract_mma_kernel<0><<<dim3(HW/128, BATCH), 256>>>(po1_b, nullptr);
        contract_mma_kernel<1><<<dim3(HW/128, BATCH), 256>>>(po2_b, out + (size_t)i*CHW);
    }
}

// round 10
// speedup vs baseline: 6.8899x; 1.2934x over previous
#include <cuda_runtime.h>
#include <cuda_fp16.h>
#include <math.h>

#define BATCH 2
#define T 8
#define C 64
#define R 16
#define H 160
#define W 160
#define HW (H*W)            // 25600
#define CHW (C*HW)          // 1,638,400
#define TCHW (T*CHW)
#define C2 128
#define C4 256

typedef unsigned long long ull;

// ---------------- scratch (device globals; referenced ONLY from device code) ----
__device__ float g_pool[BATCH*C];
__device__ float g_wd[BATCH*C*9];
__device__ float g_fp[BATCH*CHW];
__device__ float g_fusion[(size_t)BATCH*C2*HW];
__device__ float g_a1[(size_t)BATCH*C4*HW];
__device__ float g_a2[(size_t)BATCH*C4*HW];
// dw outputs as split fp16 (hi/lo) — consumed directly by contract mma staging
__device__ __half g_bh1[(size_t)BATCH*C4*HW];
__device__ __half g_bl1[(size_t)BATCH*C4*HW];
__device__ __half g_bh2[(size_t)BATCH*C4*HW];
__device__ __half g_bl2[(size_t)BATCH*C4*HW];
__device__ float g_g1[BATCH*CHW];
// conv weights pre-split fp16 hi/lo, ldmatrix-ready [tap][ch8][oc128][24]
__device__ __half g_whi[9*8*128*24];
__device__ __half g_wlo[9*8*128*24];
// expand weights [gate][ch4][oc256][24]
__device__ __half g_pwhi[2*4*256*24];
__device__ __half g_pwlo[2*4*256*24];
// contract weights [gate][ch16][oc64][24]
__device__ __half g_cwhi[2*16*64*24];
__device__ __half g_cwlo[2*16*64*24];

// ---------------- mma helpers -----------------------------------------------------
__device__ __forceinline__ void ldsm4(unsigned* r, const void* p) {
    unsigned s = (unsigned)__cvta_generic_to_shared(p);
    asm volatile("ldmatrix.sync.aligned.m8n8.x4.shared.b16 {%0,%1,%2,%3}, [%4];"
        : "=r"(r[0]), "=r"(r[1]), "=r"(r[2]), "=r"(r[3]) : "r"(s));
}
__device__ __forceinline__ void mma16816(float* d, const unsigned* a, const unsigned* b) {
    asm volatile("mma.sync.aligned.m16n8k16.row.col.f32.f16.f16.f32 "
        "{%0,%1,%2,%3},{%4,%5,%6,%7},{%8,%9},{%0,%1,%2,%3};"
        : "+f"(d[0]), "+f"(d[1]), "+f"(d[2]), "+f"(d[3])
        : "r"(a[0]), "r"(a[1]), "r"(a[2]), "r"(a[3]), "r"(b[0]), "r"(b[1]));
}
__device__ __forceinline__ void split2(float v, __half& h, __half& l) {
    h = __float2half_rn(v);
    l = __float2half_rn(v - __half2float(h));
}

// ---------------- pool ----------------------------------------------------------
__global__ void pool_kernel(const float* __restrict__ xbase) {
    int plane = blockIdx.x;
    int bi = plane >> 6, c = plane & 63;
    const float* p = xbase + (size_t)bi*TCHW + (size_t)c*HW;
    float s = 0.f;
    for (int i = threadIdx.x; i < HW; i += 256) s += p[i];
    __shared__ float red[8];
    #pragma unroll
    for (int o = 16; o; o >>= 1) s += __shfl_down_sync(0xffffffffu, s, o);
    if ((threadIdx.x & 31) == 0) red[threadIdx.x >> 5] = s;
    __syncthreads();
    if (threadIdx.x == 0) {
        float t = 0.f;
        #pragma unroll
        for (int k = 0; k < 8; k++) t += red[k];
        g_pool[plane] = t * (1.0f / (float)HW);
    }
}

// ---------------- tiny MLP ------------------------------------------------------
__global__ void mlp_kernel(const float* __restrict__ w1,
                           const float* __restrict__ gamma,
                           const float* __restrict__ beta,
                           const float* __restrict__ mean,
                           const float* __restrict__ var,
                           const float* __restrict__ w2,
                           const float* __restrict__ b2) {
    __shared__ float zs[BATCH*R];
    int tid = threadIdx.x;
    if (tid < BATCH*R) {
        int bi = tid / R, j = tid % R;
        float s = 0.f;
        for (int c = 0; c < C; c++) s = fmaf(g_pool[bi*C + c], w1[j*C + c], s);
        s = (s - mean[j]) * rsqrtf(var[j] + 1e-5f) * gamma[j] + beta[j];
        zs[tid] = fmaxf(s, 0.f);
    }
    __syncthreads();
    for (int o = tid; o < BATCH*C*9; o += blockDim.x) {
        int bi = o / (C*9), oo = o % (C*9);
        float s = b2[oo];
        #pragma unroll
        for (int j = 0; j < R; j++) s = fmaf(zs[bi*R + j], w2[oo*R + j], s);
        g_wd[o] = s;
    }
}

// ---------------- dynamic depthwise 3x3 -----------------------------------------
__global__ void dyndw_kernel(const float* __restrict__ ybase,
                             const float* __restrict__ kc_bias) {
    int idx = blockIdx.x * 256 + threadIdx.x;
    int px = idx % HW;
    int plane = idx / HW;
    int c = plane & 63, bi = plane >> 6;
    const float* p = ybase + (size_t)bi*TCHW + (size_t)c*HW;
    const float* wp = g_wd + plane*9;
    float w[9];
    #pragma unroll
    for (int k = 0; k < 9; k++) w[k] = wp[k];
    int y0 = px / W, x0 = px % W;
    float s = 0.f;
    #pragma unroll
    for (int kh = 0; kh < 3; kh++) {
        int yy = y0 + kh - 1;
        if ((unsigned)yy >= H) continue;
        const float* row = p + yy*W;
        #pragma unroll
        for (int kw = 0; kw < 3; kw++) {
            int xx = x0 + kw - 1;
            if ((unsigned)xx < W) s = fmaf(row[xx], w[kh*3 + kw], s);
        }
    }
    g_fp[idx] = s + kc_bias[c];
}

// ---------------- weight split preps (once per launch) ---------------------------
__global__ void prep_w_kernel(const float* __restrict__ conv1_w) {
    int idx = blockIdx.x * 256 + threadIdx.x;      // 9*8*128*16 = 147456
    if (idx >= 9*8*128*16) return;
    int k   = idx & 15;
    int oc  = (idx >> 4) & 127;
    int ch  = (idx >> 11) & 7;
    int tap = idx >> 14;
    int ic = ch*16 + k;
    float v = conv1_w[((size_t)oc*C2 + ic)*9 + tap];
    __half h, l; split2(v, h, l);
    size_t o = ((size_t)(tap*8 + ch)*128 + oc)*24 + k;
    g_whi[o] = h; g_wlo[o] = l;
}
__global__ void prep_pw_kernel(const float* __restrict__ pi1_w, const float* __restrict__ pi2_w) {
    int idx = blockIdx.x * 256 + threadIdx.x;      // 2*4*256*16 = 32768
    if (idx >= 2*4*256*16) return;
    int k    = idx & 15;
    int oc   = (idx >> 4) & 255;
    int ch   = (idx >> 12) & 3;
    int gate = idx >> 14;
    const float* w = gate ? pi2_w : pi1_w;         // [256][64]
    float v = w[(size_t)oc*C + ch*16 + k];
    __half h, l; split2(v, h, l);
    size_t o = ((size_t)(gate*4 + ch)*256 + oc)*24 + k;
    g_pwhi[o] = h; g_pwlo[o] = l;
}
__global__ void prep_cw_kernel(const float* __restrict__ po1_w, const float* __restrict__ po2_w) {
    int idx = blockIdx.x * 256 + threadIdx.x;      // 2*16*64*16 = 32768
    if (idx >= 2*16*64*16) return;
    int k    = idx & 15;
    int oc   = (idx >> 4) & 63;
    int ch   = (idx >> 10) & 15;
    int gate = idx >> 14;
    const float* w = gate ? po2_w : po1_w;         // [64][256]
    float v = w[(size_t)oc*C4 + ch*16 + k];
    __half h, l; split2(v, h, l);
    size_t o = ((size_t)(gate*16 + ch)*64 + oc)*24 + k;
    g_cwhi[o] = h; g_cwlo[o] = l;
}

// ---------------- conv3x3 via fp16-split mma, halo-staged X -----------------------
// block 256 thr (8 warps: wm 0..3 x wn 0..1); tile 128oc x (2y x 32x) px.
// ch outer (8): stage X halo [4y+? rows: (y0-1..y0+2) x (x0-1..x0+32)] = 136 px-rows once;
// tap inner (9): W double-buffered; taps = ldmatrix address offsets into halo tile.
__global__ void __launch_bounds__(256, 2) conv_mma_kernel(const float* __restrict__ xbase,
                                                          const float* __restrict__ bias) {
    __shared__ __align__(16) __half Xhi_s[136*24];
    __shared__ __align__(16) __half Xlo_s[136*24];
    __shared__ __align__(16) __half Whi_s[2][128*24];
    __shared__ __align__(16) __half Wlo_s[2][128*24];

    int tid = threadIdx.x;
    int lane = tid & 31, wid = tid >> 5;
    int wm = wid & 3, wn = wid >> 2;
    int x0 = blockIdx.x * 32;
    int y0 = blockIdx.y * 2;
    int bi = blockIdx.z;

    const float* xp  = xbase + (size_t)bi*TCHW;
    const float* fpp = g_fp  + (size_t)bi*CHW;

    float acc[2][4][4];
    #pragma unroll
    for (int m = 0; m < 2; m++)
        #pragma unroll
        for (int n = 0; n < 4; n++)
            #pragma unroll
            for (int r = 0; r < 4; r++) acc[m][n][r] = 0.f;

    // X stager: ic_l = tid>>4 (0..15), rg = tid&15; rows r = rg + 16j (j<9, r<136)
    int ic_l = tid >> 4;
    int rg   = tid & 15;

    // A-fragment addressing (within W buffer)
    int a_row = (lane & 7) + ((lane >> 3) & 1)*8;
    int a_col = (lane >> 4)*8;
    // B-fragment: per p, lane row = pixel n -> halo row (yy+1)*34 + xx+1
    int b_n   = (lane & 7) + ((lane >> 4) & 1)*8;
    int b_col = ((lane >> 3) & 1)*8;
    const char* bPtrHi[2];
    const char* bPtrLo[2];
    #pragma unroll
    for (int p = 0; p < 2; p++) {
        int n = wn*32 + p*16 + b_n;
        int row0 = ((n >> 5) + 1)*34 + (n & 31) + 1;
        bPtrHi[p] = (const char*)Xhi_s + row0*48 + b_col*2;
        bPtrLo[p] = (const char*)Xlo_s + row0*48 + b_col*2;
    }

    for (int ch = 0; ch < 8; ch++) {
        __syncthreads();
        // ---- stage X halo chunk [136 px-rows x 16 k], split once
        {
            int ic = ch*16 + ic_l;
            const float* pl = (ic < C) ? (xp + (size_t)ic*HW) : (fpp + (size_t)(ic - C)*HW);
            #pragma unroll
            for (int j = 0; j < 9; j++) {
                int r = rg + j*16;
                if (r < 136) {
                    int ry = r / 34, rx = r - ry*34;
                    int gy = y0 + ry - 1, gx = x0 + rx - 1;
                    float v = ((unsigned)gy < H && (unsigned)gx < W) ? __ldg(pl + gy*W + gx) : 0.f;
                    __half h, l; split2(v, h, l);
                    Xhi_s[r*24 + ic_l] = h;
                    Xlo_s[r*24 + ic_l] = l;
                }
            }
        }
        // ---- stage W(tap=0, ch) into buf 0
        {
            const float4* sH = (const float4*)(g_whi + (size_t)(0*8 + ch)*3072);
            const float4* sL = (const float4*)(g_wlo + (size_t)(0*8 + ch)*3072);
            ((float4*)Whi_s[0])[tid] = sH[tid];
            ((float4*)Wlo_s[0])[tid] = sL[tid];
            if (tid < 128) {
                ((float4*)Whi_s[0])[256 + tid] = sH[256 + tid];
                ((float4*)Wlo_s[0])[256 + tid] = sL[256 + tid];
            }
        }
        __syncthreads();

        #pragma unroll
        for (int tap = 0; tap < 9; tap++) {
            int cur = tap & 1;
            int dy = tap/3 - 1, dx = tap%3 - 1;
            int tapoff = (dy*34 + dx)*48;

            unsigned Ahi[2][4], Alo[2][4];
            ldsm4(Ahi[0], &Whi_s[cur][(wm*32 +      a_row)*24 + a_col]);
            ldsm4(Ahi[1], &Whi_s[cur][(wm*32 + 16 + a_row)*24 + a_col]);
            ldsm4(Alo[0], &Wlo_s[cur][(wm*32 +      a_row)*24 + a_col]);
            ldsm4(Alo[1], &Wlo_s[cur][(wm*32 + 16 + a_row)*24 + a_col]);
            unsigned Bhi[4][2], Blo[4][2];
            #pragma unroll
            for (int p = 0; p < 2; p++) {
                unsigned t[4];
                ldsm4(t, bPtrHi[p] + tapoff);
                Bhi[2*p][0] = t[0]; Bhi[2*p][1] = t[1];
                Bhi[2*p+1][0] = t[2]; Bhi[2*p+1][1] = t[3];
                ldsm4(t, bPtrLo[p] + tapoff);
                Blo[2*p][0] = t[0]; Blo[2*p][1] = t[1];
                Blo[2*p+1][0] = t[2]; Blo[2*p+1][1] = t[3];
            }
            #pragma unroll
            for (int m = 0; m < 2; m++)
                #pragma unroll
                for (int n = 0; n < 4; n++) {
                    mma16816(acc[m][n], Ahi[m], Bhi[n]);
                    mma16816(acc[m][n], Ahi[m], Blo[n]);
                    mma16816(acc[m][n], Alo[m], Bhi[n]);
                }

            if (tap < 8) {
                int nxt = (tap + 1) & 1;
                const float4* sH = (const float4*)(g_whi + (size_t)((tap+1)*8 + ch)*3072);
                const float4* sL = (const float4*)(g_wlo + (size_t)((tap+1)*8 + ch)*3072);
                ((float4*)Whi_s[nxt])[tid] = sH[tid];
                ((float4*)Wlo_s[nxt])[tid] = sL[tid];
                if (tid < 128) {
                    ((float4*)Whi_s[nxt])[256 + tid] = sH[256 + tid];
                    ((float4*)Wlo_s[nxt])[256 + tid] = sL[256 + tid];
                }
                __syncthreads();
            }
        }
    }

    // ---- epilogue: bias + leaky + store
    int row_ = lane >> 2;
    int colp = (lane & 3)*2;
    int yo = y0 + wn;
    #pragma unroll
    for (int m = 0; m < 2; m++) {
        int ocA = wm*32 + m*16 + row_;
        int ocB = ocA + 8;
        float bA = bias[ocA], bB = bias[ocB];
        #pragma unroll
        for (int n = 0; n < 4; n++) {
            int xo = x0 + n*8 + colp;
            float v0 = acc[m][n][0] + bA, v1 = acc[m][n][1] + bA;
            float v2 = acc[m][n][2] + bB, v3 = acc[m][n][3] + bB;
            v0 = (v0 > 0.f) ? v0 : 0.1f*v0;
            v1 = (v1 > 0.f) ? v1 : 0.1f*v1;
            v2 = (v2 > 0.f) ? v2 : 0.1f*v2;
            v3 = (v3 > 0.f) ? v3 : 0.1f*v3;
            *((float2*)(g_fusion + ((size_t)bi*C2 + ocA)*HW + (size_t)yo*W + xo)) = make_float2(v0, v1);
            *((float2*)(g_fusion + ((size_t)bi*C2 + ocB)*HW + (size_t)yo*W + xo)) = make_float2(v2, v3);
        }
    }
}

// ---------------- expand via mma: D[128oc x 64px], K=64 (verified R9) -------------
__global__ void __launch_bounds__(256, 2) expand_mma_kernel(const float* __restrict__ b1,
                                                            const float* __restrict__ b2) {
    __shared__ __align__(16) __half Whi_s[128*24];
    __shared__ __align__(16) __half Wlo_s[128*24];
    __shared__ __align__(16) __half Xhi_s[64*24];
    __shared__ __align__(16) __half Xlo_s[64*24];

    int tid = threadIdx.x;
    int lane = tid & 31, wid = tid >> 5;
    int wm = wid & 3, wn = wid >> 2;
    int px0 = blockIdx.x * 64;
    int gy  = blockIdx.y;
    int gate = gy >> 1, hh = gy & 1;
    int bi = blockIdx.z;

    const float* bias = gate ? b2 : b1;
    float* outb       = gate ? g_a2 : g_a1;
    int halfoff       = gate ? C : 0;

    float acc[2][4][4];
    #pragma unroll
    for (int m = 0; m < 2; m++)
        #pragma unroll
        for (int n = 0; n < 4; n++)
            #pragma unroll
            for (int r = 0; r < 4; r++) acc[m][n][r] = 0.f;

    int ic_l = tid >> 4;
    int n0   = (tid & 15)*4;

    int a_row = (lane & 7) + ((lane >> 3) & 1)*8;
    int a_col = (lane >> 4)*8;
    int b_n   = (lane & 7) + ((lane >> 4) & 1)*8;
    int b_col = ((lane >> 3) & 1)*8;

    #pragma unroll
    for (int ch = 0; ch < 4; ch++) {
        __syncthreads();
        {
            const float* src = g_fusion + ((size_t)(bi*C2 + halfoff + ch*16 + ic_l))*HW + px0 + n0;
            float4 v = *((const float4*)src);
            float vv[4] = {v.x, v.y, v.z, v.w};
            #pragma unroll
            for (int j = 0; j < 4; j++) {
                __half h, l; split2(vv[j], h, l);
                Xhi_s[(n0 + j)*24 + ic_l] = h;
                Xlo_s[(n0 + j)*24 + ic_l] = l;
            }
        }
        {
            const float4* sH = (const float4*)(g_pwhi + ((size_t)(gate*4 + ch)*256 + hh*128)*24);
            const float4* sL = (const float4*)(g_pwlo + ((size_t)(gate*4 + ch)*256 + hh*128)*24);
            ((float4*)Whi_s)[tid] = sH[tid];
            ((float4*)Wlo_s)[tid] = sL[tid];
            if (tid < 128) {
                ((float4*)Whi_s)[256 + tid] = sH[256 + tid];
                ((float4*)Wlo_s)[256 + tid] = sL[256 + tid];
            }
        }
        __syncthreads();

        unsigned Ahi[2][4], Alo[2][4];
        ldsm4(Ahi[0], &Whi_s[(wm*32 +      a_row)*24 + a_col]);
        ldsm4(Ahi[1], &Whi_s[(wm*32 + 16 + a_row)*24 + a_col]);
        ldsm4(Alo[0], &Wlo_s[(wm*32 +      a_row)*24 + a_col]);
        ldsm4(Alo[1], &Wlo_s[(wm*32 + 16 + a_row)*24 + a_col]);
        unsigned Bhi[4][2], Blo[4][2];
        #pragma unroll
        for (int p = 0; p < 2; p++) {
            unsigned t[4];
            ldsm4(t, &Xhi_s[(wn*32 + p*16 + b_n)*24 + b_col]);
            Bhi[2*p][0] = t[0]; Bhi[2*p][1] = t[1];
            Bhi[2*p+1][0] = t[2]; Bhi[2*p+1][1] = t[3];
            ldsm4(t, &Xlo_s[(wn*32 + p*16 + b_n)*24 + b_col]);
            Blo[2*p][0] = t[0]; Blo[2*p][1] = t[1];
            Blo[2*p+1][0] = t[2]; Blo[2*p+1][1] = t[3];
        }
        #pragma unroll
        for (int m = 0; m < 2; m++)
            #pragma unroll
            for (int n = 0; n < 4; n++) {
                mma16816(acc[m][n], Ahi[m], Bhi[n]);
                mma16816(acc[m][n], Ahi[m], Blo[n]);
                mma16816(acc[m][n], Alo[m], Bhi[n]);
            }
    }

    int row_ = lane >> 2;
    int colp = (lane & 3)*2;
    #pragma unroll
    for (int m = 0; m < 2; m++) {
        int ocA = hh*128 + wm*32 + m*16 + row_;
        int ocB = ocA + 8;
        float bA = bias[ocA], bB = bias[ocB];
        #pragma unroll
        for (int n = 0; n < 4; n++) {
            int xo = px0 + wn*32 + n*8 + colp;
            *((float2*)(outb + ((size_t)bi*C4 + ocA)*HW + xo)) =
                make_float2(acc[m][n][0] + bA, acc[m][n][1] + bA);
            *((float2*)(outb + ((size_t)bi*C4 + ocB)*HW + xo)) =
                make_float2(acc[m][n][2] + bB, acc[m][n][3] + bB);
        }
    }
}

// ---------------- static depthwise 3x3, 4px/thread; outputs split hi/lo fp16 ------
__global__ void __launch_bounds__(256) dw_both_kernel(const float* __restrict__ w1,
                                                      const float* __restrict__ b1,
                                                      const float* __restrict__ w2,
                                                      const float* __restrict__ b2) {
    int gate = blockIdx.y;
    const float* inb  = gate ? g_a2 : g_a1;
    __half* outh      = gate ? g_bh2 : g_bh1;
    __half* outl      = gate ? g_bl2 : g_bl1;
    const float* wgt  = gate ? w2 : w1;
    const float* bias = gate ? b2 : b1;

    int g = blockIdx.x * 256 + threadIdx.x;
    int px4   = g % (HW/4);
    int plane = g / (HW/4);
    int ch = plane & (C4 - 1);
    int y  = px4 / (W/4);
    int x0 = (px4 % (W/4)) * 4;

    const float* p = inb + (size_t)plane*HW;
    const float* wp = wgt + ch*9;
    float w[9];
    #pragma unroll
    for (int k = 0; k < 9; k++) w[k] = wp[k];

    float A[3][6];
    #pragma unroll
    for (int kh = 0; kh < 3; kh++) {
        int yy = y + kh - 1;
        if ((unsigned)yy < H) {
            const float* row = p + yy*W;
            float4 m = *((const float4*)(row + x0));
            A[kh][0] = (x0 > 0)      ? row[x0 - 1] : 0.f;
            A[kh][1] = m.x; A[kh][2] = m.y; A[kh][3] = m.z; A[kh][4] = m.w;
            A[kh][5] = (x0 + 4 < W)  ? row[x0 + 4] : 0.f;
        } else {
            #pragma unroll
            for (int j = 0; j < 6; j++) A[kh][j] = 0.f;
        }
    }

    float bv = bias[ch];
    __align__(8) __half hv[4];
    __align__(8) __half lv[4];
    #pragma unroll
    for (int j = 0; j < 4; j++) {
        float s = bv;
        #pragma unroll
        for (int kh = 0; kh < 3; kh++)
            #pragma unroll
            for (int kw = 0; kw < 3; kw++)
                s = fmaf(A[kh][j + kw], w[kh*3 + kw], s);
        split2(s, hv[j], lv[j]);
    }
    size_t off = (size_t)plane*HW + (size_t)y*W + x0;
    *((uint2*)(outh + off)) = *((uint2*)hv);
    *((uint2*)(outl + off)) = *((uint2*)lv);
}

// ---------------- contract via mma: D[64oc x 128px], K=256 ------------------------
// B staged by pure fp16 copy (dw pre-split). GATE=0: sigmoid -> g_g1.
// GATE=1: sigmoid + combine -> out slice. grid (HW/128, BATCH)
template<int GATE>
__global__ void __launch_bounds__(256, 2) contract_mma_kernel(const float* __restrict__ bias,
                                                              float* __restrict__ outbase) {
    __shared__ __align__(16) __half Ahi_s[64*24];
    __shared__ __align__(16) __half Alo_s[64*24];
    __shared__ __align__(16) __half Bhi_s[128*24];
    __shared__ __align__(16) __half Blo_s[128*24];

    int tid = threadIdx.x;
    int lane = tid & 31, wid = tid >> 5;
    int wm = wid & 1, wn = wid >> 1;
    int px0 = blockIdx.x * 128;
    int bi = blockIdx.y;

    const __half* inh = GATE ? g_bh2 : g_bh1;
    const __half* inl = GATE ? g_bl2 : g_bl1;

    float acc[2][4][4];
    #pragma unroll
    for (int m = 0; m < 2; m++)
        #pragma unroll
        for (int n = 0; n < 4; n++)
            #pragma unroll
            for (int r = 0; r < 4; r++) acc[m][n][r] = 0.f;

    int ic_l = tid >> 4;
    int n0   = (tid & 15)*8;

    int a_row = (lane & 7) + ((lane >> 3) & 1)*8;
    int a_col = (lane >> 4)*8;
    int b_n   = (lane & 7) + ((lane >> 4) & 1)*8;
    int b_col = ((lane >> 3) & 1)*8;

    for (int ch = 0; ch < 16; ch++) {
        __syncthreads();
        // stage B [16ic x 128px]: straight fp16 copy (no splits)
        {
            size_t off = ((size_t)(bi*C4 + ch*16 + ic_l))*HW + px0 + n0;
            float4 vh = *((const float4*)(inh + off));     // 8 halves
            float4 vl = *((const float4*)(inl + off));
            const __half* hp = (const __half*)&vh;
            const __half* lp = (const __half*)&vl;
            #pragma unroll
            for (int j = 0; j < 8; j++) {
                Bhi_s[(n0 + j)*24 + ic_l] = hp[j];
                Blo_s[(n0 + j)*24 + ic_l] = lp[j];
            }
        }
        // stage A [64oc x 16k]
        if (tid < 192) {
            const float4* sH = (const float4*)(g_cwhi + ((size_t)(GATE*16 + ch)*64)*24);
            const float4* sL = (const float4*)(g_cwlo + ((size_t)(GATE*16 + ch)*64)*24);
            ((float4*)Ahi_s)[tid] = sH[tid];
            ((float4*)Alo_s)[tid] = sL[tid];
        }
        __syncthreads();

        unsigned Ahi[2][4], Alo[2][4];
        ldsm4(Ahi[0], &Ahi_s[(wm*32 +      a_row)*24 + a_col]);
        ldsm4(Ahi[1], &Ahi_s[(wm*32 + 16 + a_row)*24 + a_col]);
        ldsm4(Alo[0], &Alo_s[(wm*32 +      a_row)*24 + a_col]);
        ldsm4(Alo[1], &Alo_s[(wm*32 + 16 + a_row)*24 + a_col]);
        unsigned Bhi[4][2], Blo[4][2];
        #pragma unroll
        for (int p = 0; p < 2; p++) {
            unsigned t[4];
            ldsm4(t, &Bhi_s[(wn*32 + p*16 + b_n)*24 + b_col]);
            Bhi[2*p][0] = t[0]; Bhi[2*p][1] = t[1];
            Bhi[2*p+1][0] = t[2]; Bhi[2*p+1][1] = t[3];
            ldsm4(t, &Blo_s[(wn*32 + p*16 + b_n)*24 + b_col]);
            Blo[2*p][0] = t[0]; Blo[2*p][1] = t[1];
            Blo[2*p+1][0] = t[2]; Blo[2*p+1][1] = t[3];
        }
        #pragma unroll
        for (int m = 0; m < 2; m++)
            #pragma unroll
            for (int n = 0; n < 4; n++) {
                mma16816(acc[m][n], Ahi[m], Bhi[n]);
                mma16816(acc[m][n], Ahi[m], Blo[n]);
                mma16816(acc[m][n], Alo[m], Bhi[n]);
            }
    }

    int row_ = lane >> 2;
    int colp = (lane & 3)*2;
    #pragma unroll
    for (int m = 0; m < 2; m++) {
        int ocA = wm*32 + m*16 + row_;
        int ocB = ocA + 8;
        float bA = bias[ocA], bB = bias[ocB];
        #pragma unroll
        for (int n = 0; n < 4; n++) {
            int xo = px0 + wn*32 + n*8 + colp;
            float gA0 = 1.0f / (1.0f + __expf(-(acc[m][n][0] + bA)));
            float gA1 = 1.0f / (1.0f + __expf(-(acc[m][n][1] + bA)));
            float gB0 = 1.0f / (1.0f + __expf(-(acc[m][n][2] + bB)));
            float gB1 = 1.0f / (1.0f + __expf(-(acc[m][n][3] + bB)));
            if (GATE == 0) {
                *((float2*)(g_g1 + ((size_t)bi*C + ocA)*HW + xo)) = make_float2(gA0, gA1);
                *((float2*)(g_g1 + ((size_t)bi*C + ocB)*HW + xo)) = make_float2(gB0, gB1);
            } else {
                float2 f1A = *((const float2*)(g_fusion + ((size_t)bi*C2 + ocA)*HW + xo));
                float2 f2A = *((const float2*)(g_fusion + ((size_t)bi*C2 + C + ocA)*HW + xo));
                float2 g1A = *((const float2*)(g_g1 + ((size_t)bi*C + ocA)*HW + xo));
                float2 f1B = *((const float2*)(g_fusion + ((size_t)bi*C2 + ocB)*HW + xo));
                float2 f2B = *((const float2*)(g_fusion + ((size_t)bi*C2 + C + ocB)*HW + xo));
                float2 g1B = *((const float2*)(g_g1 + ((size_t)bi*C + ocB)*HW + xo));
                *((float2*)(outbase + (size_t)bi*TCHW + (size_t)ocA*HW + xo)) =
                    make_float2(f1A.x*g1A.x + f2A.x*gA0, f1A.y*g1A.y + f2A.y*gA1);
                *((float2*)(outbase + (size_t)bi*TCHW + (size_t)ocB*HW + xo)) =
                    make_float2(f1B.x*g1B.x + f2B.x*gB0, f1B.y*g1B.y + f2B.y*gB1);
            }
        }
    }
}

// ---------------- launcher -------------------------------------------------------
extern "C" void kernel_launch(void* const* d_in, const int* in_sizes, int n_in,
                              void* d_out, int out_size) {
    (void)in_sizes; (void)n_in; (void)out_size;
    const float* feature   = (const float*)d_in[0];
    const float* kc_w1     = (const float*)d_in[1];
    const float* kc_gamma  = (const float*)d_in[2];
    const float* kc_beta   = (const float*)d_in[3];
    const float* kc_mean   = (const float*)d_in[4];
    const float* kc_var    = (const float*)d_in[5];
    const float* kc_w2     = (const float*)d_in[6];
    const float* kc_b2     = (const float*)d_in[7];
    const float* kc_bias   = (const float*)d_in[8];
    const float* conv1_w   = (const float*)d_in[9];
    const float* conv1_b   = (const float*)d_in[10];
    const float* pi1_w     = (const float*)d_in[11];
    const float* pi1_b     = (const float*)d_in[12];
    const float* dw1_w     = (const float*)d_in[13];
    const float* dw1_b     = (const float*)d_in[14];
    const float* po1_w     = (const float*)d_in[15];
    const float* po1_b     = (const float*)d_in[16];
    const float* pi2_w     = (const float*)d_in[17];
    const float* pi2_b     = (const float*)d_in[18];
    const float* dw2_w     = (const float*)d_in[19];
    const float* dw2_b     = (const float*)d_in[20];
    const float* po2_w     = (const float*)d_in[21];
    const float* po2_b     = (const float*)d_in[22];
    float* out = (float*)d_out;

    // out[:, T-1] = feature[:, T-1]
    for (int bi = 0; bi < BATCH; bi++) {
        size_t off = ((size_t)bi*T + (T-1)) * CHW;
        cudaMemcpyAsync(out + off, feature + off, (size_t)CHW*sizeof(float),
                        cudaMemcpyDeviceToDevice, 0);
    }

    // one-time per launch: weight splits
    prep_w_kernel<<<(9*8*128*16 + 255)/256, 256>>>(conv1_w);
    prep_pw_kernel<<<(2*4*256*16 + 255)/256, 256>>>(pi1_w, pi2_w);
    prep_cw_kernel<<<(2*16*64*16 + 255)/256, 256>>>(po1_w, po2_w);

    for (int i = T - 2; i >= 0; --i) {
        const float* xbase = feature + (size_t)i*CHW;
        const float* ybase = out + (size_t)(i+1)*CHW;

        pool_kernel<<<BATCH*C, 256>>>(xbase);
        mlp_kernel<<<1, 128>>>(kc_w1, kc_gamma, kc_beta, kc_mean, kc_var, kc_w2, kc_b2);
        dyndw_kernel<<<(BATCH*CHW)/256, 256>>>(ybase, kc_bias);
        conv_mma_kernel<<<dim3(W/32, H/2, BATCH), 256>>>(xbase, conv1_b);

        expand_mma_kernel<<<dim3(HW/64, 4, BATCH), 256>>>(pi1_b, pi2_b);
        dw_both_kernel<<<dim3((BATCH*C4*HW/4)/256, 2), 256>>>(dw1_w, dw1_b, dw2_w, dw2_b);

        contract_mma_kernel<0><<<dim3(HW/128, BATCH), 256>>>(po1_b, nullptr);
        contract_mma_kernel<1><<<dim3(HW/128, BATCH), 256>>>(po2_b, out + (size_t)i*CHW);
    }
}

// round 11
// speedup vs baseline: 7.3351x; 1.0646x over previous
#include <cuda_runtime.h>
#include <cuda_fp16.h>
#include <math.h>

#define BATCH 2
#define T 8
#define C 64
#define R 16
#define H 160
#define W 160
#define HW (H*W)            // 25600
#define CHW (C*HW)          // 1,638,400
#define TCHW (T*CHW)
#define C2 128
#define C4 256

typedef unsigned long long ull;

// ---------------- scratch (device globals; referenced ONLY from device code) ----
__device__ float g_pool_all[(T-1)*BATCH*C];
__device__ float g_wd_all[(T-1)*BATCH*C*9];
__device__ float g_fp[BATCH*CHW];
__device__ float g_fusion[(size_t)BATCH*C2*HW];
__device__ float g_a1[(size_t)BATCH*C4*HW];
__device__ float g_a2[(size_t)BATCH*C4*HW];
__device__ __half g_bh1[(size_t)BATCH*C4*HW];
__device__ __half g_bl1[(size_t)BATCH*C4*HW];
__device__ __half g_bh2[(size_t)BATCH*C4*HW];
__device__ __half g_bl2[(size_t)BATCH*C4*HW];
// conv weights pre-split fp16 hi/lo, ldmatrix-ready [tap][ch8][oc128][24]
__device__ __half g_whi[9*8*128*24];
__device__ __half g_wlo[9*8*128*24];
// expand weights [gate][ch4][oc256][24]
__device__ __half g_pwhi[2*4*256*24];
__device__ __half g_pwlo[2*4*256*24];
// contract weights [gate][ch16][oc64][24]
__device__ __half g_cwhi[2*16*64*24];
__device__ __half g_cwlo[2*16*64*24];

// ---------------- mma helpers -----------------------------------------------------
__device__ __forceinline__ void ldsm4(unsigned* r, const void* p) {
    unsigned s = (unsigned)__cvta_generic_to_shared(p);
    asm volatile("ldmatrix.sync.aligned.m8n8.x4.shared.b16 {%0,%1,%2,%3}, [%4];"
        : "=r"(r[0]), "=r"(r[1]), "=r"(r[2]), "=r"(r[3]) : "r"(s));
}
__device__ __forceinline__ void mma16816(float* d, const unsigned* a, const unsigned* b) {
    asm volatile("mma.sync.aligned.m16n8k16.row.col.f32.f16.f16.f32 "
        "{%0,%1,%2,%3},{%4,%5,%6,%7},{%8,%9},{%0,%1,%2,%3};"
        : "+f"(d[0]), "+f"(d[1]), "+f"(d[2]), "+f"(d[3])
        : "r"(a[0]), "r"(a[1]), "r"(a[2]), "r"(a[3]), "r"(b[0]), "r"(b[1]));
}
__device__ __forceinline__ void split2(float v, __half& h, __half& l) {
    h = __float2half_rn(v);
    l = __float2half_rn(v - __half2float(h));
}

// ---------------- pool for ALL steps (feature-only dependence) --------------------
// grid ((T-1)*BATCH*C) blocks
__global__ void pool_all_kernel(const float* __restrict__ feature) {
    int g = blockIdx.x;                 // step*BATCH*C + bi*C + c
    int step = g / (BATCH*C);
    int rem  = g % (BATCH*C);
    int bi = rem >> 6, c = rem & 63;
    const float* p = feature + (size_t)bi*TCHW + (size_t)step*CHW + (size_t)c*HW;
    float s = 0.f;
    for (int i = threadIdx.x; i < HW; i += 256) s += p[i];
    __shared__ float red[8];
    #pragma unroll
    for (int o = 16; o; o >>= 1) s += __shfl_down_sync(0xffffffffu, s, o);
    if ((threadIdx.x & 31) == 0) red[threadIdx.x >> 5] = s;
    __syncthreads();
    if (threadIdx.x == 0) {
        float t = 0.f;
        #pragma unroll
        for (int k = 0; k < 8; k++) t += red[k];
        g_pool_all[g] = t * (1.0f / (float)HW);
    }
}

// ---------------- tiny MLP for ALL steps ------------------------------------------
// grid (T-1) blocks, 128 thr
__global__ void mlp_all_kernel(const float* __restrict__ w1,
                               const float* __restrict__ gamma,
                               const float* __restrict__ beta,
                               const float* __restrict__ mean,
                               const float* __restrict__ var,
                               const float* __restrict__ w2,
                               const float* __restrict__ b2) {
    __shared__ float zs[BATCH*R];
    int step = blockIdx.x;
    int tid = threadIdx.x;
    const float* pool = g_pool_all + step*BATCH*C;
    float* wd = g_wd_all + step*BATCH*C*9;
    if (tid < BATCH*R) {
        int bi = tid / R, j = tid % R;
        float s = 0.f;
        for (int c = 0; c < C; c++) s = fmaf(pool[bi*C + c], w1[j*C + c], s);
        s = (s - mean[j]) * rsqrtf(var[j] + 1e-5f) * gamma[j] + beta[j];
        zs[tid] = fmaxf(s, 0.f);
    }
    __syncthreads();
    for (int o = tid; o < BATCH*C*9; o += blockDim.x) {
        int bi = o / (C*9), oo = o % (C*9);
        float s = b2[oo];
        #pragma unroll
        for (int j = 0; j < R; j++) s = fmaf(zs[bi*R + j], w2[oo*R + j], s);
        wd[o] = s;
    }
}

// ---------------- dynamic depthwise 3x3 -----------------------------------------
__global__ void dyndw_kernel(const float* __restrict__ ybase,
                             const float* __restrict__ kc_bias, int step) {
    int idx = blockIdx.x * 256 + threadIdx.x;
    int px = idx % HW;
    int plane = idx / HW;
    int c = plane & 63, bi = plane >> 6;
    const float* p = ybase + (size_t)bi*TCHW + (size_t)c*HW;
    const float* wp = g_wd_all + step*BATCH*C*9 + plane*9;
    float w[9];
    #pragma unroll
    for (int k = 0; k < 9; k++) w[k] = wp[k];
    int y0 = px / W, x0 = px % W;
    float s = 0.f;
    #pragma unroll
    for (int kh = 0; kh < 3; kh++) {
        int yy = y0 + kh - 1;
        if ((unsigned)yy >= H) continue;
        const float* row = p + yy*W;
        #pragma unroll
        for (int kw = 0; kw < 3; kw++) {
            int xx = x0 + kw - 1;
            if ((unsigned)xx < W) s = fmaf(row[xx], w[kh*3 + kw], s);
        }
    }
    g_fp[idx] = s + kc_bias[c];
}

// ---------------- weight split preps (once per launch) ---------------------------
__global__ void prep_w_kernel(const float* __restrict__ conv1_w) {
    int idx = blockIdx.x * 256 + threadIdx.x;
    if (idx >= 9*8*128*16) return;
    int k   = idx & 15;
    int oc  = (idx >> 4) & 127;
    int ch  = (idx >> 11) & 7;
    int tap = idx >> 14;
    int ic = ch*16 + k;
    float v = conv1_w[((size_t)oc*C2 + ic)*9 + tap];
    __half h, l; split2(v, h, l);
    size_t o = ((size_t)(tap*8 + ch)*128 + oc)*24 + k;
    g_whi[o] = h; g_wlo[o] = l;
}
__global__ void prep_pw_kernel(const float* __restrict__ pi1_w, const float* __restrict__ pi2_w) {
    int idx = blockIdx.x * 256 + threadIdx.x;
    if (idx >= 2*4*256*16) return;
    int k    = idx & 15;
    int oc   = (idx >> 4) & 255;
    int ch   = (idx >> 12) & 3;
    int gate = idx >> 14;
    const float* w = gate ? pi2_w : pi1_w;
    float v = w[(size_t)oc*C + ch*16 + k];
    __half h, l; split2(v, h, l);
    size_t o = ((size_t)(gate*4 + ch)*256 + oc)*24 + k;
    g_pwhi[o] = h; g_pwlo[o] = l;
}
__global__ void prep_cw_kernel(const float* __restrict__ po1_w, const float* __restrict__ po2_w) {
    int idx = blockIdx.x * 256 + threadIdx.x;
    if (idx >= 2*16*64*16) return;
    int k    = idx & 15;
    int oc   = (idx >> 4) & 63;
    int ch   = (idx >> 10) & 15;
    int gate = idx >> 14;
    const float* w = gate ? po2_w : po1_w;
    float v = w[(size_t)oc*C4 + ch*16 + k];
    __half h, l; split2(v, h, l);
    size_t o = ((size_t)(gate*16 + ch)*64 + oc)*24 + k;
    g_cwhi[o] = h; g_cwlo[o] = l;
}

// ---------------- conv3x3 via fp16-split mma, halo-staged X (verified R10) --------
__global__ void __launch_bounds__(256, 2) conv_mma_kernel(const float* __restrict__ xbase,
                                                          const float* __restrict__ bias) {
    __shared__ __align__(16) __half Xhi_s[136*24];
    __shared__ __align__(16) __half Xlo_s[136*24];
    __shared__ __align__(16) __half Whi_s[2][128*24];
    __shared__ __align__(16) __half Wlo_s[2][128*24];

    int tid = threadIdx.x;
    int lane = tid & 31, wid = tid >> 5;
    int wm = wid & 3, wn = wid >> 2;
    int x0 = blockIdx.x * 32;
    int y0 = blockIdx.y * 2;
    int bi = blockIdx.z;

    const float* xp  = xbase + (size_t)bi*TCHW;
    const float* fpp = g_fp  + (size_t)bi*CHW;

    float acc[2][4][4];
    #pragma unroll
    for (int m = 0; m < 2; m++)
        #pragma unroll
        for (int n = 0; n < 4; n++)
            #pragma unroll
            for (int r = 0; r < 4; r++) acc[m][n][r] = 0.f;

    int ic_l = tid >> 4;
    int rg   = tid & 15;

    int a_row = (lane & 7) + ((lane >> 3) & 1)*8;
    int a_col = (lane >> 4)*8;
    int b_n   = (lane & 7) + ((lane >> 4) & 1)*8;
    int b_col = ((lane >> 3) & 1)*8;
    const char* bPtrHi[2];
    const char* bPtrLo[2];
    #pragma unroll
    for (int p = 0; p < 2; p++) {
        int n = wn*32 + p*16 + b_n;
        int row0 = ((n >> 5) + 1)*34 + (n & 31) + 1;
        bPtrHi[p] = (const char*)Xhi_s + row0*48 + b_col*2;
        bPtrLo[p] = (const char*)Xlo_s + row0*48 + b_col*2;
    }

    for (int ch = 0; ch < 8; ch++) {
        __syncthreads();
        {
            int ic = ch*16 + ic_l;
            const float* pl = (ic < C) ? (xp + (size_t)ic*HW) : (fpp + (size_t)(ic - C)*HW);
            #pragma unroll
            for (int j = 0; j < 9; j++) {
                int r = rg + j*16;
                if (r < 136) {
                    int ry = r / 34, rx = r - ry*34;
                    int gy = y0 + ry - 1, gx = x0 + rx - 1;
                    float v = ((unsigned)gy < H && (unsigned)gx < W) ? __ldg(pl + gy*W + gx) : 0.f;
                    __half h, l; split2(v, h, l);
                    Xhi_s[r*24 + ic_l] = h;
                    Xlo_s[r*24 + ic_l] = l;
                }
            }
        }
        {
            const float4* sH = (const float4*)(g_whi + (size_t)(0*8 + ch)*3072);
            const float4* sL = (const float4*)(g_wlo + (size_t)(0*8 + ch)*3072);
            ((float4*)Whi_s[0])[tid] = sH[tid];
            ((float4*)Wlo_s[0])[tid] = sL[tid];
            if (tid < 128) {
                ((float4*)Whi_s[0])[256 + tid] = sH[256 + tid];
                ((float4*)Wlo_s[0])[256 + tid] = sL[256 + tid];
            }
        }
        __syncthreads();

        #pragma unroll
        for (int tap = 0; tap < 9; tap++) {
            int cur = tap & 1;
            int dy = tap/3 - 1, dx = tap%3 - 1;
            int tapoff = (dy*34 + dx)*48;

            unsigned Ahi[2][4], Alo[2][4];
            ldsm4(Ahi[0], &Whi_s[cur][(wm*32 +      a_row)*24 + a_col]);
            ldsm4(Ahi[1], &Whi_s[cur][(wm*32 + 16 + a_row)*24 + a_col]);
            ldsm4(Alo[0], &Wlo_s[cur][(wm*32 +      a_row)*24 + a_col]);
            ldsm4(Alo[1], &Wlo_s[cur][(wm*32 + 16 + a_row)*24 + a_col]);
            unsigned Bhi[4][2], Blo[4][2];
            #pragma unroll
            for (int p = 0; p < 2; p++) {
                unsigned t[4];
                ldsm4(t, bPtrHi[p] + tapoff);
                Bhi[2*p][0] = t[0]; Bhi[2*p][1] = t[1];
                Bhi[2*p+1][0] = t[2]; Bhi[2*p+1][1] = t[3];
                ldsm4(t, bPtrLo[p] + tapoff);
                Blo[2*p][0] = t[0]; Blo[2*p][1] = t[1];
                Blo[2*p+1][0] = t[2]; Blo[2*p+1][1] = t[3];
            }
            #pragma unroll
            for (int m = 0; m < 2; m++)
                #pragma unroll
                for (int n = 0; n < 4; n++) {
                    mma16816(acc[m][n], Ahi[m], Bhi[n]);
                    mma16816(acc[m][n], Ahi[m], Blo[n]);
                    mma16816(acc[m][n], Alo[m], Bhi[n]);
                }

            if (tap < 8) {
                int nxt = (tap + 1) & 1;
                const float4* sH = (const float4*)(g_whi + (size_t)((tap+1)*8 + ch)*3072);
                const float4* sL = (const float4*)(g_wlo + (size_t)((tap+1)*8 + ch)*3072);
                ((float4*)Whi_s[nxt])[tid] = sH[tid];
                ((float4*)Wlo_s[nxt])[tid] = sL[tid];
                if (tid < 128) {
                    ((float4*)Whi_s[nxt])[256 + tid] = sH[256 + tid];
                    ((float4*)Wlo_s[nxt])[256 + tid] = sL[256 + tid];
                }
                __syncthreads();
            }
        }
    }

    int row_ = lane >> 2;
    int colp = (lane & 3)*2;
    int yo = y0 + wn;
    #pragma unroll
    for (int m = 0; m < 2; m++) {
        int ocA = wm*32 + m*16 + row_;
        int ocB = ocA + 8;
        float bA = bias[ocA], bB = bias[ocB];
        #pragma unroll
        for (int n = 0; n < 4; n++) {
            int xo = x0 + n*8 + colp;
            float v0 = acc[m][n][0] + bA, v1 = acc[m][n][1] + bA;
            float v2 = acc[m][n][2] + bB, v3 = acc[m][n][3] + bB;
            v0 = (v0 > 0.f) ? v0 : 0.1f*v0;
            v1 = (v1 > 0.f) ? v1 : 0.1f*v1;
            v2 = (v2 > 0.f) ? v2 : 0.1f*v2;
            v3 = (v3 > 0.f) ? v3 : 0.1f*v3;
            *((float2*)(g_fusion + ((size_t)bi*C2 + ocA)*HW + (size_t)yo*W + xo)) = make_float2(v0, v1);
            *((float2*)(g_fusion + ((size_t)bi*C2 + ocB)*HW + (size_t)yo*W + xo)) = make_float2(v2, v3);
        }
    }
}

// ---------------- expand via mma: D[128oc x 64px], K=64 (verified R9) -------------
__global__ void __launch_bounds__(256, 2) expand_mma_kernel(const float* __restrict__ b1,
                                                            const float* __restrict__ b2) {
    __shared__ __align__(16) __half Whi_s[128*24];
    __shared__ __align__(16) __half Wlo_s[128*24];
    __shared__ __align__(16) __half Xhi_s[64*24];
    __shared__ __align__(16) __half Xlo_s[64*24];

    int tid = threadIdx.x;
    int lane = tid & 31, wid = tid >> 5;
    int wm = wid & 3, wn = wid >> 2;
    int px0 = blockIdx.x * 64;
    int gy  = blockIdx.y;
    int gate = gy >> 1, hh = gy & 1;
    int bi = blockIdx.z;

    const float* bias = gate ? b2 : b1;
    float* outb       = gate ? g_a2 : g_a1;
    int halfoff       = gate ? C : 0;

    float acc[2][4][4];
    #pragma unroll
    for (int m = 0; m < 2; m++)
        #pragma unroll
        for (int n = 0; n < 4; n++)
            #pragma unroll
            for (int r = 0; r < 4; r++) acc[m][n][r] = 0.f;

    int ic_l = tid >> 4;
    int n0   = (tid & 15)*4;

    int a_row = (lane & 7) + ((lane >> 3) & 1)*8;
    int a_col = (lane >> 4)*8;
    int b_n   = (lane & 7) + ((lane >> 4) & 1)*8;
    int b_col = ((lane >> 3) & 1)*8;

    #pragma unroll
    for (int ch = 0; ch < 4; ch++) {
        __syncthreads();
        {
            const float* src = g_fusion + ((size_t)(bi*C2 + halfoff + ch*16 + ic_l))*HW + px0 + n0;
            float4 v = *((const float4*)src);
            float vv[4] = {v.x, v.y, v.z, v.w};
            #pragma unroll
            for (int j = 0; j < 4; j++) {
                __half h, l; split2(vv[j], h, l);
                Xhi_s[(n0 + j)*24 + ic_l] = h;
                Xlo_s[(n0 + j)*24 + ic_l] = l;
            }
        }
        {
            const float4* sH = (const float4*)(g_pwhi + ((size_t)(gate*4 + ch)*256 + hh*128)*24);
            const float4* sL = (const float4*)(g_pwlo + ((size_t)(gate*4 + ch)*256 + hh*128)*24);
            ((float4*)Whi_s)[tid] = sH[tid];
            ((float4*)Wlo_s)[tid] = sL[tid];
            if (tid < 128) {
                ((float4*)Whi_s)[256 + tid] = sH[256 + tid];
                ((float4*)Wlo_s)[256 + tid] = sL[256 + tid];
            }
        }
        __syncthreads();

        unsigned Ahi[2][4], Alo[2][4];
        ldsm4(Ahi[0], &Whi_s[(wm*32 +      a_row)*24 + a_col]);
        ldsm4(Ahi[1], &Whi_s[(wm*32 + 16 + a_row)*24 + a_col]);
        ldsm4(Alo[0], &Wlo_s[(wm*32 +      a_row)*24 + a_col]);
        ldsm4(Alo[1], &Wlo_s[(wm*32 + 16 + a_row)*24 + a_col]);
        unsigned Bhi[4][2], Blo[4][2];
        #pragma unroll
        for (int p = 0; p < 2; p++) {
            unsigned t[4];
            ldsm4(t, &Xhi_s[(wn*32 + p*16 + b_n)*24 + b_col]);
            Bhi[2*p][0] = t[0]; Bhi[2*p][1] = t[1];
            Bhi[2*p+1][0] = t[2]; Bhi[2*p+1][1] = t[3];
            ldsm4(t, &Xlo_s[(wn*32 + p*16 + b_n)*24 + b_col]);
            Blo[2*p][0] = t[0]; Blo[2*p][1] = t[1];
            Blo[2*p+1][0] = t[2]; Blo[2*p+1][1] = t[3];
        }
        #pragma unroll
        for (int m = 0; m < 2; m++)
            #pragma unroll
            for (int n = 0; n < 4; n++) {
                mma16816(acc[m][n], Ahi[m], Bhi[n]);
                mma16816(acc[m][n], Ahi[m], Blo[n]);
                mma16816(acc[m][n], Alo[m], Bhi[n]);
            }
    }

    int row_ = lane >> 2;
    int colp = (lane & 3)*2;
    #pragma unroll
    for (int m = 0; m < 2; m++) {
        int ocA = hh*128 + wm*32 + m*16 + row_;
        int ocB = ocA + 8;
        float bA = bias[ocA], bB = bias[ocB];
        #pragma unroll
        for (int n = 0; n < 4; n++) {
            int xo = px0 + wn*32 + n*8 + colp;
            *((float2*)(outb + ((size_t)bi*C4 + ocA)*HW + xo)) =
                make_float2(acc[m][n][0] + bA, acc[m][n][1] + bA);
            *((float2*)(outb + ((size_t)bi*C4 + ocB)*HW + xo)) =
                make_float2(acc[m][n][2] + bB, acc[m][n][3] + bB);
        }
    }
}

// ---------------- static depthwise 3x3, 4px/thread; outputs split hi/lo fp16 ------
__global__ void __launch_bounds__(256) dw_both_kernel(const float* __restrict__ w1,
                                                      const float* __restrict__ b1,
                                                      const float* __restrict__ w2,
                                                      const float* __restrict__ b2) {
    int gate = blockIdx.y;
    const float* inb  = gate ? g_a2 : g_a1;
    __half* outh      = gate ? g_bh2 : g_bh1;
    __half* outl      = gate ? g_bl2 : g_bl1;
    const float* wgt  = gate ? w2 : w1;
    const float* bias = gate ? b2 : b1;

    int g = blockIdx.x * 256 + threadIdx.x;
    int px4   = g % (HW/4);
    int plane = g / (HW/4);
    int ch = plane & (C4 - 1);
    int y  = px4 / (W/4);
    int x0 = (px4 % (W/4)) * 4;

    const float* p = inb + (size_t)plane*HW;
    const float* wp = wgt + ch*9;
    float w[9];
    #pragma unroll
    for (int k = 0; k < 9; k++) w[k] = wp[k];

    float A[3][6];
    #pragma unroll
    for (int kh = 0; kh < 3; kh++) {
        int yy = y + kh - 1;
        if ((unsigned)yy < H) {
            const float* row = p + yy*W;
            float4 m = *((const float4*)(row + x0));
            A[kh][0] = (x0 > 0)      ? row[x0 - 1] : 0.f;
            A[kh][1] = m.x; A[kh][2] = m.y; A[kh][3] = m.z; A[kh][4] = m.w;
            A[kh][5] = (x0 + 4 < W)  ? row[x0 + 4] : 0.f;
        } else {
            #pragma unroll
            for (int j = 0; j < 6; j++) A[kh][j] = 0.f;
        }
    }

    float bv = bias[ch];
    __align__(8) __half hv[4];
    __align__(8) __half lv[4];
    #pragma unroll
    for (int j = 0; j < 4; j++) {
        float s = bv;
        #pragma unroll
        for (int kh = 0; kh < 3; kh++)
            #pragma unroll
            for (int kw = 0; kw < 3; kw++)
                s = fmaf(A[kh][j + kw], w[kh*3 + kw], s);
        split2(s, hv[j], lv[j]);
    }
    size_t off = (size_t)plane*HW + (size_t)y*W + x0;
    *((uint2*)(outh + off)) = *((uint2*)hv);
    *((uint2*)(outl + off)) = *((uint2*)lv);
}

// ---------------- fused BOTH-gate contract + sigmoid + combine --------------------
// Both 64x128 GEMMs (K=256) per block; g1/g2 combined IN REGISTERS; writes out slice.
// grid (HW/128, BATCH), 256 thr.
__global__ void __launch_bounds__(256, 2) contract_both_kernel(const float* __restrict__ po1_b,
                                                               const float* __restrict__ po2_b,
                                                               float* __restrict__ outbase) {
    __shared__ __align__(16) __half Ahi_s[2][64*24];
    __shared__ __align__(16) __half Alo_s[2][64*24];
    __shared__ __align__(16) __half Bhi_s[2][128*24];
    __shared__ __align__(16) __half Blo_s[2][128*24];

    int tid = threadIdx.x;
    int lane = tid & 31, wid = tid >> 5;
    int wm = wid & 1, wn = wid >> 1;
    int px0 = blockIdx.x * 128;
    int bi = blockIdx.y;

    float acc[2][2][4][4];
    #pragma unroll
    for (int gg = 0; gg < 2; gg++)
        #pragma unroll
        for (int m = 0; m < 2; m++)
            #pragma unroll
            for (int n = 0; n < 4; n++)
                #pragma unroll
                for (int r = 0; r < 4; r++) acc[gg][m][n][r] = 0.f;

    int ic_l = tid >> 4;
    int n0   = (tid & 15)*8;

    int a_row = (lane & 7) + ((lane >> 3) & 1)*8;
    int a_col = (lane >> 4)*8;
    int b_n   = (lane & 7) + ((lane >> 4) & 1)*8;
    int b_col = ((lane >> 3) & 1)*8;

    for (int ch = 0; ch < 16; ch++) {
        __syncthreads();
        // stage B for both gates (pure fp16 copies)
        {
            size_t off = ((size_t)(bi*C4 + ch*16 + ic_l))*HW + px0 + n0;
            float4 vh1 = *((const float4*)(g_bh1 + off));
            float4 vl1 = *((const float4*)(g_bl1 + off));
            float4 vh2 = *((const float4*)(g_bh2 + off));
            float4 vl2 = *((const float4*)(g_bl2 + off));
            const __half* h1 = (const __half*)&vh1;
            const __half* l1 = (const __half*)&vl1;
            const __half* h2 = (const __half*)&vh2;
            const __half* l2 = (const __half*)&vl2;
            #pragma unroll
            for (int j = 0; j < 8; j++) {
                Bhi_s[0][(n0 + j)*24 + ic_l] = h1[j];
                Blo_s[0][(n0 + j)*24 + ic_l] = l1[j];
                Bhi_s[1][(n0 + j)*24 + ic_l] = h2[j];
                Blo_s[1][(n0 + j)*24 + ic_l] = l2[j];
            }
        }
        // stage A both gates: 192 float4 per buf
        if (tid < 192) {
            ((float4*)Ahi_s[0])[tid] = ((const float4*)(g_cwhi + ((size_t)(0*16 + ch)*64)*24))[tid];
            ((float4*)Alo_s[0])[tid] = ((const float4*)(g_cwlo + ((size_t)(0*16 + ch)*64)*24))[tid];
        } else if (tid >= 224 && tid < 256) {
            // spread second gate over remaining threads via loop below
        }
        if (tid < 192) {
            ((float4*)Ahi_s[1])[tid] = ((const float4*)(g_cwhi + ((size_t)(1*16 + ch)*64)*24))[tid];
            ((float4*)Alo_s[1])[tid] = ((const float4*)(g_cwlo + ((size_t)(1*16 + ch)*64)*24))[tid];
        }
        __syncthreads();

        #pragma unroll
        for (int gg = 0; gg < 2; gg++) {
            unsigned Ahi[2][4], Alo[2][4];
            ldsm4(Ahi[0], &Ahi_s[gg][(wm*32 +      a_row)*24 + a_col]);
            ldsm4(Ahi[1], &Ahi_s[gg][(wm*32 + 16 + a_row)*24 + a_col]);
            ldsm4(Alo[0], &Alo_s[gg][(wm*32 +      a_row)*24 + a_col]);
            ldsm4(Alo[1], &Alo_s[gg][(wm*32 + 16 + a_row)*24 + a_col]);
            unsigned Bhi[4][2], Blo[4][2];
            #pragma unroll
            for (int p = 0; p < 2; p++) {
                unsigned t[4];
                ldsm4(t, &Bhi_s[gg][(wn*32 + p*16 + b_n)*24 + b_col]);
                Bhi[2*p][0] = t[0]; Bhi[2*p][1] = t[1];
                Bhi[2*p+1][0] = t[2]; Bhi[2*p+1][1] = t[3];
                ldsm4(t, &Blo_s[gg][(wn*32 + p*16 + b_n)*24 + b_col]);
                Blo[2*p][0] = t[0]; Blo[2*p][1] = t[1];
                Blo[2*p+1][0] = t[2]; Blo[2*p+1][1] = t[3];
            }
            #pragma unroll
            for (int m = 0; m < 2; m++)
                #pragma unroll
                for (int n = 0; n < 4; n++) {
                    mma16816(acc[gg][m][n], Ahi[m], Bhi[n]);
                    mma16816(acc[gg][m][n], Ahi[m], Blo[n]);
                    mma16816(acc[gg][m][n], Alo[m], Bhi[n]);
                }
        }
    }

    // epilogue: sigmoid both gates, combine with f1/f2, store
    int row_ = lane >> 2;
    int colp = (lane & 3)*2;
    #pragma unroll
    for (int m = 0; m < 2; m++) {
        int ocA = wm*32 + m*16 + row_;
        int ocB = ocA + 8;
        float b1A = po1_b[ocA], b1B = po1_b[ocB];
        float b2A = po2_b[ocA], b2B = po2_b[ocB];
        #pragma unroll
        for (int n = 0; n < 4; n++) {
            int xo = px0 + wn*32 + n*8 + colp;
            float g1A0 = 1.0f / (1.0f + __expf(-(acc[0][m][n][0] + b1A)));
            float g1A1 = 1.0f / (1.0f + __expf(-(acc[0][m][n][1] + b1A)));
            float g1B0 = 1.0f / (1.0f + __expf(-(acc[0][m][n][2] + b1B)));
            float g1B1 = 1.0f / (1.0f + __expf(-(acc[0][m][n][3] + b1B)));
            float g2A0 = 1.0f / (1.0f + __expf(-(acc[1][m][n][0] + b2A)));
            float g2A1 = 1.0f / (1.0f + __expf(-(acc[1][m][n][1] + b2A)));
            float g2B0 = 1.0f / (1.0f + __expf(-(acc[1][m][n][2] + b2B)));
            float g2B1 = 1.0f / (1.0f + __expf(-(acc[1][m][n][3] + b2B)));
            float2 f1A = *((const float2*)(g_fusion + ((size_t)bi*C2 + ocA)*HW + xo));
            float2 f2A = *((const float2*)(g_fusion + ((size_t)bi*C2 + C + ocA)*HW + xo));
            float2 f1B = *((const float2*)(g_fusion + ((size_t)bi*C2 + ocB)*HW + xo));
            float2 f2B = *((const float2*)(g_fusion + ((size_t)bi*C2 + C + ocB)*HW + xo));
            *((float2*)(outbase + (size_t)bi*TCHW + (size_t)ocA*HW + xo)) =
                make_float2(f1A.x*g1A0 + f2A.x*g2A0, f1A.y*g1A1 + f2A.y*g2A1);
            *((float2*)(outbase + (size_t)bi*TCHW + (size_t)ocB*HW + xo)) =
                make_float2(f1B.x*g1B0 + f2B.x*g2B0, f1B.y*g1B1 + f2B.y*g2B1);
        }
    }
}

// ---------------- launcher -------------------------------------------------------
extern "C" void kernel_launch(void* const* d_in, const int* in_sizes, int n_in,
                              void* d_out, int out_size) {
    (void)in_sizes; (void)n_in; (void)out_size;
    const float* feature   = (const float*)d_in[0];
    const float* kc_w1     = (const float*)d_in[1];
    const float* kc_gamma  = (const float*)d_in[2];
    const float* kc_beta   = (const float*)d_in[3];
    const float* kc_mean   = (const float*)d_in[4];
    const float* kc_var    = (const float*)d_in[5];
    const float* kc_w2     = (const float*)d_in[6];
    const float* kc_b2     = (const float*)d_in[7];
    const float* kc_bias   = (const float*)d_in[8];
    const float* conv1_w   = (const float*)d_in[9];
    const float* conv1_b   = (const float*)d_in[10];
    const float* pi1_w     = (const float*)d_in[11];
    const float* pi1_b     = (const float*)d_in[12];
    const float* dw1_w     = (const float*)d_in[13];
    const float* dw1_b     = (const float*)d_in[14];
    const float* po1_w     = (const float*)d_in[15];
    const float* po1_b     = (const float*)d_in[16];
    const float* pi2_w     = (const float*)d_in[17];
    const float* pi2_b     = (const float*)d_in[18];
    const float* dw2_w     = (const float*)d_in[19];
    const float* dw2_b     = (const float*)d_in[20];
    const float* po2_w     = (const float*)d_in[21];
    const float* po2_b     = (const float*)d_in[22];
    float* out = (float*)d_out;

    // out[:, T-1] = feature[:, T-1]
    for (int bi = 0; bi < BATCH; bi++) {
        size_t off = ((size_t)bi*T + (T-1)) * CHW;
        cudaMemcpyAsync(out + off, feature + off, (size_t)CHW*sizeof(float),
                        cudaMemcpyDeviceToDevice, 0);
    }

    // one-time: weight splits + ALL per-step dynamic weights (feature-only deps)
    prep_w_kernel<<<(9*8*128*16 + 255)/256, 256>>>(conv1_w);
    prep_pw_kernel<<<(2*4*256*16 + 255)/256, 256>>>(pi1_w, pi2_w);
    prep_cw_kernel<<<(2*16*64*16 + 255)/256, 256>>>(po1_w, po2_w);
    pool_all_kernel<<<(T-1)*BATCH*C, 256>>>(feature);
    mlp_all_kernel<<<T-1, 128>>>(kc_w1, kc_gamma, kc_beta, kc_mean, kc_var, kc_w2, kc_b2);

    for (int i = T - 2; i >= 0; --i) {
        const float* xbase = feature + (size_t)i*CHW;
        const float* ybase = out + (size_t)(i+1)*CHW;

        dyndw_kernel<<<(BATCH*CHW)/256, 256>>>(ybase, kc_bias, i);
        conv_mma_kernel<<<dim3(W/32, H/2, BATCH), 256>>>(xbase, conv1_b);
        expand_mma_kernel<<<dim3(HW/64, 4, BATCH), 256>>>(pi1_b, pi2_b);
        dw_both_kernel<<<dim3((BATCH*C4*HW/4)/256, 2), 256>>>(dw1_w, dw1_b, dw2_w, dw2_b);
        contract_both_kernel<<<dim3(HW/128, BATCH), 256>>>(po1_b, po2_b, out + (size_t)i*CHW);
    }
}

// round 12
// speedup vs baseline: 7.4421x; 1.0146x over previous
#include <cuda_runtime.h>
#include <cuda_fp16.h>
#include <math.h>

#define BATCH 2
#define T 8
#define C 64
#define R 16
#define H 160
#define W 160
#define HW (H*W)            // 25600
#define CHW (C*HW)          // 1,638,400
#define TCHW (T*CHW)
#define C2 128
#define C4 256

typedef unsigned long long ull;

// ---------------- scratch (device globals; referenced ONLY from device code) ----
__device__ float g_pool_all[(T-1)*BATCH*C];
__device__ float g_wd_all[(T-1)*BATCH*C*9];
__device__ float g_fp[BATCH*CHW];
__device__ float g_fusion[(size_t)BATCH*C2*HW];
__device__ float g_a1[(size_t)BATCH*C4*HW];
__device__ float g_a2[(size_t)BATCH*C4*HW];
__device__ __half g_bh1[(size_t)BATCH*C4*HW];
__device__ __half g_bl1[(size_t)BATCH*C4*HW];
__device__ __half g_bh2[(size_t)BATCH*C4*HW];
__device__ __half g_bl2[(size_t)BATCH*C4*HW];
// conv weights pre-split fp16 hi/lo, ldmatrix-ready [tap][ch8][oc128][24]
__device__ __half g_whi[9*8*128*24];
__device__ __half g_wlo[9*8*128*24];
// expand weights [gate][ch4][oc256][24]
__device__ __half g_pwhi[2*4*256*24];
__device__ __half g_pwlo[2*4*256*24];
// contract weights [gate][ch16][oc64][24]
__device__ __half g_cwhi[2*16*64*24];
__device__ __half g_cwlo[2*16*64*24];

// ---------------- mma helpers -----------------------------------------------------
__device__ __forceinline__ void ldsm4(unsigned* r, const void* p) {
    unsigned s = (unsigned)__cvta_generic_to_shared(p);
    asm volatile("ldmatrix.sync.aligned.m8n8.x4.shared.b16 {%0,%1,%2,%3}, [%4];"
        : "=r"(r[0]), "=r"(r[1]), "=r"(r[2]), "=r"(r[3]) : "r"(s));
}
__device__ __forceinline__ void mma16816(float* d, const unsigned* a, const unsigned* b) {
    asm volatile("mma.sync.aligned.m16n8k16.row.col.f32.f16.f16.f32 "
        "{%0,%1,%2,%3},{%4,%5,%6,%7},{%8,%9},{%0,%1,%2,%3};"
        : "+f"(d[0]), "+f"(d[1]), "+f"(d[2]), "+f"(d[3])
        : "r"(a[0]), "r"(a[1]), "r"(a[2]), "r"(a[3]), "r"(b[0]), "r"(b[1]));
}
__device__ __forceinline__ void split2(float v, __half& h, __half& l) {
    h = __float2half_rn(v);
    l = __float2half_rn(v - __half2float(h));
}

// ---------------- pool for ALL steps ----------------------------------------------
__global__ void pool_all_kernel(const float* __restrict__ feature) {
    int g = blockIdx.x;
    int step = g / (BATCH*C);
    int rem  = g % (BATCH*C);
    int bi = rem >> 6, c = rem & 63;
    const float* p = feature + (size_t)bi*TCHW + (size_t)step*CHW + (size_t)c*HW;
    float s = 0.f;
    for (int i = threadIdx.x; i < HW; i += 256) s += p[i];
    __shared__ float red[8];
    #pragma unroll
    for (int o = 16; o; o >>= 1) s += __shfl_down_sync(0xffffffffu, s, o);
    if ((threadIdx.x & 31) == 0) red[threadIdx.x >> 5] = s;
    __syncthreads();
    if (threadIdx.x == 0) {
        float t = 0.f;
        #pragma unroll
        for (int k = 0; k < 8; k++) t += red[k];
        g_pool_all[g] = t * (1.0f / (float)HW);
    }
}

// ---------------- tiny MLP for ALL steps ------------------------------------------
__global__ void mlp_all_kernel(const float* __restrict__ w1,
                               const float* __restrict__ gamma,
                               const float* __restrict__ beta,
                               const float* __restrict__ mean,
                               const float* __restrict__ var,
                               const float* __restrict__ w2,
                               const float* __restrict__ b2) {
    __shared__ float zs[BATCH*R];
    int step = blockIdx.x;
    int tid = threadIdx.x;
    const float* pool = g_pool_all + step*BATCH*C;
    float* wd = g_wd_all + step*BATCH*C*9;
    if (tid < BATCH*R) {
        int bi = tid / R, j = tid % R;
        float s = 0.f;
        for (int c = 0; c < C; c++) s = fmaf(pool[bi*C + c], w1[j*C + c], s);
        s = (s - mean[j]) * rsqrtf(var[j] + 1e-5f) * gamma[j] + beta[j];
        zs[tid] = fmaxf(s, 0.f);
    }
    __syncthreads();
    for (int o = tid; o < BATCH*C*9; o += blockDim.x) {
        int bi = o / (C*9), oo = o % (C*9);
        float s = b2[oo];
        #pragma unroll
        for (int j = 0; j < R; j++) s = fmaf(zs[bi*R + j], w2[oo*R + j], s);
        wd[o] = s;
    }
}

// ---------------- dynamic depthwise 3x3 -----------------------------------------
__global__ void dyndw_kernel(const float* __restrict__ ybase,
                             const float* __restrict__ kc_bias, int step) {
    int idx = blockIdx.x * 256 + threadIdx.x;
    int px = idx % HW;
    int plane = idx / HW;
    int c = plane & 63, bi = plane >> 6;
    const float* p = ybase + (size_t)bi*TCHW + (size_t)c*HW;
    const float* wp = g_wd_all + step*BATCH*C*9 + plane*9;
    float w[9];
    #pragma unroll
    for (int k = 0; k < 9; k++) w[k] = wp[k];
    int y0 = px / W, x0 = px % W;
    float s = 0.f;
    #pragma unroll
    for (int kh = 0; kh < 3; kh++) {
        int yy = y0 + kh - 1;
        if ((unsigned)yy >= H) continue;
        const float* row = p + yy*W;
        #pragma unroll
        for (int kw = 0; kw < 3; kw++) {
            int xx = x0 + kw - 1;
            if ((unsigned)xx < W) s = fmaf(row[xx], w[kh*3 + kw], s);
        }
    }
    g_fp[idx] = s + kc_bias[c];
}

// ---------------- weight split preps (once per launch) ---------------------------
__global__ void prep_w_kernel(const float* __restrict__ conv1_w) {
    int idx = blockIdx.x * 256 + threadIdx.x;
    if (idx >= 9*8*128*16) return;
    int k   = idx & 15;
    int oc  = (idx >> 4) & 127;
    int ch  = (idx >> 11) & 7;
    int tap = idx >> 14;
    int ic = ch*16 + k;
    float v = conv1_w[((size_t)oc*C2 + ic)*9 + tap];
    __half h, l; split2(v, h, l);
    size_t o = ((size_t)(tap*8 + ch)*128 + oc)*24 + k;
    g_whi[o] = h; g_wlo[o] = l;
}
__global__ void prep_pw_kernel(const float* __restrict__ pi1_w, const float* __restrict__ pi2_w) {
    int idx = blockIdx.x * 256 + threadIdx.x;
    if (idx >= 2*4*256*16) return;
    int k    = idx & 15;
    int oc   = (idx >> 4) & 255;
    int ch   = (idx >> 12) & 3;
    int gate = idx >> 14;
    const float* w = gate ? pi2_w : pi1_w;
    float v = w[(size_t)oc*C + ch*16 + k];
    __half h, l; split2(v, h, l);
    size_t o = ((size_t)(gate*4 + ch)*256 + oc)*24 + k;
    g_pwhi[o] = h; g_pwlo[o] = l;
}
__global__ void prep_cw_kernel(const float* __restrict__ po1_w, const float* __restrict__ po2_w) {
    int idx = blockIdx.x * 256 + threadIdx.x;
    if (idx >= 2*16*64*16) return;
    int k    = idx & 15;
    int oc   = (idx >> 4) & 63;
    int ch   = (idx >> 10) & 15;
    int gate = idx >> 14;
    const float* w = gate ? po2_w : po1_w;
    float v = w[(size_t)oc*C4 + ch*16 + k];
    __half h, l; split2(v, h, l);
    size_t o = ((size_t)(gate*16 + ch)*64 + oc)*24 + k;
    g_cwhi[o] = h; g_cwlo[o] = l;
}

// ---------------- conv3x3 via fp16-split mma, 512 thr, 128oc x 128px tile ---------
// 16 warps: wm 0..3 (32oc each) x wn 0..3 (one y-row of 32px each).
// Halo: 6 rows x 34 cols = 204 px-rows. grid (W/32=5, H/4=40, BATCH).
__global__ void __launch_bounds__(512, 1) conv_mma_kernel(const float* __restrict__ xbase,
                                                          const float* __restrict__ bias) {
    __shared__ __align__(16) __half Xhi_s[204*24];
    __shared__ __align__(16) __half Xlo_s[204*24];
    __shared__ __align__(16) __half Whi_s[2][128*24];
    __shared__ __align__(16) __half Wlo_s[2][128*24];

    int tid = threadIdx.x;
    int lane = tid & 31, wid = tid >> 5;
    int wm = wid & 3, wn = wid >> 2;        // wn 0..3
    int x0 = blockIdx.x * 32;
    int y0 = blockIdx.y * 4;
    int bi = blockIdx.z;

    const float* xp  = xbase + (size_t)bi*TCHW;
    const float* fpp = g_fp  + (size_t)bi*CHW;

    float acc[2][4][4];
    #pragma unroll
    for (int m = 0; m < 2; m++)
        #pragma unroll
        for (int n = 0; n < 4; n++)
            #pragma unroll
            for (int r = 0; r < 4; r++) acc[m][n][r] = 0.f;

    // X stager: ic_l = tid>>5 (0..15), rg = tid&31; rows r = rg + 32j (j<7, r<204)
    int ic_l = tid >> 5;
    int rg   = tid & 31;
    // hoisted halo indices (ch-invariant)
    int hgoff[7]; bool hval[7]; int hsm[7];
    #pragma unroll
    for (int j = 0; j < 7; j++) {
        int r = rg + j*32;
        bool ok = r < 204;
        int ry = r / 34, rx = r - ry*34;
        int gy = y0 + ry - 1, gx = x0 + rx - 1;
        bool v = ok && ((unsigned)gy < H) && ((unsigned)gx < W);
        hval[j] = v;
        hgoff[j] = v ? gy*W + gx : 0;
        hsm[j] = ok ? (r*24 + ic_l) : 0;
        if (!ok) hsm[j] = -1;
    }

    int a_row = (lane & 7) + ((lane >> 3) & 1)*8;
    int a_col = (lane >> 4)*8;
    int b_n   = (lane & 7) + ((lane >> 4) & 1)*8;
    int b_col = ((lane >> 3) & 1)*8;
    const char* bPtrHi[2];
    const char* bPtrLo[2];
    #pragma unroll
    for (int p = 0; p < 2; p++) {
        int n = wn*32 + p*16 + b_n;
        int row0 = ((n >> 5) + 1)*34 + (n & 31) + 1;
        bPtrHi[p] = (const char*)Xhi_s + row0*48 + b_col*2;
        bPtrLo[p] = (const char*)Xlo_s + row0*48 + b_col*2;
    }

    for (int ch = 0; ch < 8; ch++) {
        __syncthreads();
        // ---- stage X halo chunk [204 px-rows x 16 k], split once per ch
        {
            int ic = ch*16 + ic_l;
            const float* pl = (ic < C) ? (xp + (size_t)ic*HW) : (fpp + (size_t)(ic - C)*HW);
            #pragma unroll
            for (int j = 0; j < 7; j++) {
                if (hsm[j] >= 0) {
                    float v = hval[j] ? __ldg(pl + hgoff[j]) : 0.f;
                    __half h, l; split2(v, h, l);
                    Xhi_s[hsm[j]] = h;
                    Xlo_s[hsm[j]] = l;
                }
            }
        }
        // ---- stage W(tap=0, ch) into buf 0 (384 float4 per buf)
        if (tid < 384) {
            ((float4*)Whi_s[0])[tid] = ((const float4*)(g_whi + (size_t)(0*8 + ch)*3072))[tid];
            ((float4*)Wlo_s[0])[tid] = ((const float4*)(g_wlo + (size_t)(0*8 + ch)*3072))[tid];
        }
        __syncthreads();

        #pragma unroll
        for (int tap = 0; tap < 9; tap++) {
            int cur = tap & 1;
            int dy = tap/3 - 1, dx = tap%3 - 1;
            int tapoff = (dy*34 + dx)*48;

            unsigned Ahi[2][4], Alo[2][4];
            ldsm4(Ahi[0], &Whi_s[cur][(wm*32 +      a_row)*24 + a_col]);
            ldsm4(Ahi[1], &Whi_s[cur][(wm*32 + 16 + a_row)*24 + a_col]);
            ldsm4(Alo[0], &Wlo_s[cur][(wm*32 +      a_row)*24 + a_col]);
            ldsm4(Alo[1], &Wlo_s[cur][(wm*32 + 16 + a_row)*24 + a_col]);
            unsigned Bhi[4][2], Blo[4][2];
            #pragma unroll
            for (int p = 0; p < 2; p++) {
                unsigned t[4];
                ldsm4(t, bPtrHi[p] + tapoff);
                Bhi[2*p][0] = t[0]; Bhi[2*p][1] = t[1];
                Bhi[2*p+1][0] = t[2]; Bhi[2*p+1][1] = t[3];
                ldsm4(t, bPtrLo[p] + tapoff);
                Blo[2*p][0] = t[0]; Blo[2*p][1] = t[1];
                Blo[2*p+1][0] = t[2]; Blo[2*p+1][1] = t[3];
            }
            #pragma unroll
            for (int m = 0; m < 2; m++)
                #pragma unroll
                for (int n = 0; n < 4; n++) {
                    mma16816(acc[m][n], Ahi[m], Bhi[n]);
                    mma16816(acc[m][n], Ahi[m], Blo[n]);
                    mma16816(acc[m][n], Alo[m], Bhi[n]);
                }

            if (tap < 8) {
                int nxt = (tap + 1) & 1;
                if (tid < 384) {
                    ((float4*)Whi_s[nxt])[tid] = ((const float4*)(g_whi + (size_t)((tap+1)*8 + ch)*3072))[tid];
                    ((float4*)Wlo_s[nxt])[tid] = ((const float4*)(g_wlo + (size_t)((tap+1)*8 + ch)*3072))[tid];
                }
                __syncthreads();
            }
        }
    }

    // ---- epilogue: bias + leaky + store
    int row_ = lane >> 2;
    int colp = (lane & 3)*2;
    int yo = y0 + wn;
    #pragma unroll
    for (int m = 0; m < 2; m++) {
        int ocA = wm*32 + m*16 + row_;
        int ocB = ocA + 8;
        float bA = bias[ocA], bB = bias[ocB];
        #pragma unroll
        for (int n = 0; n < 4; n++) {
            int xo = x0 + n*8 + colp;
            float v0 = acc[m][n][0] + bA, v1 = acc[m][n][1] + bA;
            float v2 = acc[m][n][2] + bB, v3 = acc[m][n][3] + bB;
            v0 = (v0 > 0.f) ? v0 : 0.1f*v0;
            v1 = (v1 > 0.f) ? v1 : 0.1f*v1;
            v2 = (v2 > 0.f) ? v2 : 0.1f*v2;
            v3 = (v3 > 0.f) ? v3 : 0.1f*v3;
            *((float2*)(g_fusion + ((size_t)bi*C2 + ocA)*HW + (size_t)yo*W + xo)) = make_float2(v0, v1);
            *((float2*)(g_fusion + ((size_t)bi*C2 + ocB)*HW + (size_t)yo*W + xo)) = make_float2(v2, v3);
        }
    }
}

// ---------------- expand via mma: D[128oc x 64px], K=64 (verified R9) -------------
__global__ void __launch_bounds__(256, 2) expand_mma_kernel(const float* __restrict__ b1,
                                                            const float* __restrict__ b2) {
    __shared__ __align__(16) __half Whi_s[128*24];
    __shared__ __align__(16) __half Wlo_s[128*24];
    __shared__ __align__(16) __half Xhi_s[64*24];
    __shared__ __align__(16) __half Xlo_s[64*24];

    int tid = threadIdx.x;
    int lane = tid & 31, wid = tid >> 5;
    int wm = wid & 3, wn = wid >> 2;
    int px0 = blockIdx.x * 64;
    int gy  = blockIdx.y;
    int gate = gy >> 1, hh = gy & 1;
    int bi = blockIdx.z;

    const float* bias = gate ? b2 : b1;
    float* outb       = gate ? g_a2 : g_a1;
    int halfoff       = gate ? C : 0;

    float acc[2][4][4];
    #pragma unroll
    for (int m = 0; m < 2; m++)
        #pragma unroll
        for (int n = 0; n < 4; n++)
            #pragma unroll
            for (int r = 0; r < 4; r++) acc[m][n][r] = 0.f;

    int ic_l = tid >> 4;
    int n0   = (tid & 15)*4;

    int a_row = (lane & 7) + ((lane >> 3) & 1)*8;
    int a_col = (lane >> 4)*8;
    int b_n   = (lane & 7) + ((lane >> 4) & 1)*8;
    int b_col = ((lane >> 3) & 1)*8;

    #pragma unroll
    for (int ch = 0; ch < 4; ch++) {
        __syncthreads();
        {
            const float* src = g_fusion + ((size_t)(bi*C2 + halfoff + ch*16 + ic_l))*HW + px0 + n0;
            float4 v = *((const float4*)src);
            float vv[4] = {v.x, v.y, v.z, v.w};
            #pragma unroll
            for (int j = 0; j < 4; j++) {
                __half h, l; split2(vv[j], h, l);
                Xhi_s[(n0 + j)*24 + ic_l] = h;
                Xlo_s[(n0 + j)*24 + ic_l] = l;
            }
        }
        {
            const float4* sH = (const float4*)(g_pwhi + ((size_t)(gate*4 + ch)*256 + hh*128)*24);
            const float4* sL = (const float4*)(g_pwlo + ((size_t)(gate*4 + ch)*256 + hh*128)*24);
            ((float4*)Whi_s)[tid] = sH[tid];
            ((float4*)Wlo_s)[tid] = sL[tid];
            if (tid < 128) {
                ((float4*)Whi_s)[256 + tid] = sH[256 + tid];
                ((float4*)Wlo_s)[256 + tid] = sL[256 + tid];
            }
        }
        __syncthreads();

        unsigned Ahi[2][4], Alo[2][4];
        ldsm4(Ahi[0], &Whi_s[(wm*32 +      a_row)*24 + a_col]);
        ldsm4(Ahi[1], &Whi_s[(wm*32 + 16 + a_row)*24 + a_col]);
        ldsm4(Alo[0], &Wlo_s[(wm*32 +      a_row)*24 + a_col]);
        ldsm4(Alo[1], &Wlo_s[(wm*32 + 16 + a_row)*24 + a_col]);
        unsigned Bhi[4][2], Blo[4][2];
        #pragma unroll
        for (int p = 0; p < 2; p++) {
            unsigned t[4];
            ldsm4(t, &Xhi_s[(wn*32 + p*16 + b_n)*24 + b_col]);
            Bhi[2*p][0] = t[0]; Bhi[2*p][1] = t[1];
            Bhi[2*p+1][0] = t[2]; Bhi[2*p+1][1] = t[3];
            ldsm4(t, &Xlo_s[(wn*32 + p*16 + b_n)*24 + b_col]);
            Blo[2*p][0] = t[0]; Blo[2*p][1] = t[1];
            Blo[2*p+1][0] = t[2]; Blo[2*p+1][1] = t[3];
        }
        #pragma unroll
        for (int m = 0; m < 2; m++)
            #pragma unroll
            for (int n = 0; n < 4; n++) {
                mma16816(acc[m][n], Ahi[m], Bhi[n]);
                mma16816(acc[m][n], Ahi[m], Blo[n]);
                mma16816(acc[m][n], Alo[m], Bhi[n]);
            }
    }

    int row_ = lane >> 2;
    int colp = (lane & 3)*2;
    #pragma unroll
    for (int m = 0; m < 2; m++) {
        int ocA = hh*128 + wm*32 + m*16 + row_;
        int ocB = ocA + 8;
        float bA = bias[ocA], bB = bias[ocB];
        #pragma unroll
        for (int n = 0; n < 4; n++) {
            int xo = px0 + wn*32 + n*8 + colp;
            *((float2*)(outb + ((size_t)bi*C4 + ocA)*HW + xo)) =
                make_float2(acc[m][n][0] + bA, acc[m][n][1] + bA);
            *((float2*)(outb + ((size_t)bi*C4 + ocB)*HW + xo)) =
                make_float2(acc[m][n][2] + bB, acc[m][n][3] + bB);
        }
    }
}

// ---------------- static depthwise 3x3, 4px/thread; outputs split hi/lo fp16 ------
__global__ void __launch_bounds__(256) dw_both_kernel(const float* __restrict__ w1,
                                                      const float* __restrict__ b1,
                                                      const float* __restrict__ w2,
                                                      const float* __restrict__ b2) {
    int gate = blockIdx.y;
    const float* inb  = gate ? g_a2 : g_a1;
    __half* outh      = gate ? g_bh2 : g_bh1;
    __half* outl      = gate ? g_bl2 : g_bl1;
    const float* wgt  = gate ? w2 : w1;
    const float* bias = gate ? b2 : b1;

    int g = blockIdx.x * 256 + threadIdx.x;
    int px4   = g % (HW/4);
    int plane = g / (HW/4);
    int ch = plane & (C4 - 1);
    int y  = px4 / (W/4);
    int x0 = (px4 % (W/4)) * 4;

    const float* p = inb + (size_t)plane*HW;
    const float* wp = wgt + ch*9;
    float w[9];
    #pragma unroll
    for (int k = 0; k < 9; k++) w[k] = wp[k];

    float A[3][6];
    #pragma unroll
    for (int kh = 0; kh < 3; kh++) {
        int yy = y + kh - 1;
        if ((unsigned)yy < H) {
            const float* row = p + yy*W;
            float4 m = *((const float4*)(row + x0));
            A[kh][0] = (x0 > 0)      ? row[x0 - 1] : 0.f;
            A[kh][1] = m.x; A[kh][2] = m.y; A[kh][3] = m.z; A[kh][4] = m.w;
            A[kh][5] = (x0 + 4 < W)  ? row[x0 + 4] : 0.f;
        } else {
            #pragma unroll
            for (int j = 0; j < 6; j++) A[kh][j] = 0.f;
        }
    }

    float bv = bias[ch];
    __align__(8) __half hv[4];
    __align__(8) __half lv[4];
    #pragma unroll
    for (int j = 0; j < 4; j++) {
        float s = bv;
        #pragma unroll
        for (int kh = 0; kh < 3; kh++)
            #pragma unroll
            for (int kw = 0; kw < 3; kw++)
                s = fmaf(A[kh][j + kw], w[kh*3 + kw], s);
        split2(s, hv[j], lv[j]);
    }
    size_t off = (size_t)plane*HW + (size_t)y*W + x0;
    *((uint2*)(outh + off)) = *((uint2*)hv);
    *((uint2*)(outl + off)) = *((uint2*)lv);
}

// ---------------- fused BOTH-gate contract + sigmoid + combine (verified R11) -----
__global__ void __launch_bounds__(256, 2) contract_both_kernel(const float* __restrict__ po1_b,
                                                               const float* __restrict__ po2_b,
                                                               float* __restrict__ outbase) {
    __shared__ __align__(16) __half Ahi_s[2][64*24];
    __shared__ __align__(16) __half Alo_s[2][64*24];
    __shared__ __align__(16) __half Bhi_s[2][128*24];
    __shared__ __align__(16) __half Blo_s[2][128*24];

    int tid = threadIdx.x;
    int lane = tid & 31, wid = tid >> 5;
    int wm = wid & 1, wn = wid >> 1;
    int px0 = blockIdx.x * 128;
    int bi = blockIdx.y;

    float acc[2][2][4][4];
    #pragma unroll
    for (int gg = 0; gg < 2; gg++)
        #pragma unroll
        for (int m = 0; m < 2; m++)
            #pragma unroll
            for (int n = 0; n < 4; n++)
                #pragma unroll
                for (int r = 0; r < 4; r++) acc[gg][m][n][r] = 0.f;

    int ic_l = tid >> 4;
    int n0   = (tid & 15)*8;

    int a_row = (lane & 7) + ((lane >> 3) & 1)*8;
    int a_col = (lane >> 4)*8;
    int b_n   = (lane & 7) + ((lane >> 4) & 1)*8;
    int b_col = ((lane >> 3) & 1)*8;

    for (int ch = 0; ch < 16; ch++) {
        __syncthreads();
        {
            size_t off = ((size_t)(bi*C4 + ch*16 + ic_l))*HW + px0 + n0;
            float4 vh1 = *((const float4*)(g_bh1 + off));
            float4 vl1 = *((const float4*)(g_bl1 + off));
            float4 vh2 = *((const float4*)(g_bh2 + off));
            float4 vl2 = *((const float4*)(g_bl2 + off));
            const __half* h1 = (const __half*)&vh1;
            const __half* l1 = (const __half*)&vl1;
            const __half* h2 = (const __half*)&vh2;
            const __half* l2 = (const __half*)&vl2;
            #pragma unroll
            for (int j = 0; j < 8; j++) {
                Bhi_s[0][(n0 + j)*24 + ic_l] = h1[j];
                Blo_s[0][(n0 + j)*24 + ic_l] = l1[j];
                Bhi_s[1][(n0 + j)*24 + ic_l] = h2[j];
                Blo_s[1][(n0 + j)*24 + ic_l] = l2[j];
            }
        }
        if (tid < 192) {
            ((float4*)Ahi_s[0])[tid] = ((const float4*)(g_cwhi + ((size_t)(0*16 + ch)*64)*24))[tid];
            ((float4*)Alo_s[0])[tid] = ((const float4*)(g_cwlo + ((size_t)(0*16 + ch)*64)*24))[tid];
            ((float4*)Ahi_s[1])[tid] = ((const float4*)(g_cwhi + ((size_t)(1*16 + ch)*64)*24))[tid];
            ((float4*)Alo_s[1])[tid] = ((const float4*)(g_cwlo + ((size_t)(1*16 + ch)*64)*24))[tid];
        }
        __syncthreads();

        #pragma unroll
        for (int gg = 0; gg < 2; gg++) {
            unsigned Ahi[2][4], Alo[2][4];
            ldsm4(Ahi[0], &Ahi_s[gg][(wm*32 +      a_row)*24 + a_col]);
            ldsm4(Ahi[1], &Ahi_s[gg][(wm*32 + 16 + a_row)*24 + a_col]);
            ldsm4(Alo[0], &Alo_s[gg][(wm*32 +      a_row)*24 + a_col]);
            ldsm4(Alo[1], &Alo_s[gg][(wm*32 + 16 + a_row)*24 + a_col]);
            unsigned Bhi[4][2], Blo[4][2];
            #pragma unroll
            for (int p = 0; p < 2; p++) {
                unsigned t[4];
                ldsm4(t, &Bhi_s[gg][(wn*32 + p*16 + b_n)*24 + b_col]);
                Bhi[2*p][0] = t[0]; Bhi[2*p][1] = t[1];
                Bhi[2*p+1][0] = t[2]; Bhi[2*p+1][1] = t[3];
                ldsm4(t, &Blo_s[gg][(wn*32 + p*16 + b_n)*24 + b_col]);
                Blo[2*p][0] = t[0]; Blo[2*p][1] = t[1];
                Blo[2*p+1][0] = t[2]; Blo[2*p+1][1] = t[3];
            }
            #pragma unroll
            for (int m = 0; m < 2; m++)
                #pragma unroll
                for (int n = 0; n < 4; n++) {
                    mma16816(acc[gg][m][n], Ahi[m], Bhi[n]);
                    mma16816(acc[gg][m][n], Ahi[m], Blo[n]);
                    mma16816(acc[gg][m][n], Alo[m], Bhi[n]);
                }
        }
    }

    int row_ = lane >> 2;
    int colp = (lane & 3)*2;
    #pragma unroll
    for (int m = 0; m < 2; m++) {
        int ocA = wm*32 + m*16 + row_;
        int ocB = ocA + 8;
        float b1A = po1_b[ocA], b1B = po1_b[ocB];
        float b2A = po2_b[ocA], b2B = po2_b[ocB];
        #pragma unroll
        for (int n = 0; n < 4; n++) {
            int xo = px0 + wn*32 + n*8 + colp;
            float g1A0 = 1.0f / (1.0f + __expf(-(acc[0][m][n][0] + b1A)));
            float g1A1 = 1.0f / (1.0f + __expf(-(acc[0][m][n][1] + b1A)));
            float g1B0 = 1.0f / (1.0f + __expf(-(acc[0][m][n][2] + b1B)));
            float g1B1 = 1.0f / (1.0f + __expf(-(acc[0][m][n][3] + b1B)));
            float g2A0 = 1.0f / (1.0f + __expf(-(acc[1][m][n][0] + b2A)));
            float g2A1 = 1.0f / (1.0f + __expf(-(acc[1][m][n][1] + b2A)));
            float g2B0 = 1.0f / (1.0f + __expf(-(acc[1][m][n][2] + b2B)));
            float g2B1 = 1.0f / (1.0f + __expf(-(acc[1][m][n][3] + b2B)));
            float2 f1A = *((const float2*)(g_fusion + ((size_t)bi*C2 + ocA)*HW + xo));
            float2 f2A = *((const float2*)(g_fusion + ((size_t)bi*C2 + C + ocA)*HW + xo));
            float2 f1B = *((const float2*)(g_fusion + ((size_t)bi*C2 + ocB)*HW + xo));
            float2 f2B = *((const float2*)(g_fusion + ((size_t)bi*C2 + C + ocB)*HW + xo));
            *((float2*)(outbase + (size_t)bi*TCHW + (size_t)ocA*HW + xo)) =
                make_float2(f1A.x*g1A0 + f2A.x*g2A0, f1A.y*g1A1 + f2A.y*g2A1);
            *((float2*)(outbase + (size_t)bi*TCHW + (size_t)ocB*HW + xo)) =
                make_float2(f1B.x*g1B0 + f2B.x*g2B0, f1B.y*g1B1 + f2B.y*g2B1);
        }
    }
}

// ---------------- launcher -------------------------------------------------------
extern "C" void kernel_launch(void* const* d_in, const int* in_sizes, int n_in,
                              void* d_out, int out_size) {
    (void)in_sizes; (void)n_in; (void)out_size;
    const float* feature   = (const float*)d_in[0];
    const float* kc_w1     = (const float*)d_in[1];
    const float* kc_gamma  = (const float*)d_in[2];
    const float* kc_beta   = (const float*)d_in[3];
    const float* kc_mean   = (const float*)d_in[4];
    const float* kc_var    = (const float*)d_in[5];
    const float* kc_w2     = (const float*)d_in[6];
    const float* kc_b2     = (const float*)d_in[7];
    const float* kc_bias   = (const float*)d_in[8];
    const float* conv1_w   = (const float*)d_in[9];
    const float* conv1_b   = (const float*)d_in[10];
    const float* pi1_w     = (const float*)d_in[11];
    const float* pi1_b     = (const float*)d_in[12];
    const float* dw1_w     = (const float*)d_in[13];
    const float* dw1_b     = (const float*)d_in[14];
    const float* po1_w     = (const float*)d_in[15];
    const float* po1_b     = (const float*)d_in[16];
    const float* pi2_w     = (const float*)d_in[17];
    const float* pi2_b     = (const float*)d_in[18];
    const float* dw2_w     = (const float*)d_in[19];
    const float* dw2_b     = (const float*)d_in[20];
    const float* po2_w     = (const float*)d_in[21];
    const float* po2_b     = (const float*)d_in[22];
    float* out = (float*)d_out;

    // out[:, T-1] = feature[:, T-1]
    for (int bi = 0; bi < BATCH; bi++) {
        size_t off = ((size_t)bi*T + (T-1)) * CHW;
        cudaMemcpyAsync(out + off, feature + off, (size_t)CHW*sizeof(float),
                        cudaMemcpyDeviceToDevice, 0);
    }

    // one-time: weight splits + ALL per-step dynamic weights
    prep_w_kernel<<<(9*8*128*16 + 255)/256, 256>>>(conv1_w);
    prep_pw_kernel<<<(2*4*256*16 + 255)/256, 256>>>(pi1_w, pi2_w);
    prep_cw_kernel<<<(2*16*64*16 + 255)/256, 256>>>(po1_w, po2_w);
    pool_all_kernel<<<(T-1)*BATCH*C, 256>>>(feature);
    mlp_all_kernel<<<T-1, 128>>>(kc_w1, kc_gamma, kc_beta, kc_mean, kc_var, kc_w2, kc_b2);

    for (int i = T - 2; i >= 0; --i) {
        const float* xbase = feature + (size_t)i*CHW;
        const float* ybase = out + (size_t)(i+1)*CHW;

        dyndw_kernel<<<(BATCH*CHW)/256, 256>>>(ybase, kc_bias, i);
        conv_mma_kernel<<<dim3(W/32, H/4, BATCH), 512>>>(xbase, conv1_b);
        expand_mma_kernel<<<dim3(HW/64, 4, BATCH), 256>>>(pi1_b, pi2_b);
        dw_both_kernel<<<dim3((BATCH*C4*HW/4)/256, 2), 256>>>(dw1_w, dw1_b, dw2_w, dw2_b);
        contract_both_kernel<<<dim3(HW/128, BATCH), 256>>>(po1_b, po2_b, out + (size_t)i*CHW);
    }
}

// round 14
// speedup vs baseline: 9.5229x; 1.2796x over previous
#include <cuda_runtime.h>
#include <cuda_fp16.h>
#include <math.h>

#define BATCH 2
#define T 8
#define C 64
#define R 16
#define H 160
#define W 160
#define HW (H*W)            // 25600
#define CHW (C*HW)          // 1,638,400
#define TCHW (T*CHW)
#define C2 128
#define C4 256

typedef unsigned long long ull;

// ---------------- scratch (device globals; referenced ONLY from device code) ----
__device__ float g_pool_all[(T-1)*BATCH*C];
__device__ float g_wd_all[(T-1)*BATCH*C*9];
__device__ float g_fp[BATCH*CHW];
__device__ float g_fusion[(size_t)BATCH*C2*HW];
__device__ float g_a1[(size_t)BATCH*C4*HW];
__device__ float g_a2[(size_t)BATCH*C4*HW];
__device__ __half g_bh1[(size_t)BATCH*C4*HW];
__device__ __half g_bl1[(size_t)BATCH*C4*HW];
__device__ __half g_bh2[(size_t)BATCH*C4*HW];
__device__ __half g_bl2[(size_t)BATCH*C4*HW];
// conv weights pre-split fp16 hi/lo, ldmatrix-ready [tap][ch8][oc128][24]
__device__ __half g_whi[9*8*128*24];
__device__ __half g_wlo[9*8*128*24];
// expand weights [gate][ch4][oc256][24]
__device__ __half g_pwhi[2*4*256*24];
__device__ __half g_pwlo[2*4*256*24];
// contract weights [gate][ch16][oc64][24]
__device__ __half g_cwhi[2*16*64*24];
__device__ __half g_cwlo[2*16*64*24];

// ---------------- mma helpers -----------------------------------------------------
__device__ __forceinline__ void ldsm4(unsigned* r, const void* p) {
    unsigned s = (unsigned)__cvta_generic_to_shared(p);
    asm volatile("ldmatrix.sync.aligned.m8n8.x4.shared.b16 {%0,%1,%2,%3}, [%4];"
        : "=r"(r[0]), "=r"(r[1]), "=r"(r[2]), "=r"(r[3]) : "r"(s));
}
__device__ __forceinline__ void ldsm4t(unsigned* r, const void* p) {
    unsigned s = (unsigned)__cvta_generic_to_shared(p);
    asm volatile("ldmatrix.sync.aligned.m8n8.x4.trans.shared.b16 {%0,%1,%2,%3}, [%4];"
        : "=r"(r[0]), "=r"(r[1]), "=r"(r[2]), "=r"(r[3]) : "r"(s));
}
__device__ __forceinline__ void mma16816(float* d, const unsigned* a, const unsigned* b) {
    asm volatile("mma.sync.aligned.m16n8k16.row.col.f32.f16.f16.f32 "
        "{%0,%1,%2,%3},{%4,%5,%6,%7},{%8,%9},{%0,%1,%2,%3};"
        : "+f"(d[0]), "+f"(d[1]), "+f"(d[2]), "+f"(d[3])
        : "r"(a[0]), "r"(a[1]), "r"(a[2]), "r"(a[3]), "r"(b[0]), "r"(b[1]));
}
__device__ __forceinline__ void split2(float v, __half& h, __half& l) {
    h = __float2half_rn(v);
    l = __float2half_rn(v - __half2float(h));
}

// ---------------- pool for ALL steps ----------------------------------------------
__global__ void pool_all_kernel(const float* __restrict__ feature) {
    int g = blockIdx.x;
    int step = g / (BATCH*C);
    int rem  = g % (BATCH*C);
    int bi = rem >> 6, c = rem & 63;
    const float* p = feature + (size_t)bi*TCHW + (size_t)step*CHW + (size_t)c*HW;
    float s = 0.f;
    for (int i = threadIdx.x; i < HW; i += 256) s += p[i];
    __shared__ float red[8];
    #pragma unroll
    for (int o = 16; o; o >>= 1) s += __shfl_down_sync(0xffffffffu, s, o);
    if ((threadIdx.x & 31) == 0) red[threadIdx.x >> 5] = s;
    __syncthreads();
    if (threadIdx.x == 0) {
        float t = 0.f;
        #pragma unroll
        for (int k = 0; k < 8; k++) t += red[k];
        g_pool_all[g] = t * (1.0f / (float)HW);
    }
}

// ---------------- tiny MLP for ALL steps ------------------------------------------
__global__ void mlp_all_kernel(const float* __restrict__ w1,
                               const float* __restrict__ gamma,
                               const float* __restrict__ beta,
                               const float* __restrict__ mean,
                               const float* __restrict__ var,
                               const float* __restrict__ w2,
                               const float* __restrict__ b2) {
    __shared__ float zs[BATCH*R];
    int step = blockIdx.x;
    int tid = threadIdx.x;
    const float* pool = g_pool_all + step*BATCH*C;
    float* wd = g_wd_all + step*BATCH*C*9;
    if (tid < BATCH*R) {
        int bi = tid / R, j = tid % R;
        float s = 0.f;
        for (int c = 0; c < C; c++) s = fmaf(pool[bi*C + c], w1[j*C + c], s);
        s = (s - mean[j]) * rsqrtf(var[j] + 1e-5f) * gamma[j] + beta[j];
        zs[tid] = fmaxf(s, 0.f);
    }
    __syncthreads();
    for (int o = tid; o < BATCH*C*9; o += blockDim.x) {
        int bi = o / (C*9), oo = o % (C*9);
        float s = b2[oo];
        #pragma unroll
        for (int j = 0; j < R; j++) s = fmaf(zs[bi*R + j], w2[oo*R + j], s);
        wd[o] = s;
    }
}

// ---------------- dynamic depthwise 3x3 -----------------------------------------
__global__ void dyndw_kernel(const float* __restrict__ ybase,
                             const float* __restrict__ kc_bias, int step) {
    int idx = blockIdx.x * 256 + threadIdx.x;
    int px = idx % HW;
    int plane = idx / HW;
    int c = plane & 63, bi = plane >> 6;
    const float* p = ybase + (size_t)bi*TCHW + (size_t)c*HW;
    const float* wp = g_wd_all + step*BATCH*C*9 + plane*9;
    float w[9];
    #pragma unroll
    for (int k = 0; k < 9; k++) w[k] = wp[k];
    int y0 = px / W, x0 = px % W;
    float s = 0.f;
    #pragma unroll
    for (int kh = 0; kh < 3; kh++) {
        int yy = y0 + kh - 1;
        if ((unsigned)yy >= H) continue;
        const float* row = p + yy*W;
        #pragma unroll
        for (int kw = 0; kw < 3; kw++) {
            int xx = x0 + kw - 1;
            if ((unsigned)xx < W) s = fmaf(row[xx], w[kh*3 + kw], s);
        }
    }
    g_fp[idx] = s + kc_bias[c];
}

// ---------------- weight split preps (once per launch) ---------------------------
__global__ void prep_w_kernel(const float* __restrict__ conv1_w) {
    int idx = blockIdx.x * 256 + threadIdx.x;
    if (idx >= 9*8*128*16) return;
    int k   = idx & 15;
    int oc  = (idx >> 4) & 127;
    int ch  = (idx >> 11) & 7;
    int tap = idx >> 14;
    int ic = ch*16 + k;
    float v = conv1_w[((size_t)oc*C2 + ic)*9 + tap];
    __half h, l; split2(v, h, l);
    size_t o = ((size_t)(tap*8 + ch)*128 + oc)*24 + k;
    g_whi[o] = h; g_wlo[o] = l;
}
__global__ void prep_pw_kernel(const float* __restrict__ pi1_w, const float* __restrict__ pi2_w) {
    int idx = blockIdx.x * 256 + threadIdx.x;
    if (idx >= 2*4*256*16) return;
    int k    = idx & 15;
    int oc   = (idx >> 4) & 255;
    int ch   = (idx >> 12) & 3;
    int gate = idx >> 14;
    const float* w = gate ? pi2_w : pi1_w;
    float v = w[(size_t)oc*C + ch*16 + k];
    __half h, l; split2(v, h, l);
    size_t o = ((size_t)(gate*4 + ch)*256 + oc)*24 + k;
    g_pwhi[o] = h; g_pwlo[o] = l;
}
__global__ void prep_cw_kernel(const float* __restrict__ po1_w, const float* __restrict__ po2_w) {
    int idx = blockIdx.x * 256 + threadIdx.x;
    if (idx >= 2*16*64*16) return;
    int k    = idx & 15;
    int oc   = (idx >> 4) & 63;
    int ch   = (idx >> 10) & 15;
    int gate = idx >> 14;
    const float* w = gate ? po2_w : po1_w;
    float v = w[(size_t)oc*C4 + ch*16 + k];
    __half h, l; split2(v, h, l);
    size_t o = ((size_t)(gate*16 + ch)*64 + oc)*24 + k;
    g_cwhi[o] = h; g_cwlo[o] = l;
}

// ---------------- conv3x3 via fp16-split mma (verified R12: [px][k] halo) ---------
// 512 thr, 128oc x 128px tile (4y x 32x). Halo 204 px-rows x 16 k, stride 24.
// Tap offsets are row-stride multiples (48 B) -> ldmatrix alignment OK.
__global__ void __launch_bounds__(512, 1) conv_mma_kernel(const float* __restrict__ xbase,
                                                          const float* __restrict__ bias) {
    __shared__ __align__(16) __half Xhi_s[204*24];
    __shared__ __align__(16) __half Xlo_s[204*24];
    __shared__ __align__(16) __half Whi_s[2][128*24];
    __shared__ __align__(16) __half Wlo_s[2][128*24];

    int tid = threadIdx.x;
    int lane = tid & 31, wid = tid >> 5;
    int wm = wid & 3, wn = wid >> 2;
    int x0 = blockIdx.x * 32;
    int y0 = blockIdx.y * 4;
    int bi = blockIdx.z;

    const float* xp  = xbase + (size_t)bi*TCHW;
    const float* fpp = g_fp  + (size_t)bi*CHW;

    float acc[2][4][4];
    #pragma unroll
    for (int m = 0; m < 2; m++)
        #pragma unroll
        for (int n = 0; n < 4; n++)
            #pragma unroll
            for (int r = 0; r < 4; r++) acc[m][n][r] = 0.f;

    int ic_l = tid >> 5;
    int rg   = tid & 31;
    int hgoff[7]; bool hval[7]; int hsm[7];
    #pragma unroll
    for (int j = 0; j < 7; j++) {
        int r = rg + j*32;
        bool ok = r < 204;
        int ry = r / 34, rx = r - ry*34;
        int gy = y0 + ry - 1, gx = x0 + rx - 1;
        bool v = ok && ((unsigned)gy < H) && ((unsigned)gx < W);
        hval[j] = v;
        hgoff[j] = v ? gy*W + gx : 0;
        hsm[j] = ok ? (r*24 + ic_l) : -1;
    }

    int a_row = (lane & 7) + ((lane >> 3) & 1)*8;
    int a_col = (lane >> 4)*8;
    int b_n   = (lane & 7) + ((lane >> 4) & 1)*8;
    int b_col = ((lane >> 3) & 1)*8;
    const char* bPtrHi[2];
    const char* bPtrLo[2];
    #pragma unroll
    for (int p = 0; p < 2; p++) {
        int n = wn*32 + p*16 + b_n;
        int row0 = ((n >> 5) + 1)*34 + (n & 31) + 1;
        bPtrHi[p] = (const char*)Xhi_s + row0*48 + b_col*2;
        bPtrLo[p] = (const char*)Xlo_s + row0*48 + b_col*2;
    }

    for (int ch = 0; ch < 8; ch++) {
        __syncthreads();
        {
            int ic = ch*16 + ic_l;
            const float* pl = (ic < C) ? (xp + (size_t)ic*HW) : (fpp + (size_t)(ic - C)*HW);
            #pragma unroll
            for (int j = 0; j < 7; j++) {
                if (hsm[j] >= 0) {
                    float v = hval[j] ? __ldg(pl + hgoff[j]) : 0.f;
                    __half h, l; split2(v, h, l);
                    Xhi_s[hsm[j]] = h;
                    Xlo_s[hsm[j]] = l;
                }
            }
        }
        if (tid < 384) {
            ((float4*)Whi_s[0])[tid] = ((const float4*)(g_whi + (size_t)(0*8 + ch)*3072))[tid];
            ((float4*)Wlo_s[0])[tid] = ((const float4*)(g_wlo + (size_t)(0*8 + ch)*3072))[tid];
        }
        __syncthreads();

        #pragma unroll
        for (int tap = 0; tap < 9; tap++) {
            int cur = tap & 1;
            int dy = tap/3 - 1, dx = tap%3 - 1;
            int tapoff = (dy*34 + dx)*48;

            unsigned Ahi[2][4], Alo[2][4];
            ldsm4(Ahi[0], &Whi_s[cur][(wm*32 +      a_row)*24 + a_col]);
            ldsm4(Ahi[1], &Whi_s[cur][(wm*32 + 16 + a_row)*24 + a_col]);
            ldsm4(Alo[0], &Wlo_s[cur][(wm*32 +      a_row)*24 + a_col]);
            ldsm4(Alo[1], &Wlo_s[cur][(wm*32 + 16 + a_row)*24 + a_col]);
            unsigned Bhi[4][2], Blo[4][2];
            #pragma unroll
            for (int p = 0; p < 2; p++) {
                unsigned t[4];
                ldsm4(t, bPtrHi[p] + tapoff);
                Bhi[2*p][0] = t[0]; Bhi[2*p][1] = t[1];
                Bhi[2*p+1][0] = t[2]; Bhi[2*p+1][1] = t[3];
                ldsm4(t, bPtrLo[p] + tapoff);
                Blo[2*p][0] = t[0]; Blo[2*p][1] = t[1];
                Blo[2*p+1][0] = t[2]; Blo[2*p+1][1] = t[3];
            }
            #pragma unroll
            for (int m = 0; m < 2; m++)
                #pragma unroll
                for (int n = 0; n < 4; n++) {
                    mma16816(acc[m][n], Ahi[m], Bhi[n]);
                    mma16816(acc[m][n], Ahi[m], Blo[n]);
                    mma16816(acc[m][n], Alo[m], Bhi[n]);
                }

            if (tap < 8) {
                int nxt = (tap + 1) & 1;
                if (tid < 384) {
                    ((float4*)Whi_s[nxt])[tid] = ((const float4*)(g_whi + (size_t)((tap+1)*8 + ch)*3072))[tid];
                    ((float4*)Wlo_s[nxt])[tid] = ((const float4*)(g_wlo + (size_t)((tap+1)*8 + ch)*3072))[tid];
                }
                __syncthreads();
            }
        }
    }

    int row_ = lane >> 2;
    int colp = (lane & 3)*2;
    int yo = y0 + wn;
    #pragma unroll
    for (int m = 0; m < 2; m++) {
        int ocA = wm*32 + m*16 + row_;
        int ocB = ocA + 8;
        float bA = bias[ocA], bB = bias[ocB];
        #pragma unroll
        for (int n = 0; n < 4; n++) {
            int xo = x0 + n*8 + colp;
            float v0 = acc[m][n][0] + bA, v1 = acc[m][n][1] + bA;
            float v2 = acc[m][n][2] + bB, v3 = acc[m][n][3] + bB;
            v0 = (v0 > 0.f) ? v0 : 0.1f*v0;
            v1 = (v1 > 0.f) ? v1 : 0.1f*v1;
            v2 = (v2 > 0.f) ? v2 : 0.1f*v2;
            v3 = (v3 > 0.f) ? v3 : 0.1f*v3;
            *((float2*)(g_fusion + ((size_t)bi*C2 + ocA)*HW + (size_t)yo*W + xo)) = make_float2(v0, v1);
            *((float2*)(g_fusion + ((size_t)bi*C2 + ocB)*HW + (size_t)yo*W + xo)) = make_float2(v2, v3);
        }
    }
}

// ---------------- expand via mma, [k][px] X + trans (aligned): K=64 ---------------
#define EPS 72
__global__ void __launch_bounds__(256, 2) expand_mma_kernel(const float* __restrict__ b1,
                                                            const float* __restrict__ b2) {
    __shared__ __align__(16) __half Whi_s[128*24];
    __shared__ __align__(16) __half Wlo_s[128*24];
    __shared__ __align__(16) __half Xhi_s[16*EPS];
    __shared__ __align__(16) __half Xlo_s[16*EPS];

    int tid = threadIdx.x;
    int lane = tid & 31, wid = tid >> 5;
    int wm = wid & 3, wn = wid >> 2;
    int px0 = blockIdx.x * 64;
    int gy  = blockIdx.y;
    int gate = gy >> 1, hh = gy & 1;
    int bi = blockIdx.z;

    const float* bias = gate ? b2 : b1;
    float* outb       = gate ? g_a2 : g_a1;
    int halfoff       = gate ? C : 0;

    float acc[2][4][4];
    #pragma unroll
    for (int m = 0; m < 2; m++)
        #pragma unroll
        for (int n = 0; n < 4; n++)
            #pragma unroll
            for (int r = 0; r < 4; r++) acc[m][n][r] = 0.f;

    int ic_l = tid >> 4;
    int n0   = (tid & 15)*4;

    int a_row = (lane & 7) + ((lane >> 3) & 1)*8;
    int a_col = (lane >> 4)*8;
    int k_l  = (lane & 7) + ((lane >> 3) & 1)*8;
    int nsel = ((lane >> 4) & 1)*8;

    #pragma unroll
    for (int ch = 0; ch < 4; ch++) {
        __syncthreads();
        {
            const float* src = g_fusion + ((size_t)(bi*C2 + halfoff + ch*16 + ic_l))*HW + px0 + n0;
            float4 v = *((const float4*)src);
            float vv[4] = {v.x, v.y, v.z, v.w};
            __align__(8) __half hv[4], lv[4];
            #pragma unroll
            for (int j = 0; j < 4; j++) split2(vv[j], hv[j], lv[j]);
            *((uint2*)(Xhi_s + ic_l*EPS + n0)) = *((uint2*)hv);
            *((uint2*)(Xlo_s + ic_l*EPS + n0)) = *((uint2*)lv);
        }
        {
            const float4* sH = (const float4*)(g_pwhi + ((size_t)(gate*4 + ch)*256 + hh*128)*24);
            const float4* sL = (const float4*)(g_pwlo + ((size_t)(gate*4 + ch)*256 + hh*128)*24);
            ((float4*)Whi_s)[tid] = sH[tid];
            ((float4*)Wlo_s)[tid] = sL[tid];
            if (tid < 128) {
                ((float4*)Whi_s)[256 + tid] = sH[256 + tid];
                ((float4*)Wlo_s)[256 + tid] = sL[256 + tid];
            }
        }
        __syncthreads();

        unsigned Ahi[2][4], Alo[2][4];
        ldsm4(Ahi[0], &Whi_s[(wm*32 +      a_row)*24 + a_col]);
        ldsm4(Ahi[1], &Whi_s[(wm*32 + 16 + a_row)*24 + a_col]);
        ldsm4(Alo[0], &Wlo_s[(wm*32 +      a_row)*24 + a_col]);
        ldsm4(Alo[1], &Wlo_s[(wm*32 + 16 + a_row)*24 + a_col]);
        unsigned Bhi[4][2], Blo[4][2];
        #pragma unroll
        for (int p = 0; p < 2; p++) {
            unsigned t[4];
            ldsm4t(t, &Xhi_s[k_l*EPS + wn*32 + p*16 + nsel]);
            Bhi[2*p][0] = t[0]; Bhi[2*p][1] = t[1];
            Bhi[2*p+1][0] = t[2]; Bhi[2*p+1][1] = t[3];
            ldsm4t(t, &Xlo_s[k_l*EPS + wn*32 + p*16 + nsel]);
            Blo[2*p][0] = t[0]; Blo[2*p][1] = t[1];
            Blo[2*p+1][0] = t[2]; Blo[2*p+1][1] = t[3];
        }
        #pragma unroll
        for (int m = 0; m < 2; m++)
            #pragma unroll
            for (int n = 0; n < 4; n++) {
                mma16816(acc[m][n], Ahi[m], Bhi[n]);
                mma16816(acc[m][n], Ahi[m], Blo[n]);
                mma16816(acc[m][n], Alo[m], Bhi[n]);
            }
    }

    int row_ = lane >> 2;
    int colp = (lane & 3)*2;
    #pragma unroll
    for (int m = 0; m < 2; m++) {
        int ocA = hh*128 + wm*32 + m*16 + row_;
        int ocB = ocA + 8;
        float bA = bias[ocA], bB = bias[ocB];
        #pragma unroll
        for (int n = 0; n < 4; n++) {
            int xo = px0 + wn*32 + n*8 + colp;
            *((float2*)(outb + ((size_t)bi*C4 + ocA)*HW + xo)) =
                make_float2(acc[m][n][0] + bA, acc[m][n][1] + bA);
            *((float2*)(outb + ((size_t)bi*C4 + ocB)*HW + xo)) =
                make_float2(acc[m][n][2] + bB, acc[m][n][3] + bB);
        }
    }
}

// ---------------- static depthwise 3x3, 4px/thread; outputs split hi/lo fp16 ------
__global__ void __launch_bounds__(256) dw_both_kernel(const float* __restrict__ w1,
                                                      const float* __restrict__ b1,
                                                      const float* __restrict__ w2,
                                                      const float* __restrict__ b2) {
    int gate = blockIdx.y;
    const float* inb  = gate ? g_a2 : g_a1;
    __half* outh      = gate ? g_bh2 : g_bh1;
    __half* outl      = gate ? g_bl2 : g_bl1;
    const float* wgt  = gate ? w2 : w1;
    const float* bias = gate ? b2 : b1;

    int g = blockIdx.x * 256 + threadIdx.x;
    int px4   = g % (HW/4);
    int plane = g / (HW/4);
    int ch = plane & (C4 - 1);
    int y  = px4 / (W/4);
    int x0 = (px4 % (W/4)) * 4;

    const float* p = inb + (size_t)plane*HW;
    const float* wp = wgt + ch*9;
    float w[9];
    #pragma unroll
    for (int k = 0; k < 9; k++) w[k] = wp[k];

    float A[3][6];
    #pragma unroll
    for (int kh = 0; kh < 3; kh++) {
        int yy = y + kh - 1;
        if ((unsigned)yy < H) {
            const float* row = p + yy*W;
            float4 m = *((const float4*)(row + x0));
            A[kh][0] = (x0 > 0)      ? row[x0 - 1] : 0.f;
            A[kh][1] = m.x; A[kh][2] = m.y; A[kh][3] = m.z; A[kh][4] = m.w;
            A[kh][5] = (x0 + 4 < W)  ? row[x0 + 4] : 0.f;
        } else {
            #pragma unroll
            for (int j = 0; j < 6; j++) A[kh][j] = 0.f;
        }
    }

    float bv = bias[ch];
    __align__(8) __half hv[4];
    __align__(8) __half lv[4];
    #pragma unroll
    for (int j = 0; j < 4; j++) {
        float s = bv;
        #pragma unroll
        for (int kh = 0; kh < 3; kh++)
            #pragma unroll
            for (int kw = 0; kw < 3; kw++)
                s = fmaf(A[kh][j + kw], w[kh*3 + kw], s);
        split2(s, hv[j], lv[j]);
    }
    size_t off = (size_t)plane*HW + (size_t)y*W + x0;
    *((uint2*)(outh + off)) = *((uint2*)hv);
    *((uint2*)(outl + off)) = *((uint2*)lv);
}

// ---------------- fused BOTH-gate contract, [k][px] B + trans (aligned) -----------
#define CPS 136
__global__ void __launch_bounds__(256, 2) contract_both_kernel(const float* __restrict__ po1_b,
                                                               const float* __restrict__ po2_b,
                                                               float* __restrict__ outbase) {
    __shared__ __align__(16) __half Ahi_s[2][64*24];
    __shared__ __align__(16) __half Alo_s[2][64*24];
    __shared__ __align__(16) __half Bhi_s[2][16*CPS];
    __shared__ __align__(16) __half Blo_s[2][16*CPS];

    int tid = threadIdx.x;
    int lane = tid & 31, wid = tid >> 5;
    int wm = wid & 1, wn = wid >> 1;
    int px0 = blockIdx.x * 128;
    int bi = blockIdx.y;

    float acc[2][2][4][4];
    #pragma unroll
    for (int gg = 0; gg < 2; gg++)
        #pragma unroll
        for (int m = 0; m < 2; m++)
            #pragma unroll
            for (int n = 0; n < 4; n++)
                #pragma unroll
                for (int r = 0; r < 4; r++) acc[gg][m][n][r] = 0.f;

    int ic_l = tid >> 4;
    int n0   = (tid & 15)*8;

    int a_row = (lane & 7) + ((lane >> 3) & 1)*8;
    int a_col = (lane >> 4)*8;
    int k_l  = (lane & 7) + ((lane >> 3) & 1)*8;
    int nsel = ((lane >> 4) & 1)*8;

    for (int ch = 0; ch < 16; ch++) {
        __syncthreads();
        {
            size_t off = ((size_t)(bi*C4 + ch*16 + ic_l))*HW + px0 + n0;
            *((float4*)(Bhi_s[0] + ic_l*CPS + n0)) = *((const float4*)(g_bh1 + off));
            *((float4*)(Blo_s[0] + ic_l*CPS + n0)) = *((const float4*)(g_bl1 + off));
            *((float4*)(Bhi_s[1] + ic_l*CPS + n0)) = *((const float4*)(g_bh2 + off));
            *((float4*)(Blo_s[1] + ic_l*CPS + n0)) = *((const float4*)(g_bl2 + off));
        }
        if (tid < 192) {
            ((float4*)Ahi_s[0])[tid] = ((const float4*)(g_cwhi + ((size_t)(0*16 + ch)*64)*24))[tid];
            ((float4*)Alo_s[0])[tid] = ((const float4*)(g_cwlo + ((size_t)(0*16 + ch)*64)*24))[tid];
            ((float4*)Ahi_s[1])[tid] = ((const float4*)(g_cwhi + ((size_t)(1*16 + ch)*64)*24))[tid];
            ((float4*)Alo_s[1])[tid] = ((const float4*)(g_cwlo + ((size_t)(1*16 + ch)*64)*24))[tid];
        }
        __syncthreads();

        #pragma unroll
        for (int gg = 0; gg < 2; gg++) {
            unsigned Ahi[2][4], Alo[2][4];
            ldsm4(Ahi[0], &Ahi_s[gg][(wm*32 +      a_row)*24 + a_col]);
            ldsm4(Ahi[1], &Ahi_s[gg][(wm*32 + 16 + a_row)*24 + a_col]);
            ldsm4(Alo[0], &Alo_s[gg][(wm*32 +      a_row)*24 + a_col]);
            ldsm4(Alo[1], &Alo_s[gg][(wm*32 + 16 + a_row)*24 + a_col]);
            unsigned Bhi[4][2], Blo[4][2];
            #pragma unroll
            for (int p = 0; p < 2; p++) {
                unsigned t[4];
                ldsm4t(t, &Bhi_s[gg][k_l*CPS + wn*32 + p*16 + nsel]);
                Bhi[2*p][0] = t[0]; Bhi[2*p][1] = t[1];
                Bhi[2*p+1][0] = t[2]; Bhi[2*p+1][1] = t[3];
                ldsm4t(t, &Blo_s[gg][k_l*CPS + wn*32 + p*16 + nsel]);
                Blo[2*p][0] = t[0]; Blo[2*p][1] = t[1];
                Blo[2*p+1][0] = t[2]; Blo[2*p+1][1] = t[3];
            }
            #pragma unroll
            for (int m = 0; m < 2; m++)
                #pragma unroll
                for (int n = 0; n < 4; n++) {
                    mma16816(acc[gg][m][n], Ahi[m], Bhi[n]);
                    mma16816(acc[gg][m][n], Ahi[m], Blo[n]);
                    mma16816(acc[gg][m][n], Alo[m], Bhi[n]);
                }
        }
    }

    int row_ = lane >> 2;
    int colp = (lane & 3)*2;
    #pragma unroll
    for (int m = 0; m < 2; m++) {
        int ocA = wm*32 + m*16 + row_;
        int ocB = ocA + 8;
        float b1A = po1_b[ocA], b1B = po1_b[ocB];
        float b2A = po2_b[ocA], b2B = po2_b[ocB];
        #pragma unroll
        for (int n = 0; n < 4; n++) {
            int xo = px0 + wn*32 + n*8 + colp;
            float g1A0 = 1.0f / (1.0f + __expf(-(acc[0][m][n][0] + b1A)));
            float g1A1 = 1.0f / (1.0f + __expf(-(acc[0][m][n][1] + b1A)));
            float g1B0 = 1.0f / (1.0f + __expf(-(acc[0][m][n][2] + b1B)));
            float g1B1 = 1.0f / (1.0f + __expf(-(acc[0][m][n][3] + b1B)));
            float g2A0 = 1.0f / (1.0f + __expf(-(acc[1][m][n][0] + b2A)));
            float g2A1 = 1.0f / (1.0f + __expf(-(acc[1][m][n][1] + b2A)));
            float g2B0 = 1.0f / (1.0f + __expf(-(acc[1][m][n][2] + b2B)));
            float g2B1 = 1.0f / (1.0f + __expf(-(acc[1][m][n][3] + b2B)));
            float2 f1A = *((const float2*)(g_fusion + ((size_t)bi*C2 + ocA)*HW + xo));
            float2 f2A = *((const float2*)(g_fusion + ((size_t)bi*C2 + C + ocA)*HW + xo));
            float2 f1B = *((const float2*)(g_fusion + ((size_t)bi*C2 + ocB)*HW + xo));
            float2 f2B = *((const float2*)(g_fusion + ((size_t)bi*C2 + C + ocB)*HW + xo));
            *((float2*)(outbase + (size_t)bi*TCHW + (size_t)ocA*HW + xo)) =
                make_float2(f1A.x*g1A0 + f2A.x*g2A0, f1A.y*g1A1 + f2A.y*g2A1);
            *((float2*)(outbase + (size_t)bi*TCHW + (size_t)ocB*HW + xo)) =
                make_float2(f1B.x*g1B0 + f2B.x*g2B0, f1B.y*g1B1 + f2B.y*g2B1);
        }
    }
}

// ---------------- launcher -------------------------------------------------------
extern "C" void kernel_launch(void* const* d_in, const int* in_sizes, int n_in,
                              void* d_out, int out_size) {
    (void)in_sizes; (void)n_in; (void)out_size;
    const float* feature   = (const float*)d_in[0];
    const float* kc_w1     = (const float*)d_in[1];
    const float* kc_gamma  = (const float*)d_in[2];
    const float* kc_beta   = (const float*)d_in[3];
    const float* kc_mean   = (const float*)d_in[4];
    const float* kc_var    = (const float*)d_in[5];
    const float* kc_w2     = (const float*)d_in[6];
    const float* kc_b2     = (const float*)d_in[7];
    const float* kc_bias   = (const float*)d_in[8];
    const float* conv1_w   = (const float*)d_in[9];
    const float* conv1_b   = (const float*)d_in[10];
    const float* pi1_w     = (const float*)d_in[11];
    const float* pi1_b     = (const float*)d_in[12];
    const float* dw1_w     = (const float*)d_in[13];
    const float* dw1_b     = (const float*)d_in[14];
    const float* po1_w     = (const float*)d_in[15];
    const float* po1_b     = (const float*)d_in[16];
    const float* pi2_w     = (const float*)d_in[17];
    const float* pi2_b     = (const float*)d_in[18];
    const float* dw2_w     = (const float*)d_in[19];
    const float* dw2_b     = (const float*)d_in[20];
    const float* po2_w     = (const float*)d_in[21];
    const float* po2_b     = (const float*)d_in[22];
    float* out = (float*)d_out;

    // out[:, T-1] = feature[:, T-1]
    for (int bi = 0; bi < BATCH; bi++) {
        size_t off = ((size_t)bi*T + (T-1)) * CHW;
        cudaMemcpyAsync(out + off, feature + off, (size_t)CHW*sizeof(float),
                        cudaMemcpyDeviceToDevice, 0);
    }

    // one-time: weight splits + ALL per-step dynamic weights
    prep_w_kernel<<<(9*8*128*16 + 255)/256, 256>>>(conv1_w);
    prep_pw_kernel<<<(2*4*256*16 + 255)/256, 256>>>(pi1_w, pi2_w);
    prep_cw_kernel<<<(2*16*64*16 + 255)/256, 256>>>(po1_w, po2_w);
    pool_all_kernel<<<(T-1)*BATCH*C, 256>>>(feature);
    mlp_all_kernel<<<T-1, 128>>>(kc_w1, kc_gamma, kc_beta, kc_mean, kc_var, kc_w2, kc_b2);

    for (int i = T - 2; i >= 0; --i) {
        const float* xbase = feature + (size_t)i*CHW;
        const float* ybase = out + (size_t)(i+1)*CHW;

        dyndw_kernel<<<(BATCH*CHW)/256, 256>>>(ybase, kc_bias, i);
        conv_mma_kernel<<<dim3(W/32, H/4, BATCH), 512>>>(xbase, conv1_b);
        expand_mma_kernel<<<dim3(HW/64, 4, BATCH), 256>>>(pi1_b, pi2_b);
        dw_both_kernel<<<dim3((BATCH*C4*HW/4)/256, 2), 256>>>(dw1_w, dw1_b, dw2_w, dw2_b);
        contract_both_kernel<<<dim3(HW/128, BATCH), 256>>>(po1_b, po2_b, out + (size_t)i*CHW);
    }
}

// round 15
// speedup vs baseline: 9.7702x; 1.0260x over previous
#include <cuda_runtime.h>
#include <cuda_fp16.h>
#include <math.h>

#define BATCH 2
#define T 8
#define C 64
#define R 16
#define H 160
#define W 160
#define HW (H*W)            // 25600
#define CHW (C*HW)          // 1,638,400
#define TCHW (T*CHW)
#define C2 128
#define C4 256

typedef unsigned long long ull;

// ---------------- scratch (device globals; referenced ONLY from device code) ----
__device__ float g_pool_all[(T-1)*BATCH*C];
__device__ float g_wd_all[(T-1)*BATCH*C*9];
__device__ float g_fp[BATCH*CHW];
__device__ float g_fusion[(size_t)BATCH*C2*HW];
__device__ float g_a1[(size_t)BATCH*C4*HW];
__device__ float g_a2[(size_t)BATCH*C4*HW];
__device__ __half g_bh1[(size_t)BATCH*C4*HW];
__device__ __half g_bl1[(size_t)BATCH*C4*HW];
__device__ __half g_bh2[(size_t)BATCH*C4*HW];
__device__ __half g_bl2[(size_t)BATCH*C4*HW];
// conv weights pre-split fp16 hi/lo, ldmatrix-ready [tap][ch8][oc128][24]
__device__ __half g_whi[9*8*128*24];
__device__ __half g_wlo[9*8*128*24];
// expand weights [gate][ch4][oc256][24]
__device__ __half g_pwhi[2*4*256*24];
__device__ __half g_pwlo[2*4*256*24];
// contract weights [gate][ch16][oc64][24]
__device__ __half g_cwhi[2*16*64*24];
__device__ __half g_cwlo[2*16*64*24];

// ---------------- mma helpers -----------------------------------------------------
__device__ __forceinline__ void ldsm4(unsigned* r, const void* p) {
    unsigned s = (unsigned)__cvta_generic_to_shared(p);
    asm volatile("ldmatrix.sync.aligned.m8n8.x4.shared.b16 {%0,%1,%2,%3}, [%4];"
        : "=r"(r[0]), "=r"(r[1]), "=r"(r[2]), "=r"(r[3]) : "r"(s));
}
__device__ __forceinline__ void ldsm4t(unsigned* r, const void* p) {
    unsigned s = (unsigned)__cvta_generic_to_shared(p);
    asm volatile("ldmatrix.sync.aligned.m8n8.x4.trans.shared.b16 {%0,%1,%2,%3}, [%4];"
        : "=r"(r[0]), "=r"(r[1]), "=r"(r[2]), "=r"(r[3]) : "r"(s));
}
__device__ __forceinline__ void mma16816(float* d, const unsigned* a, const unsigned* b) {
    asm volatile("mma.sync.aligned.m16n8k16.row.col.f32.f16.f16.f32 "
        "{%0,%1,%2,%3},{%4,%5,%6,%7},{%8,%9},{%0,%1,%2,%3};"
        : "+f"(d[0]), "+f"(d[1]), "+f"(d[2]), "+f"(d[3])
        : "r"(a[0]), "r"(a[1]), "r"(a[2]), "r"(a[3]), "r"(b[0]), "r"(b[1]));
}
__device__ __forceinline__ void split2(float v, __half& h, __half& l) {
    h = __float2half_rn(v);
    l = __float2half_rn(v - __half2float(h));
}

// ---------------- pool for ALL steps ----------------------------------------------
__global__ void pool_all_kernel(const float* __restrict__ feature) {
    int g = blockIdx.x;
    int step = g / (BATCH*C);
    int rem  = g % (BATCH*C);
    int bi = rem >> 6, c = rem & 63;
    const float* p = feature + (size_t)bi*TCHW + (size_t)step*CHW + (size_t)c*HW;
    float s = 0.f;
    for (int i = threadIdx.x; i < HW; i += 256) s += p[i];
    __shared__ float red[8];
    #pragma unroll
    for (int o = 16; o; o >>= 1) s += __shfl_down_sync(0xffffffffu, s, o);
    if ((threadIdx.x & 31) == 0) red[threadIdx.x >> 5] = s;
    __syncthreads();
    if (threadIdx.x == 0) {
        float t = 0.f;
        #pragma unroll
        for (int k = 0; k < 8; k++) t += red[k];
        g_pool_all[g] = t * (1.0f / (float)HW);
    }
}

// ---------------- tiny MLP for ALL steps ------------------------------------------
__global__ void mlp_all_kernel(const float* __restrict__ w1,
                               const float* __restrict__ gamma,
                               const float* __restrict__ beta,
                               const float* __restrict__ mean,
                               const float* __restrict__ var,
                               const float* __restrict__ w2,
                               const float* __restrict__ b2) {
    __shared__ float zs[BATCH*R];
    int step = blockIdx.x;
    int tid = threadIdx.x;
    const float* pool = g_pool_all + step*BATCH*C;
    float* wd = g_wd_all + step*BATCH*C*9;
    if (tid < BATCH*R) {
        int bi = tid / R, j = tid % R;
        float s = 0.f;
        for (int c = 0; c < C; c++) s = fmaf(pool[bi*C + c], w1[j*C + c], s);
        s = (s - mean[j]) * rsqrtf(var[j] + 1e-5f) * gamma[j] + beta[j];
        zs[tid] = fmaxf(s, 0.f);
    }
    __syncthreads();
    for (int o = tid; o < BATCH*C*9; o += blockDim.x) {
        int bi = o / (C*9), oo = o % (C*9);
        float s = b2[oo];
        #pragma unroll
        for (int j = 0; j < R; j++) s = fmaf(zs[bi*R + j], w2[oo*R + j], s);
        wd[o] = s;
    }
}

// ---------------- dynamic depthwise 3x3, 4px/thread (dw_both pattern) -------------
__global__ void __launch_bounds__(256) dyndw_kernel(const float* __restrict__ ybase,
                                                    const float* __restrict__ kc_bias, int step) {
    int g = blockIdx.x * 256 + threadIdx.x;        // BATCH*CHW/4 threads
    int px4   = g % (HW/4);
    int plane = g / (HW/4);                        // bi*C + c
    int c = plane & 63, bi = plane >> 6;
    int y  = px4 / (W/4);
    int x0 = (px4 % (W/4)) * 4;

    const float* p = ybase + (size_t)bi*TCHW + (size_t)c*HW;
    const float* wp = g_wd_all + step*BATCH*C*9 + plane*9;
    float w[9];
    #pragma unroll
    for (int k = 0; k < 9; k++) w[k] = wp[k];

    float A[3][6];
    #pragma unroll
    for (int kh = 0; kh < 3; kh++) {
        int yy = y + kh - 1;
        if ((unsigned)yy < H) {
            const float* row = p + yy*W;
            float4 m = *((const float4*)(row + x0));
            A[kh][0] = (x0 > 0)      ? row[x0 - 1] : 0.f;
            A[kh][1] = m.x; A[kh][2] = m.y; A[kh][3] = m.z; A[kh][4] = m.w;
            A[kh][5] = (x0 + 4 < W)  ? row[x0 + 4] : 0.f;
        } else {
            #pragma unroll
            for (int j = 0; j < 6; j++) A[kh][j] = 0.f;
        }
    }

    float bv = kc_bias[c];
    float r[4];
    #pragma unroll
    for (int j = 0; j < 4; j++) {
        float s = bv;
        #pragma unroll
        for (int kh = 0; kh < 3; kh++)
            #pragma unroll
            for (int kw = 0; kw < 3; kw++)
                s = fmaf(A[kh][j + kw], w[kh*3 + kw], s);
        r[j] = s;
    }
    *((float4*)(g_fp + (size_t)plane*HW + (size_t)y*W + x0)) = make_float4(r[0], r[1], r[2], r[3]);
}

// ---------------- weight split preps (once per launch) ---------------------------
__global__ void prep_w_kernel(const float* __restrict__ conv1_w) {
    int idx = blockIdx.x * 256 + threadIdx.x;
    if (idx >= 9*8*128*16) return;
    int k   = idx & 15;
    int oc  = (idx >> 4) & 127;
    int ch  = (idx >> 11) & 7;
    int tap = idx >> 14;
    int ic = ch*16 + k;
    float v = conv1_w[((size_t)oc*C2 + ic)*9 + tap];
    __half h, l; split2(v, h, l);
    size_t o = ((size_t)(tap*8 + ch)*128 + oc)*24 + k;
    g_whi[o] = h; g_wlo[o] = l;
}
__global__ void prep_pw_kernel(const float* __restrict__ pi1_w, const float* __restrict__ pi2_w) {
    int idx = blockIdx.x * 256 + threadIdx.x;
    if (idx >= 2*4*256*16) return;
    int k    = idx & 15;
    int oc   = (idx >> 4) & 255;
    int ch   = (idx >> 12) & 3;
    int gate = idx >> 14;
    const float* w = gate ? pi2_w : pi1_w;
    float v = w[(size_t)oc*C + ch*16 + k];
    __half h, l; split2(v, h, l);
    size_t o = ((size_t)(gate*4 + ch)*256 + oc)*24 + k;
    g_pwhi[o] = h; g_pwlo[o] = l;
}
__global__ void prep_cw_kernel(const float* __restrict__ po1_w, const float* __restrict__ po2_w) {
    int idx = blockIdx.x * 256 + threadIdx.x;
    if (idx >= 2*16*64*16) return;
    int k    = idx & 15;
    int oc   = (idx >> 4) & 63;
    int ch   = (idx >> 10) & 15;
    int gate = idx >> 14;
    const float* w = gate ? po2_w : po1_w;
    float v = w[(size_t)oc*C4 + ch*16 + k];
    __half h, l; split2(v, h, l);
    size_t o = ((size_t)(gate*16 + ch)*64 + oc)*24 + k;
    g_cwhi[o] = h; g_cwlo[o] = l;
}

// ---------------- conv3x3 via fp16-split mma (verified R12/R14: [px][k] halo) -----
__global__ void __launch_bounds__(512, 1) conv_mma_kernel(const float* __restrict__ xbase,
                                                          const float* __restrict__ bias) {
    __shared__ __align__(16) __half Xhi_s[204*24];
    __shared__ __align__(16) __half Xlo_s[204*24];
    __shared__ __align__(16) __half Whi_s[2][128*24];
    __shared__ __align__(16) __half Wlo_s[2][128*24];

    int tid = threadIdx.x;
    int lane = tid & 31, wid = tid >> 5;
    int wm = wid & 3, wn = wid >> 2;
    int x0 = blockIdx.x * 32;
    int y0 = blockIdx.y * 4;
    int bi = blockIdx.z;

    const float* xp  = xbase + (size_t)bi*TCHW;
    const float* fpp = g_fp  + (size_t)bi*CHW;

    float acc[2][4][4];
    #pragma unroll
    for (int m = 0; m < 2; m++)
        #pragma unroll
        for (int n = 0; n < 4; n++)
            #pragma unroll
            for (int r = 0; r < 4; r++) acc[m][n][r] = 0.f;

    int ic_l = tid >> 5;
    int rg   = tid & 31;
    int hgoff[7]; bool hval[7]; int hsm[7];
    #pragma unroll
    for (int j = 0; j < 7; j++) {
        int r = rg + j*32;
        bool ok = r < 204;
        int ry = r / 34, rx = r - ry*34;
        int gy = y0 + ry - 1, gx = x0 + rx - 1;
        bool v = ok && ((unsigned)gy < H) && ((unsigned)gx < W);
        hval[j] = v;
        hgoff[j] = v ? gy*W + gx : 0;
        hsm[j] = ok ? (r*24 + ic_l) : -1;
    }

    int a_row = (lane & 7) + ((lane >> 3) & 1)*8;
    int a_col = (lane >> 4)*8;
    int b_n   = (lane & 7) + ((lane >> 4) & 1)*8;
    int b_col = ((lane >> 3) & 1)*8;
    const char* bPtrHi[2];
    const char* bPtrLo[2];
    #pragma unroll
    for (int p = 0; p < 2; p++) {
        int n = wn*32 + p*16 + b_n;
        int row0 = ((n >> 5) + 1)*34 + (n & 31) + 1;
        bPtrHi[p] = (const char*)Xhi_s + row0*48 + b_col*2;
        bPtrLo[p] = (const char*)Xlo_s + row0*48 + b_col*2;
    }

    for (int ch = 0; ch < 8; ch++) {
        __syncthreads();
        {
            int ic = ch*16 + ic_l;
            const float* pl = (ic < C) ? (xp + (size_t)ic*HW) : (fpp + (size_t)(ic - C)*HW);
            #pragma unroll
            for (int j = 0; j < 7; j++) {
                if (hsm[j] >= 0) {
                    float v = hval[j] ? __ldg(pl + hgoff[j]) : 0.f;
                    __half h, l; split2(v, h, l);
                    Xhi_s[hsm[j]] = h;
                    Xlo_s[hsm[j]] = l;
                }
            }
        }
        if (tid < 384) {
            ((float4*)Whi_s[0])[tid] = ((const float4*)(g_whi + (size_t)(0*8 + ch)*3072))[tid];
            ((float4*)Wlo_s[0])[tid] = ((const float4*)(g_wlo + (size_t)(0*8 + ch)*3072))[tid];
        }
        __syncthreads();

        #pragma unroll
        for (int tap = 0; tap < 9; tap++) {
            int cur = tap & 1;
            int dy = tap/3 - 1, dx = tap%3 - 1;
            int tapoff = (dy*34 + dx)*48;

            unsigned Ahi[2][4], Alo[2][4];
            ldsm4(Ahi[0], &Whi_s[cur][(wm*32 +      a_row)*24 + a_col]);
            ldsm4(Ahi[1], &Whi_s[cur][(wm*32 + 16 + a_row)*24 + a_col]);
            ldsm4(Alo[0], &Wlo_s[cur][(wm*32 +      a_row)*24 + a_col]);
            ldsm4(Alo[1], &Wlo_s[cur][(wm*32 + 16 + a_row)*24 + a_col]);
            unsigned Bhi[4][2], Blo[4][2];
            #pragma unroll
            for (int p = 0; p < 2; p++) {
                unsigned t[4];
                ldsm4(t, bPtrHi[p] + tapoff);
                Bhi[2*p][0] = t[0]; Bhi[2*p][1] = t[1];
                Bhi[2*p+1][0] = t[2]; Bhi[2*p+1][1] = t[3];
                ldsm4(t, bPtrLo[p] + tapoff);
                Blo[2*p][0] = t[0]; Blo[2*p][1] = t[1];
                Blo[2*p+1][0] = t[2]; Blo[2*p+1][1] = t[3];
            }
            #pragma unroll
            for (int m = 0; m < 2; m++)
                #pragma unroll
                for (int n = 0; n < 4; n++) {
                    mma16816(acc[m][n], Ahi[m], Bhi[n]);
                    mma16816(acc[m][n], Ahi[m], Blo[n]);
                    mma16816(acc[m][n], Alo[m], Bhi[n]);
                }

            if (tap < 8) {
                int nxt = (tap + 1) & 1;
                if (tid < 384) {
                    ((float4*)Whi_s[nxt])[tid] = ((const float4*)(g_whi + (size_t)((tap+1)*8 + ch)*3072))[tid];
                    ((float4*)Wlo_s[nxt])[tid] = ((const float4*)(g_wlo + (size_t)((tap+1)*8 + ch)*3072))[tid];
                }
                __syncthreads();
            }
        }
    }

    int row_ = lane >> 2;
    int colp = (lane & 3)*2;
    int yo = y0 + wn;
    #pragma unroll
    for (int m = 0; m < 2; m++) {
        int ocA = wm*32 + m*16 + row_;
        int ocB = ocA + 8;
        float bA = bias[ocA], bB = bias[ocB];
        #pragma unroll
        for (int n = 0; n < 4; n++) {
            int xo = x0 + n*8 + colp;
            float v0 = acc[m][n][0] + bA, v1 = acc[m][n][1] + bA;
            float v2 = acc[m][n][2] + bB, v3 = acc[m][n][3] + bB;
            v0 = (v0 > 0.f) ? v0 : 0.1f*v0;
            v1 = (v1 > 0.f) ? v1 : 0.1f*v1;
            v2 = (v2 > 0.f) ? v2 : 0.1f*v2;
            v3 = (v3 > 0.f) ? v3 : 0.1f*v3;
            *((float2*)(g_fusion + ((size_t)bi*C2 + ocA)*HW + (size_t)yo*W + xo)) = make_float2(v0, v1);
            *((float2*)(g_fusion + ((size_t)bi*C2 + ocB)*HW + (size_t)yo*W + xo)) = make_float2(v2, v3);
        }
    }
}

// ---------------- expand via mma, [k][px] X + trans (verified R14): K=64 ----------
#define EPS 72
__global__ void __launch_bounds__(256, 2) expand_mma_kernel(const float* __restrict__ b1,
                                                            const float* __restrict__ b2) {
    __shared__ __align__(16) __half Whi_s[128*24];
    __shared__ __align__(16) __half Wlo_s[128*24];
    __shared__ __align__(16) __half Xhi_s[16*EPS];
    __shared__ __align__(16) __half Xlo_s[16*EPS];

    int tid = threadIdx.x;
    int lane = tid & 31, wid = tid >> 5;
    int wm = wid & 3, wn = wid >> 2;
    int px0 = blockIdx.x * 64;
    int gy  = blockIdx.y;
    int gate = gy >> 1, hh = gy & 1;
    int bi = blockIdx.z;

    const float* bias = gate ? b2 : b1;
    float* outb       = gate ? g_a2 : g_a1;
    int halfoff       = gate ? C : 0;

    float acc[2][4][4];
    #pragma unroll
    for (int m = 0; m < 2; m++)
        #pragma unroll
        for (int n = 0; n < 4; n++)
            #pragma unroll
            for (int r = 0; r < 4; r++) acc[m][n][r] = 0.f;

    int ic_l = tid >> 4;
    int n0   = (tid & 15)*4;

    int a_row = (lane & 7) + ((lane >> 3) & 1)*8;
    int a_col = (lane >> 4)*8;
    int k_l  = (lane & 7) + ((lane >> 3) & 1)*8;
    int nsel = ((lane >> 4) & 1)*8;

    #pragma unroll
    for (int ch = 0; ch < 4; ch++) {
        __syncthreads();
        {
            const float* src = g_fusion + ((size_t)(bi*C2 + halfoff + ch*16 + ic_l))*HW + px0 + n0;
            float4 v = *((const float4*)src);
            float vv[4] = {v.x, v.y, v.z, v.w};
            __align__(8) __half hv[4], lv[4];
            #pragma unroll
            for (int j = 0; j < 4; j++) split2(vv[j], hv[j], lv[j]);
            *((uint2*)(Xhi_s + ic_l*EPS + n0)) = *((uint2*)hv);
            *((uint2*)(Xlo_s + ic_l*EPS + n0)) = *((uint2*)lv);
        }
        {
            const float4* sH = (const float4*)(g_pwhi + ((size_t)(gate*4 + ch)*256 + hh*128)*24);
            const float4* sL = (const float4*)(g_pwlo + ((size_t)(gate*4 + ch)*256 + hh*128)*24);
            ((float4*)Whi_s)[tid] = sH[tid];
            ((float4*)Wlo_s)[tid] = sL[tid];
            if (tid < 128) {
                ((float4*)Whi_s)[256 + tid] = sH[256 + tid];
                ((float4*)Wlo_s)[256 + tid] = sL[256 + tid];
            }
        }
        __syncthreads();

        unsigned Ahi[2][4], Alo[2][4];
        ldsm4(Ahi[0], &Whi_s[(wm*32 +      a_row)*24 + a_col]);
        ldsm4(Ahi[1], &Whi_s[(wm*32 + 16 + a_row)*24 + a_col]);
        ldsm4(Alo[0], &Wlo_s[(wm*32 +      a_row)*24 + a_col]);
        ldsm4(Alo[1], &Wlo_s[(wm*32 + 16 + a_row)*24 + a_col]);
        unsigned Bhi[4][2], Blo[4][2];
        #pragma unroll
        for (int p = 0; p < 2; p++) {
            unsigned t[4];
            ldsm4t(t, &Xhi_s[k_l*EPS + wn*32 + p*16 + nsel]);
            Bhi[2*p][0] = t[0]; Bhi[2*p][1] = t[1];
            Bhi[2*p+1][0] = t[2]; Bhi[2*p+1][1] = t[3];
            ldsm4t(t, &Xlo_s[k_l*EPS + wn*32 + p*16 + nsel]);
            Blo[2*p][0] = t[0]; Blo[2*p][1] = t[1];
            Blo[2*p+1][0] = t[2]; Blo[2*p+1][1] = t[3];
        }
        #pragma unroll
        for (int m = 0; m < 2; m++)
            #pragma unroll
            for (int n = 0; n < 4; n++) {
                mma16816(acc[m][n], Ahi[m], Bhi[n]);
                mma16816(acc[m][n], Ahi[m], Blo[n]);
                mma16816(acc[m][n], Alo[m], Bhi[n]);
            }
    }

    int row_ = lane >> 2;
    int colp = (lane & 3)*2;
    #pragma unroll
    for (int m = 0; m < 2; m++) {
        int ocA = hh*128 + wm*32 + m*16 + row_;
        int ocB = ocA + 8;
        float bA = bias[ocA], bB = bias[ocB];
        #pragma unroll
        for (int n = 0; n < 4; n++) {
            int xo = px0 + wn*32 + n*8 + colp;
            *((float2*)(outb + ((size_t)bi*C4 + ocA)*HW + xo)) =
                make_float2(acc[m][n][0] + bA, acc[m][n][1] + bA);
            *((float2*)(outb + ((size_t)bi*C4 + ocB)*HW + xo)) =
                make_float2(acc[m][n][2] + bB, acc[m][n][3] + bB);
        }
    }
}

// ---------------- static depthwise 3x3, 4px/thread; outputs split hi/lo fp16 ------
__global__ void __launch_bounds__(256) dw_both_kernel(const float* __restrict__ w1,
                                                      const float* __restrict__ b1,
                                                      const float* __restrict__ w2,
                                                      const float* __restrict__ b2) {
    int gate = blockIdx.y;
    const float* inb  = gate ? g_a2 : g_a1;
    __half* outh      = gate ? g_bh2 : g_bh1;
    __half* outl      = gate ? g_bl2 : g_bl1;
    const float* wgt  = gate ? w2 : w1;
    const float* bias = gate ? b2 : b1;

    int g = blockIdx.x * 256 + threadIdx.x;
    int px4   = g % (HW/4);
    int plane = g / (HW/4);
    int ch = plane & (C4 - 1);
    int y  = px4 / (W/4);
    int x0 = (px4 % (W/4)) * 4;

    const float* p = inb + (size_t)plane*HW;
    const float* wp = wgt + ch*9;
    float w[9];
    #pragma unroll
    for (int k = 0; k < 9; k++) w[k] = wp[k];

    float A[3][6];
    #pragma unroll
    for (int kh = 0; kh < 3; kh++) {
        int yy = y + kh - 1;
        if ((unsigned)yy < H) {
            const float* row = p + yy*W;
            float4 m = *((const float4*)(row + x0));
            A[kh][0] = (x0 > 0)      ? row[x0 - 1] : 0.f;
            A[kh][1] = m.x; A[kh][2] = m.y; A[kh][3] = m.z; A[kh][4] = m.w;
            A[kh][5] = (x0 + 4 < W)  ? row[x0 + 4] : 0.f;
        } else {
            #pragma unroll
            for (int j = 0; j < 6; j++) A[kh][j] = 0.f;
        }
    }

    float bv = bias[ch];
    __align__(8) __half hv[4];
    __align__(8) __half lv[4];
    #pragma unroll
    for (int j = 0; j < 4; j++) {
        float s = bv;
        #pragma unroll
        for (int kh = 0; kh < 3; kh++)
            #pragma unroll
            for (int kw = 0; kw < 3; kw++)
                s = fmaf(A[kh][j + kw], w[kh*3 + kw], s);
        split2(s, hv[j], lv[j]);
    }
    size_t off = (size_t)plane*HW + (size_t)y*W + x0;
    *((uint2*)(outh + off)) = *((uint2*)hv);
    *((uint2*)(outl + off)) = *((uint2*)lv);
}

// ---------------- fused BOTH-gate contract, [k][px] B + trans (verified R14) ------
#define CPS 136
__global__ void __launch_bounds__(256, 2) contract_both_kernel(const float* __restrict__ po1_b,
                                                               const float* __restrict__ po2_b,
                                                               float* __restrict__ outbase) {
    __shared__ __align__(16) __half Ahi_s[2][64*24];
    __shared__ __align__(16) __half Alo_s[2][64*24];
    __shared__ __align__(16) __half Bhi_s[2][16*CPS];
    __shared__ __align__(16) __half Blo_s[2][16*CPS];

    int tid = threadIdx.x;
    int lane = tid & 31, wid = tid >> 5;
    int wm = wid & 1, wn = wid >> 1;
    int px0 = blockIdx.x * 128;
    int bi = blockIdx.y;

    float acc[2][2][4][4];
    #pragma unroll
    for (int gg = 0; gg < 2; gg++)
        #pragma unroll
        for (int m = 0; m < 2; m++)
            #pragma unroll
            for (int n = 0; n < 4; n++)
                #pragma unroll
                for (int r = 0; r < 4; r++) acc[gg][m][n][r] = 0.f;

    int ic_l = tid >> 4;
    int n0   = (tid & 15)*8;

    int a_row = (lane & 7) + ((lane >> 3) & 1)*8;
    int a_col = (lane >> 4)*8;
    int k_l  = (lane & 7) + ((lane >> 3) & 1)*8;
    int nsel = ((lane >> 4) & 1)*8;

    for (int ch = 0; ch < 16; ch++) {
        __syncthreads();
        {
            size_t off = ((size_t)(bi*C4 + ch*16 + ic_l))*HW + px0 + n0;
            *((float4*)(Bhi_s[0] + ic_l*CPS + n0)) = *((const float4*)(g_bh1 + off));
            *((float4*)(Blo_s[0] + ic_l*CPS + n0)) = *((const float4*)(g_bl1 + off));
            *((float4*)(Bhi_s[1] + ic_l*CPS + n0)) = *((const float4*)(g_bh2 + off));
            *((float4*)(Blo_s[1] + ic_l*CPS + n0)) = *((const float4*)(g_bl2 + off));
        }
        if (tid < 192) {
            ((float4*)Ahi_s[0])[tid] = ((const float4*)(g_cwhi + ((size_t)(0*16 + ch)*64)*24))[tid];
            ((float4*)Alo_s[0])[tid] = ((const float4*)(g_cwlo + ((size_t)(0*16 + ch)*64)*24))[tid];
            ((float4*)Ahi_s[1])[tid] = ((const float4*)(g_cwhi + ((size_t)(1*16 + ch)*64)*24))[tid];
            ((float4*)Alo_s[1])[tid] = ((const float4*)(g_cwlo + ((size_t)(1*16 + ch)*64)*24))[tid];
        }
        __syncthreads();

        #pragma unroll
        for (int gg = 0; gg < 2; gg++) {
            unsigned Ahi[2][4], Alo[2][4];
            ldsm4(Ahi[0], &Ahi_s[gg][(wm*32 +      a_row)*24 + a_col]);
            ldsm4(Ahi[1], &Ahi_s[gg][(wm*32 + 16 + a_row)*24 + a_col]);
            ldsm4(Alo[0], &Alo_s[gg][(wm*32 +      a_row)*24 + a_col]);
            ldsm4(Alo[1], &Alo_s[gg][(wm*32 + 16 + a_row)*24 + a_col]);
            unsigned Bhi[4][2], Blo[4][2];
            #pragma unroll
            for (int p = 0; p < 2; p++) {
                unsigned t[4];
                ldsm4t(t, &Bhi_s[gg][k_l*CPS + wn*32 + p*16 + nsel]);
                Bhi[2*p][0] = t[0]; Bhi[2*p][1] = t[1];
                Bhi[2*p+1][0] = t[2]; Bhi[2*p+1][1] = t[3];
                ldsm4t(t, &Blo_s[gg][k_l*CPS + wn*32 + p*16 + nsel]);
                Blo[2*p][0] = t[0]; Blo[2*p][1] = t[1];
                Blo[2*p+1][0] = t[2]; Blo[2*p+1][1] = t[3];
            }
            #pragma unroll
            for (int m = 0; m < 2; m++)
                #pragma unroll
                for (int n = 0; n < 4; n++) {
                    mma16816(acc[gg][m][n], Ahi[m], Bhi[n]);
                    mma16816(acc[gg][m][n], Ahi[m], Blo[n]);
                    mma16816(acc[gg][m][n], Alo[m], Bhi[n]);
                }
        }
    }

    int row_ = lane >> 2;
    int colp = (lane & 3)*2;
    #pragma unroll
    for (int m = 0; m < 2; m++) {
        int ocA = wm*32 + m*16 + row_;
        int ocB = ocA + 8;
        float b1A = po1_b[ocA], b1B = po1_b[ocB];
        float b2A = po2_b[ocA], b2B = po2_b[ocB];
        #pragma unroll
        for (int n = 0; n < 4; n++) {
            int xo = px0 + wn*32 + n*8 + colp;
            float g1A0 = 1.0f / (1.0f + __expf(-(acc[0][m][n][0] + b1A)));
            float g1A1 = 1.0f / (1.0f + __expf(-(acc[0][m][n][1] + b1A)));
            float g1B0 = 1.0f / (1.0f + __expf(-(acc[0][m][n][2] + b1B)));
            float g1B1 = 1.0f / (1.0f + __expf(-(acc[0][m][n][3] + b1B)));
            float g2A0 = 1.0f / (1.0f + __expf(-(acc[1][m][n][0] + b2A)));
            float g2A1 = 1.0f / (1.0f + __expf(-(acc[1][m][n][1] + b2A)));
            float g2B0 = 1.0f / (1.0f + __expf(-(acc[1][m][n][2] + b2B)));
            float g2B1 = 1.0f / (1.0f + __expf(-(acc[1][m][n][3] + b2B)));
            float2 f1A = *((const float2*)(g_fusion + ((size_t)bi*C2 + ocA)*HW + xo));
            float2 f2A = *((const float2*)(g_fusion + ((size_t)bi*C2 + C + ocA)*HW + xo));
            float2 f1B = *((const float2*)(g_fusion + ((size_t)bi*C2 + ocB)*HW + xo));
            float2 f2B = *((const float2*)(g_fusion + ((size_t)bi*C2 + C + ocB)*HW + xo));
            *((float2*)(outbase + (size_t)bi*TCHW + (size_t)ocA*HW + xo)) =
                make_float2(f1A.x*g1A0 + f2A.x*g2A0, f1A.y*g1A1 + f2A.y*g2A1);
            *((float2*)(outbase + (size_t)bi*TCHW + (size_t)ocB*HW + xo)) =
                make_float2(f1B.x*g1B0 + f2B.x*g2B0, f1B.y*g1B1 + f2B.y*g2B1);
        }
    }
}

// ---------------- launcher -------------------------------------------------------
extern "C" void kernel_launch(void* const* d_in, const int* in_sizes, int n_in,
                              void* d_out, int out_size) {
    (void)in_sizes; (void)n_in; (void)out_size;
    const float* feature   = (const float*)d_in[0];
    const float* kc_w1     = (const float*)d_in[1];
    const float* kc_gamma  = (const float*)d_in[2];
    const float* kc_beta   = (const float*)d_in[3];
    const float* kc_mean   = (const float*)d_in[4];
    const float* kc_var    = (const float*)d_in[5];
    const float* kc_w2     = (const float*)d_in[6];
    const float* kc_b2     = (const float*)d_in[7];
    const float* kc_bias   = (const float*)d_in[8];
    const float* conv1_w   = (const float*)d_in[9];
    const float* conv1_b   = (const float*)d_in[10];
    const float* pi1_w     = (const float*)d_in[11];
    const float* pi1_b     = (const float*)d_in[12];
    const float* dw1_w     = (const float*)d_in[13];
    const float* dw1_b     = (const float*)d_in[14];
    const float* po1_w     = (const float*)d_in[15];
    const float* po1_b     = (const float*)d_in[16];
    const float* pi2_w     = (const float*)d_in[17];
    const float* pi2_b     = (const float*)d_in[18];
    const float* dw2_w     = (const float*)d_in[19];
    const float* dw2_b     = (const float*)d_in[20];
    const float* po2_w     = (const float*)d_in[21];
    const float* po2_b     = (const float*)d_in[22];
    float* out = (float*)d_out;

    // out[:, T-1] = feature[:, T-1]
    for (int bi = 0; bi < BATCH; bi++) {
        size_t off = ((size_t)bi*T + (T-1)) * CHW;
        cudaMemcpyAsync(out + off, feature + off, (size_t)CHW*sizeof(float),
                        cudaMemcpyDeviceToDevice, 0);
    }

    // one-time: weight splits + ALL per-step dynamic weights
    prep_w_kernel<<<(9*8*128*16 + 255)/256, 256>>>(conv1_w);
    prep_pw_kernel<<<(2*4*256*16 + 255)/256, 256>>>(pi1_w, pi2_w);
    prep_cw_kernel<<<(2*16*64*16 + 255)/256, 256>>>(po1_w, po2_w);
    pool_all_kernel<<<(T-1)*BATCH*C, 256>>>(feature);
    mlp_all_kernel<<<T-1, 128>>>(kc_w1, kc_gamma, kc_beta, kc_mean, kc_var, kc_w2, kc_b2);

    for (int i = T - 2; i >= 0; --i) {
        const float* xbase = feature + (size_t)i*CHW;
        const float* ybase = out + (size_t)(i+1)*CHW;

        dyndw_kernel<<<(BATCH*CHW/4)/256, 256>>>(ybase, kc_bias, i);
        conv_mma_kernel<<<dim3(W/32, H/4, BATCH), 512>>>(xbase, conv1_b);
        expand_mma_kernel<<<dim3(HW/64, 4, BATCH), 256>>>(pi1_b, pi2_b);
        dw_both_kernel<<<dim3((BATCH*C4*HW/4)/256, 2), 256>>>(dw1_w, dw1_b, dw2_w, dw2_b);
        contract_both_kernel<<<dim3(HW/128, BATCH), 256>>>(po1_b, po2_b, out + (size_t)i*CHW);
    }
}

// round 16
// speedup vs baseline: 9.7710x; 1.0001x over previous
#include <cuda_runtime.h>
#include <cuda_fp16.h>
#include <math.h>

#define BATCH 2
#define T 8
#define C 64
#define R 16
#define H 160
#define W 160
#define HW (H*W)            // 25600
#define CHW (C*HW)          // 1,638,400
#define TCHW (T*CHW)
#define C2 128
#define C4 256

typedef unsigned long long ull;

// ---------------- scratch (device globals; referenced ONLY from device code) ----
__device__ float g_pool_all[(T-1)*BATCH*C];
__device__ float g_wd_all[(T-1)*BATCH*C*9];
__device__ float g_fp[BATCH*CHW];
__device__ float g_fusion[(size_t)BATCH*C2*HW];
__device__ float g_a1[(size_t)BATCH*C4*HW];
__device__ float g_a2[(size_t)BATCH*C4*HW];
__device__ __half g_bh1[(size_t)BATCH*C4*HW];
__device__ __half g_bl1[(size_t)BATCH*C4*HW];
__device__ __half g_bh2[(size_t)BATCH*C4*HW];
__device__ __half g_bl2[(size_t)BATCH*C4*HW];
// conv weights pre-split fp16 hi/lo, ldmatrix-ready [tap][ch8][oc128][24]
__device__ __half g_whi[9*8*128*24];
__device__ __half g_wlo[9*8*128*24];
// expand weights [gate][ch4][oc256][24]
__device__ __half g_pwhi[2*4*256*24];
__device__ __half g_pwlo[2*4*256*24];
// contract weights [gate][ch16][oc64][24]
__device__ __half g_cwhi[2*16*64*24];
__device__ __half g_cwlo[2*16*64*24];

// ---------------- mma helpers -----------------------------------------------------
__device__ __forceinline__ void ldsm4(unsigned* r, const void* p) {
    unsigned s = (unsigned)__cvta_generic_to_shared(p);
    asm volatile("ldmatrix.sync.aligned.m8n8.x4.shared.b16 {%0,%1,%2,%3}, [%4];"
        : "=r"(r[0]), "=r"(r[1]), "=r"(r[2]), "=r"(r[3]) : "r"(s));
}
__device__ __forceinline__ void ldsm4t(unsigned* r, const void* p) {
    unsigned s = (unsigned)__cvta_generic_to_shared(p);
    asm volatile("ldmatrix.sync.aligned.m8n8.x4.trans.shared.b16 {%0,%1,%2,%3}, [%4];"
        : "=r"(r[0]), "=r"(r[1]), "=r"(r[2]), "=r"(r[3]) : "r"(s));
}
__device__ __forceinline__ void mma16816(float* d, const unsigned* a, const unsigned* b) {
    asm volatile("mma.sync.aligned.m16n8k16.row.col.f32.f16.f16.f32 "
        "{%0,%1,%2,%3},{%4,%5,%6,%7},{%8,%9},{%0,%1,%2,%3};"
        : "+f"(d[0]), "+f"(d[1]), "+f"(d[2]), "+f"(d[3])
        : "r"(a[0]), "r"(a[1]), "r"(a[2]), "r"(a[3]), "r"(b[0]), "r"(b[1]));
}
__device__ __forceinline__ void split2(float v, __half& h, __half& l) {
    h = __float2half_rn(v);
    l = __float2half_rn(v - __half2float(h));
}

// ---------------- pool for ALL steps (float4 vectorized) ---------------------------
__global__ void pool_all_kernel(const float* __restrict__ feature) {
    int g = blockIdx.x;
    int step = g / (BATCH*C);
    int rem  = g % (BATCH*C);
    int bi = rem >> 6, c = rem & 63;
    const float4* p = (const float4*)(feature + (size_t)bi*TCHW + (size_t)step*CHW + (size_t)c*HW);
    float s = 0.f;
    for (int i = threadIdx.x; i < HW/4; i += 256) {
        float4 v = p[i];
        s += (v.x + v.y) + (v.z + v.w);
    }
    __shared__ float red[8];
    #pragma unroll
    for (int o = 16; o; o >>= 1) s += __shfl_down_sync(0xffffffffu, s, o);
    if ((threadIdx.x & 31) == 0) red[threadIdx.x >> 5] = s;
    __syncthreads();
    if (threadIdx.x == 0) {
        float t = 0.f;
        #pragma unroll
        for (int k = 0; k < 8; k++) t += red[k];
        g_pool_all[g] = t * (1.0f / (float)HW);
    }
}

// ---------------- tiny MLP for ALL steps ------------------------------------------
__global__ void mlp_all_kernel(const float* __restrict__ w1,
                               const float* __restrict__ gamma,
                               const float* __restrict__ beta,
                               const float* __restrict__ mean,
                               const float* __restrict__ var,
                               const float* __restrict__ w2,
                               const float* __restrict__ b2) {
    __shared__ float zs[BATCH*R];
    int step = blockIdx.x;
    int tid = threadIdx.x;
    const float* pool = g_pool_all + step*BATCH*C;
    float* wd = g_wd_all + step*BATCH*C*9;
    if (tid < BATCH*R) {
        int bi = tid / R, j = tid % R;
        float s = 0.f;
        for (int c = 0; c < C; c++) s = fmaf(pool[bi*C + c], w1[j*C + c], s);
        s = (s - mean[j]) * rsqrtf(var[j] + 1e-5f) * gamma[j] + beta[j];
        zs[tid] = fmaxf(s, 0.f);
    }
    __syncthreads();
    for (int o = tid; o < BATCH*C*9; o += blockDim.x) {
        int bi = o / (C*9), oo = o % (C*9);
        float s = b2[oo];
        #pragma unroll
        for (int j = 0; j < R; j++) s = fmaf(zs[bi*R + j], w2[oo*R + j], s);
        wd[o] = s;
    }
}

// ---------------- dynamic depthwise 3x3, 4px/thread (verified R15) ----------------
__global__ void __launch_bounds__(256) dyndw_kernel(const float* __restrict__ ybase,
                                                    const float* __restrict__ kc_bias, int step) {
    int g = blockIdx.x * 256 + threadIdx.x;
    int px4   = g % (HW/4);
    int plane = g / (HW/4);
    int c = plane & 63, bi = plane >> 6;
    int y  = px4 / (W/4);
    int x0 = (px4 % (W/4)) * 4;

    const float* p = ybase + (size_t)bi*TCHW + (size_t)c*HW;
    const float* wp = g_wd_all + step*BATCH*C*9 + plane*9;
    float w[9];
    #pragma unroll
    for (int k = 0; k < 9; k++) w[k] = wp[k];

    float A[3][6];
    #pragma unroll
    for (int kh = 0; kh < 3; kh++) {
        int yy = y + kh - 1;
        if ((unsigned)yy < H) {
            const float* row = p + yy*W;
            float4 m = *((const float4*)(row + x0));
            A[kh][0] = (x0 > 0)      ? row[x0 - 1] : 0.f;
            A[kh][1] = m.x; A[kh][2] = m.y; A[kh][3] = m.z; A[kh][4] = m.w;
            A[kh][5] = (x0 + 4 < W)  ? row[x0 + 4] : 0.f;
        } else {
            #pragma unroll
            for (int j = 0; j < 6; j++) A[kh][j] = 0.f;
        }
    }

    float bv = kc_bias[c];
    float r[4];
    #pragma unroll
    for (int j = 0; j < 4; j++) {
        float s = bv;
        #pragma unroll
        for (int kh = 0; kh < 3; kh++)
            #pragma unroll
            for (int kw = 0; kw < 3; kw++)
                s = fmaf(A[kh][j + kw], w[kh*3 + kw], s);
        r[j] = s;
    }
    *((float4*)(g_fp + (size_t)plane*HW + (size_t)y*W + x0)) = make_float4(r[0], r[1], r[2], r[3]);
}

// ---------------- weight split preps (once per launch) ---------------------------
__global__ void prep_w_kernel(const float* __restrict__ conv1_w) {
    int idx = blockIdx.x * 256 + threadIdx.x;
    if (idx >= 9*8*128*16) return;
    int k   = idx & 15;
    int oc  = (idx >> 4) & 127;
    int ch  = (idx >> 11) & 7;
    int tap = idx >> 14;
    int ic = ch*16 + k;
    float v = conv1_w[((size_t)oc*C2 + ic)*9 + tap];
    __half h, l; split2(v, h, l);
    size_t o = ((size_t)(tap*8 + ch)*128 + oc)*24 + k;
    g_whi[o] = h; g_wlo[o] = l;
}
__global__ void prep_pw_kernel(const float* __restrict__ pi1_w, const float* __restrict__ pi2_w) {
    int idx = blockIdx.x * 256 + threadIdx.x;
    if (idx >= 2*4*256*16) return;
    int k    = idx & 15;
    int oc   = (idx >> 4) & 255;
    int ch   = (idx >> 12) & 3;
    int gate = idx >> 14;
    const float* w = gate ? pi2_w : pi1_w;
    float v = w[(size_t)oc*C + ch*16 + k];
    __half h, l; split2(v, h, l);
    size_t o = ((size_t)(gate*4 + ch)*256 + oc)*24 + k;
    g_pwhi[o] = h; g_pwlo[o] = l;
}
__global__ void prep_cw_kernel(const float* __restrict__ po1_w, const float* __restrict__ po2_w) {
    int idx = blockIdx.x * 256 + threadIdx.x;
    if (idx >= 2*16*64*16) return;
    int k    = idx & 15;
    int oc   = (idx >> 4) & 63;
    int ch   = (idx >> 10) & 15;
    int gate = idx >> 14;
    const float* w = gate ? po2_w : po1_w;
    float v = w[(size_t)oc*C4 + ch*16 + k];
    __half h, l; split2(v, h, l);
    size_t o = ((size_t)(gate*16 + ch)*64 + oc)*24 + k;
    g_cwhi[o] = h; g_cwlo[o] = l;
}

// ---------------- conv3x3 via fp16-split mma, all-taps W preload ------------------
// 512 thr, 128oc x 128px tile (4y x 32x). Halo 204 px-rows x 16 k, stride 24.
// Per ch: ONE X stage + ONE W stage (all 9 taps), then 9 uninterrupted tap mmas.
// Dynamic smem: Xhi 4896 + Xlo 4896 + Whi 27648 + Wlo 27648 halves = 130,176 B.
#define CONV_SMEM ((204*24*2 + 9*3072*2)*2)
__global__ void __launch_bounds__(512, 1) conv_mma_kernel(const float* __restrict__ xbase,
                                                          const float* __restrict__ bias) {
    extern __shared__ __align__(16) __half sm[];
    __half* Xhi_s = sm;                       // 204*24
    __half* Xlo_s = sm + 204*24;              // +4896
    __half* Whi_s = sm + 2*204*24;            // 9*3072
    __half* Wlo_s = sm + 2*204*24 + 9*3072;

    int tid = threadIdx.x;
    int lane = tid & 31, wid = tid >> 5;
    int wm = wid & 3, wn = wid >> 2;
    int x0 = blockIdx.x * 32;
    int y0 = blockIdx.y * 4;
    int bi = blockIdx.z;

    const float* xp  = xbase + (size_t)bi*TCHW;
    const float* fpp = g_fp  + (size_t)bi*CHW;

    float acc[2][4][4];
    #pragma unroll
    for (int m = 0; m < 2; m++)
        #pragma unroll
        for (int n = 0; n < 4; n++)
            #pragma unroll
            for (int r = 0; r < 4; r++) acc[m][n][r] = 0.f;

    int ic_l = tid >> 5;
    int rg   = tid & 31;
    int hgoff[7]; bool hval[7]; int hsm[7];
    #pragma unroll
    for (int j = 0; j < 7; j++) {
        int r = rg + j*32;
        bool ok = r < 204;
        int ry = r / 34, rx = r - ry*34;
        int gy = y0 + ry - 1, gx = x0 + rx - 1;
        bool v = ok && ((unsigned)gy < H) && ((unsigned)gx < W);
        hval[j] = v;
        hgoff[j] = v ? gy*W + gx : 0;
        hsm[j] = ok ? (r*24 + ic_l) : -1;
    }

    int a_row = (lane & 7) + ((lane >> 3) & 1)*8;
    int a_col = (lane >> 4)*8;
    int b_n   = (lane & 7) + ((lane >> 4) & 1)*8;
    int b_col = ((lane >> 3) & 1)*8;
    const char* bPtrHi[2];
    const char* bPtrLo[2];
    #pragma unroll
    for (int p = 0; p < 2; p++) {
        int n = wn*32 + p*16 + b_n;
        int row0 = ((n >> 5) + 1)*34 + (n & 31) + 1;
        bPtrHi[p] = (const char*)Xhi_s + row0*48 + b_col*2;
        bPtrLo[p] = (const char*)Xlo_s + row0*48 + b_col*2;
    }

    for (int ch = 0; ch < 8; ch++) {
        __syncthreads();
        // ---- stage X halo chunk (split once per ch)
        {
            int ic = ch*16 + ic_l;
            const float* pl = (ic < C) ? (xp + (size_t)ic*HW) : (fpp + (size_t)(ic - C)*HW);
            #pragma unroll
            for (int j = 0; j < 7; j++) {
                if (hsm[j] >= 0) {
                    float v = hval[j] ? __ldg(pl + hgoff[j]) : 0.f;
                    __half h, l; split2(v, h, l);
                    Xhi_s[hsm[j]] = h;
                    Xlo_s[hsm[j]] = l;
                }
            }
        }
        // ---- stage ALL 9 taps of W(ch): 3456 float4 per buf, flat over 512 thr
        {
            #pragma unroll
            for (int i = 0; i < 7; i++) {
                int flat = tid + 512*i;
                if (flat < 3456) {
                    int t = flat / 384;
                    int e = flat - t*384;
                    ((float4*)(Whi_s + t*3072))[e] = ((const float4*)(g_whi + (size_t)(t*8 + ch)*3072))[e];
                    ((float4*)(Wlo_s + t*3072))[e] = ((const float4*)(g_wlo + (size_t)(t*8 + ch)*3072))[e];
                }
            }
        }
        __syncthreads();

        #pragma unroll
        for (int tap = 0; tap < 9; tap++) {
            int dy = tap/3 - 1, dx = tap%3 - 1;
            int tapoff = (dy*34 + dx)*48;
            const __half* Wb_hi = Whi_s + tap*3072;
            const __half* Wb_lo = Wlo_s + tap*3072;

            unsigned Ahi[2][4], Alo[2][4];
            ldsm4(Ahi[0], &Wb_hi[(wm*32 +      a_row)*24 + a_col]);
            ldsm4(Ahi[1], &Wb_hi[(wm*32 + 16 + a_row)*24 + a_col]);
            ldsm4(Alo[0], &Wb_lo[(wm*32 +      a_row)*24 + a_col]);
            ldsm4(Alo[1], &Wb_lo[(wm*32 + 16 + a_row)*24 + a_col]);
            unsigned Bhi[4][2], Blo[4][2];
            #pragma unroll
            for (int p = 0; p < 2; p++) {
                unsigned t[4];
                ldsm4(t, bPtrHi[p] + tapoff);
                Bhi[2*p][0] = t[0]; Bhi[2*p][1] = t[1];
                Bhi[2*p+1][0] = t[2]; Bhi[2*p+1][1] = t[3];
                ldsm4(t, bPtrLo[p] + tapoff);
                Blo[2*p][0] = t[0]; Blo[2*p][1] = t[1];
                Blo[2*p+1][0] = t[2]; Blo[2*p+1][1] = t[3];
            }
            #pragma unroll
            for (int m = 0; m < 2; m++)
                #pragma unroll
                for (int n = 0; n < 4; n++) {
                    mma16816(acc[m][n], Ahi[m], Bhi[n]);
                    mma16816(acc[m][n], Ahi[m], Blo[n]);
                    mma16816(acc[m][n], Alo[m], Bhi[n]);
                }
        }
    }

    int row_ = lane >> 2;
    int colp = (lane & 3)*2;
    int yo = y0 + wn;
    #pragma unroll
    for (int m = 0; m < 2; m++) {
        int ocA = wm*32 + m*16 + row_;
        int ocB = ocA + 8;
        float bA = bias[ocA], bB = bias[ocB];
        #pragma unroll
        for (int n = 0; n < 4; n++) {
            int xo = x0 + n*8 + colp;
            float v0 = acc[m][n][0] + bA, v1 = acc[m][n][1] + bA;
            float v2 = acc[m][n][2] + bB, v3 = acc[m][n][3] + bB;
            v0 = (v0 > 0.f) ? v0 : 0.1f*v0;
            v1 = (v1 > 0.f) ? v1 : 0.1f*v1;
            v2 = (v2 > 0.f) ? v2 : 0.1f*v2;
            v3 = (v3 > 0.f) ? v3 : 0.1f*v3;
            *((float2*)(g_fusion + ((size_t)bi*C2 + ocA)*HW + (size_t)yo*W + xo)) = make_float2(v0, v1);
            *((float2*)(g_fusion + ((size_t)bi*C2 + ocB)*HW + (size_t)yo*W + xo)) = make_float2(v2, v3);
        }
    }
}

// ---------------- expand via mma, [k][px] X + trans (verified R14): K=64 ----------
#define EPS 72
__global__ void __launch_bounds__(256, 2) expand_mma_kernel(const float* __restrict__ b1,
                                                            const float* __restrict__ b2) {
    __shared__ __align__(16) __half Whi_s[128*24];
    __shared__ __align__(16) __half Wlo_s[128*24];
    __shared__ __align__(16) __half Xhi_s[16*EPS];
    __shared__ __align__(16) __half Xlo_s[16*EPS];

    int tid = threadIdx.x;
    int lane = tid & 31, wid = tid >> 5;
    int wm = wid & 3, wn = wid >> 2;
    int px0 = blockIdx.x * 64;
    int gy  = blockIdx.y;
    int gate = gy >> 1, hh = gy & 1;
    int bi = blockIdx.z;

    const float* bias = gate ? b2 : b1;
    float* outb       = gate ? g_a2 : g_a1;
    int halfoff       = gate ? C : 0;

    float acc[2][4][4];
    #pragma unroll
    for (int m = 0; m < 2; m++)
        #pragma unroll
        for (int n = 0; n < 4; n++)
            #pragma unroll
            for (int r = 0; r < 4; r++) acc[m][n][r] = 0.f;

    int ic_l = tid >> 4;
    int n0   = (tid & 15)*4;

    int a_row = (lane & 7) + ((lane >> 3) & 1)*8;
    int a_col = (lane >> 4)*8;
    int k_l  = (lane & 7) + ((lane >> 3) & 1)*8;
    int nsel = ((lane >> 4) & 1)*8;

    #pragma unroll
    for (int ch = 0; ch < 4; ch++) {
        __syncthreads();
        {
            const float* src = g_fusion + ((size_t)(bi*C2 + halfoff + ch*16 + ic_l))*HW + px0 + n0;
            float4 v = *((const float4*)src);
            float vv[4] = {v.x, v.y, v.z, v.w};
            __align__(8) __half hv[4], lv[4];
            #pragma unroll
            for (int j = 0; j < 4; j++) split2(vv[j], hv[j], lv[j]);
            *((uint2*)(Xhi_s + ic_l*EPS + n0)) = *((uint2*)hv);
            *((uint2*)(Xlo_s + ic_l*EPS + n0)) = *((uint2*)lv);
        }
        {
            const float4* sH = (const float4*)(g_pwhi + ((size_t)(gate*4 + ch)*256 + hh*128)*24);
            const float4* sL = (const float4*)(g_pwlo + ((size_t)(gate*4 + ch)*256 + hh*128)*24);
            ((float4*)Whi_s)[tid] = sH[tid];
            ((float4*)Wlo_s)[tid] = sL[tid];
            if (tid < 128) {
                ((float4*)Whi_s)[256 + tid] = sH[256 + tid];
                ((float4*)Wlo_s)[256 + tid] = sL[256 + tid];
            }
        }
        __syncthreads();

        unsigned Ahi[2][4], Alo[2][4];
        ldsm4(Ahi[0], &Whi_s[(wm*32 +      a_row)*24 + a_col]);
        ldsm4(Ahi[1], &Whi_s[(wm*32 + 16 + a_row)*24 + a_col]);
        ldsm4(Alo[0], &Wlo_s[(wm*32 +      a_row)*24 + a_col]);
        ldsm4(Alo[1], &Wlo_s[(wm*32 + 16 + a_row)*24 + a_col]);
        unsigned Bhi[4][2], Blo[4][2];
        #pragma unroll
        for (int p = 0; p < 2; p++) {
            unsigned t[4];
            ldsm4t(t, &Xhi_s[k_l*EPS + wn*32 + p*16 + nsel]);
            Bhi[2*p][0] = t[0]; Bhi[2*p][1] = t[1];
            Bhi[2*p+1][0] = t[2]; Bhi[2*p+1][1] = t[3];
            ldsm4t(t, &Xlo_s[k_l*EPS + wn*32 + p*16 + nsel]);
            Blo[2*p][0] = t[0]; Blo[2*p][1] = t[1];
            Blo[2*p+1][0] = t[2]; Blo[2*p+1][1] = t[3];
        }
        #pragma unroll
        for (int m = 0; m < 2; m++)
            #pragma unroll
            for (int n = 0; n < 4; n++) {
                mma16816(acc[m][n], Ahi[m], Bhi[n]);
                mma16816(acc[m][n], Ahi[m], Blo[n]);
                mma16816(acc[m][n], Alo[m], Bhi[n]);
            }
    }

    int row_ = lane >> 2;
    int colp = (lane & 3)*2;
    #pragma unroll
    for (int m = 0; m < 2; m++) {
        int ocA = hh*128 + wm*32 + m*16 + row_;
        int ocB = ocA + 8;
        float bA = bias[ocA], bB = bias[ocB];
        #pragma unroll
        for (int n = 0; n < 4; n++) {
            int xo = px0 + wn*32 + n*8 + colp;
            *((float2*)(outb + ((size_t)bi*C4 + ocA)*HW + xo)) =
                make_float2(acc[m][n][0] + bA, acc[m][n][1] + bA);
            *((float2*)(outb + ((size_t)bi*C4 + ocB)*HW + xo)) =
                make_float2(acc[m][n][2] + bB, acc[m][n][3] + bB);
        }
    }
}

// ---------------- static depthwise 3x3, 4px/thread; outputs split hi/lo fp16 ------
__global__ void __launch_bounds__(256) dw_both_kernel(const float* __restrict__ w1,
                                                      const float* __restrict__ b1,
                                                      const float* __restrict__ w2,
                                                      const float* __restrict__ b2) {
    int gate = blockIdx.y;
    const float* inb  = gate ? g_a2 : g_a1;
    __half* outh      = gate ? g_bh2 : g_bh1;
    __half* outl      = gate ? g_bl2 : g_bl1;
    const float* wgt  = gate ? w2 : w1;
    const float* bias = gate ? b2 : b1;

    int g = blockIdx.x * 256 + threadIdx.x;
    int px4   = g % (HW/4);
    int plane = g / (HW/4);
    int ch = plane & (C4 - 1);
    int y  = px4 / (W/4);
    int x0 = (px4 % (W/4)) * 4;

    const float* p = inb + (size_t)plane*HW;
    const float* wp = wgt + ch*9;
    float w[9];
    #pragma unroll
    for (int k = 0; k < 9; k++) w[k] = wp[k];

    float A[3][6];
    #pragma unroll
    for (int kh = 0; kh < 3; kh++) {
        int yy = y + kh - 1;
        if ((unsigned)yy < H) {
            const float* row = p + yy*W;
            float4 m = *((const float4*)(row + x0));
            A[kh][0] = (x0 > 0)      ? row[x0 - 1] : 0.f;
            A[kh][1] = m.x; A[kh][2] = m.y; A[kh][3] = m.z; A[kh][4] = m.w;
            A[kh][5] = (x0 + 4 < W)  ? row[x0 + 4] : 0.f;
        } else {
            #pragma unroll
            for (int j = 0; j < 6; j++) A[kh][j] = 0.f;
        }
    }

    float bv = bias[ch];
    __align__(8) __half hv[4];
    __align__(8) __half lv[4];
    #pragma unroll
    for (int j = 0; j < 4; j++) {
        float s = bv;
        #pragma unroll
        for (int kh = 0; kh < 3; kh++)
            #pragma unroll
            for (int kw = 0; kw < 3; kw++)
                s = fmaf(A[kh][j + kw], w[kh*3 + kw], s);
        split2(s, hv[j], lv[j]);
    }
    size_t off = (size_t)plane*HW + (size_t)y*W + x0;
    *((uint2*)(outh + off)) = *((uint2*)hv);
    *((uint2*)(outl + off)) = *((uint2*)lv);
}

// ---------------- fused BOTH-gate contract, [k][px] B + trans (verified R14) ------
#define CPS 136
__global__ void __launch_bounds__(256, 2) contract_both_kernel(const float* __restrict__ po1_b,
                                                               const float* __restrict__ po2_b,
                                                               float* __restrict__ outbase) {
    __shared__ __align__(16) __half Ahi_s[2][64*24];
    __shared__ __align__(16) __half Alo_s[2][64*24];
    __shared__ __align__(16) __half Bhi_s[2][16*CPS];
    __shared__ __align__(16) __half Blo_s[2][16*CPS];

    int tid = threadIdx.x;
    int lane = tid & 31, wid = tid >> 5;
    int wm = wid & 1, wn = wid >> 1;
    int px0 = blockIdx.x * 128;
    int bi = blockIdx.y;

    float acc[2][2][4][4];
    #pragma unroll
    for (int gg = 0; gg < 2; gg++)
        #pragma unroll
        for (int m = 0; m < 2; m++)
            #pragma unroll
            for (int n = 0; n < 4; n++)
                #pragma unroll
                for (int r = 0; r < 4; r++) acc[gg][m][n][r] = 0.f;

    int ic_l = tid >> 4;
    int n0   = (tid & 15)*8;

    int a_row = (lane & 7) + ((lane >> 3) & 1)*8;
    int a_col = (lane >> 4)*8;
    int k_l  = (lane & 7) + ((lane >> 3) & 1)*8;
    int nsel = ((lane >> 4) & 1)*8;

    for (int ch = 0; ch < 16; ch++) {
        __syncthreads();
        {
            size_t off = ((size_t)(bi*C4 + ch*16 + ic_l))*HW + px0 + n0;
            *((float4*)(Bhi_s[0] + ic_l*CPS + n0)) = *((const float4*)(g_bh1 + off));
            *((float4*)(Blo_s[0] + ic_l*CPS + n0)) = *((const float4*)(g_bl1 + off));
            *((float4*)(Bhi_s[1] + ic_l*CPS + n0)) = *((const float4*)(g_bh2 + off));
            *((float4*)(Blo_s[1] + ic_l*CPS + n0)) = *((const float4*)(g_bl2 + off));
        }
        if (tid < 192) {
            ((float4*)Ahi_s[0])[tid] = ((const float4*)(g_cwhi + ((size_t)(0*16 + ch)*64)*24))[tid];
            ((float4*)Alo_s[0])[tid] = ((const float4*)(g_cwlo + ((size_t)(0*16 + ch)*64)*24))[tid];
            ((float4*)Ahi_s[1])[tid] = ((const float4*)(g_cwhi + ((size_t)(1*16 + ch)*64)*24))[tid];
            ((float4*)Alo_s[1])[tid] = ((const float4*)(g_cwlo + ((size_t)(1*16 + ch)*64)*24))[tid];
        }
        __syncthreads();

        #pragma unroll
        for (int gg = 0; gg < 2; gg++) {
            unsigned Ahi[2][4], Alo[2][4];
            ldsm4(Ahi[0], &Ahi_s[gg][(wm*32 +      a_row)*24 + a_col]);
            ldsm4(Ahi[1], &Ahi_s[gg][(wm*32 + 16 + a_row)*24 + a_col]);
            ldsm4(Alo[0], &Alo_s[gg][(wm*32 +      a_row)*24 + a_col]);
            ldsm4(Alo[1], &Alo_s[gg][(wm*32 + 16 + a_row)*24 + a_col]);
            unsigned Bhi[4][2], Blo[4][2];
            #pragma unroll
            for (int p = 0; p < 2; p++) {
                unsigned t[4];
                ldsm4t(t, &Bhi_s[gg][k_l*CPS + wn*32 + p*16 + nsel]);
                Bhi[2*p][0] = t[0]; Bhi[2*p][1] = t[1];
                Bhi[2*p+1][0] = t[2]; Bhi[2*p+1][1] = t[3];
                ldsm4t(t, &Blo_s[gg][k_l*CPS + wn*32 + p*16 + nsel]);
                Blo[2*p][0] = t[0]; Blo[2*p][1] = t[1];
                Blo[2*p+1][0] = t[2]; Blo[2*p+1][1] = t[3];
            }
            #pragma unroll
            for (int m = 0; m < 2; m++)
                #pragma unroll
                for (int n = 0; n < 4; n++) {
                    mma16816(acc[gg][m][n], Ahi[m], Bhi[n]);
                    mma16816(acc[gg][m][n], Ahi[m], Blo[n]);
                    mma16816(acc[gg][m][n], Alo[m], Bhi[n]);
                }
        }
    }

    int row_ = lane >> 2;
    int colp = (lane & 3)*2;
    #pragma unroll
    for (int m = 0; m < 2; m++) {
        int ocA = wm*32 + m*16 + row_;
        int ocB = ocA + 8;
        float b1A = po1_b[ocA], b1B = po1_b[ocB];
        float b2A = po2_b[ocA], b2B = po2_b[ocB];
        #pragma unroll
        for (int n = 0; n < 4; n++) {
            int xo = px0 + wn*32 + n*8 + colp;
            float g1A0 = 1.0f / (1.0f + __expf(-(acc[0][m][n][0] + b1A)));
            float g1A1 = 1.0f / (1.0f + __expf(-(acc[0][m][n][1] + b1A)));
            float g1B0 = 1.0f / (1.0f + __expf(-(acc[0][m][n][2] + b1B)));
            float g1B1 = 1.0f / (1.0f + __expf(-(acc[0][m][n][3] + b1B)));
            float g2A0 = 1.0f / (1.0f + __expf(-(acc[1][m][n][0] + b2A)));
            float g2A1 = 1.0f / (1.0f + __expf(-(acc[1][m][n][1] + b2A)));
            float g2B0 = 1.0f / (1.0f + __expf(-(acc[1][m][n][2] + b2B)));
            float g2B1 = 1.0f / (1.0f + __expf(-(acc[1][m][n][3] + b2B)));
            float2 f1A = *((const float2*)(g_fusion + ((size_t)bi*C2 + ocA)*HW + xo));
            float2 f2A = *((const float2*)(g_fusion + ((size_t)bi*C2 + C + ocA)*HW + xo));
            float2 f1B = *((const float2*)(g_fusion + ((size_t)bi*C2 + ocB)*HW + xo));
            float2 f2B = *((const float2*)(g_fusion + ((size_t)bi*C2 + C + ocB)*HW + xo));
            *((float2*)(outbase + (size_t)bi*TCHW + (size_t)ocA*HW + xo)) =
                make_float2(f1A.x*g1A0 + f2A.x*g2A0, f1A.y*g1A1 + f2A.y*g2A1);
            *((float2*)(outbase + (size_t)bi*TCHW + (size_t)ocB*HW + xo)) =
                make_float2(f1B.x*g1B0 + f2B.x*g2B0, f1B.y*g1B1 + f2B.y*g2B1);
        }
    }
}

// ---------------- launcher -------------------------------------------------------
extern "C" void kernel_launch(void* const* d_in, const int* in_sizes, int n_in,
                              void* d_out, int out_size) {
    (void)in_sizes; (void)n_in; (void)out_size;
    const float* feature   = (const float*)d_in[0];
    const float* kc_w1     = (const float*)d_in[1];
    const float* kc_gamma  = (const float*)d_in[2];
    const float* kc_beta   = (const float*)d_in[3];
    const float* kc_mean   = (const float*)d_in[4];
    const float* kc_var    = (const float*)d_in[5];
    const float* kc_w2     = (const float*)d_in[6];
    const float* kc_b2     = (const float*)d_in[7];
    const float* kc_bias   = (const float*)d_in[8];
    const float* conv1_w   = (const float*)d_in[9];
    const float* conv1_b   = (const float*)d_in[10];
    const float* pi1_w     = (const float*)d_in[11];
    const float* pi1_b     = (const float*)d_in[12];
    const float* dw1_w     = (const float*)d_in[13];
    const float* dw1_b     = (const float*)d_in[14];
    const float* po1_w     = (const float*)d_in[15];
    const float* po1_b     = (const float*)d_in[16];
    const float* pi2_w     = (const float*)d_in[17];
    const float* pi2_b     = (const float*)d_in[18];
    const float* dw2_w     = (const float*)d_in[19];
    const float* dw2_b     = (const float*)d_in[20];
    const float* po2_w     = (const float*)d_in[21];
    const float* po2_b     = (const float*)d_in[22];
    float* out = (float*)d_out;

    static bool attr_done = false;
    if (!attr_done) {
        cudaFuncSetAttribute(conv_mma_kernel, cudaFuncAttributeMaxDynamicSharedMemorySize, CONV_SMEM);
        attr_done = true;
    }

    // out[:, T-1] = feature[:, T-1]
    for (int bi = 0; bi < BATCH; bi++) {
        size_t off = ((size_t)bi*T + (T-1)) * CHW;
        cudaMemcpyAsync(out + off, feature + off, (size_t)CHW*sizeof(float),
                        cudaMemcpyDeviceToDevice, 0);
    }

    // one-time: weight splits + ALL per-step dynamic weights
    prep_w_kernel<<<(9*8*128*16 + 255)/256, 256>>>(conv1_w);
    prep_pw_kernel<<<(2*4*256*16 + 255)/256, 256>>>(pi1_w, pi2_w);
    prep_cw_kernel<<<(2*16*64*16 + 255)/256, 256>>>(po1_w, po2_w);
    pool_all_kernel<<<(T-1)*BATCH*C, 256>>>(feature);
    mlp_all_kernel<<<T-1, 128>>>(kc_w1, kc_gamma, kc_beta, kc_mean, kc_var, kc_w2, kc_b2);

    for (int i = T - 2; i >= 0; --i) {
        const float* xbase = feature + (size_t)i*CHW;
        const float* ybase = out + (size_t)(i+1)*CHW;

        dyndw_kernel<<<(BATCH*CHW/4)/256, 256>>>(ybase, kc_bias, i);
        conv_mma_kernel<<<dim3(W/32, H/4, BATCH), 512, CONV_SMEM>>>(xbase, conv1_b);
        expand_mma_kernel<<<dim3(HW/64, 4, BATCH), 256>>>(pi1_b, pi2_b);
        dw_both_kernel<<<dim3((BATCH*C4*HW/4)/256, 2), 256>>>(dw1_w, dw1_b, dw2_w, dw2_b);
        contract_both_kernel<<<dim3(HW/128, BATCH), 256>>>(po1_b, po2_b, out + (size_t)i*CHW);
    }
}